// round 1
// baseline (speedup 1.0000x reference)
#include <cuda_runtime.h>
#include <math.h>

// ---------------- static device scratch (no allocations allowed) ----------------
__device__ float g_pos[64 * 64];
__device__ float g_q[3 * 1024 * 4 * 64 * 16];
__device__ float g_k[3 * 1024 * 4 * 64 * 16];
__device__ float g_v[3 * 1024 * 4 * 64 * 16];
__device__ float g_gin[3 * 1024 * 64 * 192];   // GEGLU inputs: [attA|attB|mergedQ]
__device__ float g_y[3 * 1024 * 64 * 64];      // GEGLU outputs
__device__ float g_xres[192 * 65536];          // residual after conv1x1 + x0
__device__ float g_hb[768 * 65536];            // ff_in output
__device__ float g_gb[384 * 65536];            // gelu(dw(g1))*dw(g2)
__device__ float g_wt192[192 * 192];           // conv11_w transposed (i-major)
__device__ float g_wtin[192 * 768];            // ff_in_w transposed
__device__ float g_wtout[384 * 192];           // ff_out_w transposed

// ---------------- K0a: DETR-style sine positional encoding (8x8, 64 feats) ------
__global__ void kpos() {
  int n = threadIdx.x;               // token 0..63
  int i = n >> 3, j = n & 7;
  double scale = 6.283185307179586476925286766559;
  double yv = (double)(i + 1) / (8.0 + 1e-6) * scale;
  double xv = (double)(j + 1) / (8.0 + 1e-6) * scale;
  for (int c = 0; c < 64; c++) {
    double base = (c < 32) ? yv : xv;
    int k = (c < 32) ? c : (c - 32);
    double dt = pow(10000.0, (double)(k >> 1) / 16.0);
    double v = base / dt;
    g_pos[n * 64 + c] = (float)(((k & 1) == 0) ? sin(v) : cos(v));
  }
}

// ---------------- K0b: weight transposes for 'oi' einsums ------------------------
__global__ void ktrans_all(const float* __restrict__ c11,
                           const float* __restrict__ ffin,
                           const float* __restrict__ ffout) {
  int idx = blockIdx.x * 256 + threadIdx.x;
  if (idx < 192 * 192) { int r = idx / 192, c = idx - r * 192; g_wt192[c * 192 + r] = c11[idx]; }
  if (idx < 768 * 192) { int r = idx / 192, c = idx - r * 192; g_wtin[c * 768 + r] = ffin[idx]; }
  if (idx < 192 * 384) { int r = idx / 384, c = idx - r * 384; g_wtout[c * 192 + r] = ffout[idx]; }
}

// ---------------- K1: shift+window partition + LN1 + pos + QKV GEMM --------------
// block per (e, window), 256 threads. q stored UNscaled (scale applied in attn).
// head split: feature f = ch*4 + h (head fast). merged-q also written to GIN[...,128+h*16+ch].
__global__ void k1_qkv(const float* __restrict__ x, const float* __restrict__ ln1w,
                       const float* __restrict__ ln1b, const float* __restrict__ wqkv) {
  int blk = blockIdx.x;
  int e = blk >> 10, wwin = blk & 1023;
  int wh = wwin >> 5, ww = wwin & 31;
  __shared__ float sx[64 * 65];
  __shared__ float sn[64 * 65];
  for (int idx = threadIdx.x; idx < 4096; idx += 256) {
    int c = idx >> 6, n = idx & 63;
    int i = n >> 3, j = n & 7;
    int h0 = (wh * 8 + i + 4) & 255;   // roll(x, -4) : xs[h] = x[(h+4)%256]
    int w0 = (ww * 8 + j + 4) & 255;
    sx[n * 65 + c] = x[((e * 64 + c) * 256 + h0) * 256 + w0];
  }
  __syncthreads();
  if (threadIdx.x < 64) {
    int n = threadIdx.x;
    float m = 0.f;
#pragma unroll
    for (int c = 0; c < 64; c++) m += sx[n * 65 + c];
    m *= (1.f / 64.f);
    float v = 0.f;
#pragma unroll
    for (int c = 0; c < 64; c++) { float d = sx[n * 65 + c] - m; v += d * d; }
    v *= (1.f / 64.f);
    float rs = rsqrtf(v + 1e-5f);
    for (int c = 0; c < 64; c++)
      sn[n * 65 + c] = (sx[n * 65 + c] - m) * rs * ln1w[c] + ln1b[c] + g_pos[n * 64 + c];
  }
  __syncthreads();
  long wb = (long)(e * 1024 + wwin);
  for (int o = threadIdx.x; o < 64 * 192; o += 256) {
    int n = o / 192, jc = o - n * 192;
    float acc = 0.f;
#pragma unroll
    for (int c = 0; c < 64; c++) acc += sn[n * 65 + c] * wqkv[c * 192 + jc];
    int p = jc / 64, f = jc - p * 64;
    int hh = f & 3, ch = f >> 2;                 // head-fast split
    long qi = (wb * 4 + hh) * 1024 + n * 16 + ch;
    if (p == 0) {
      g_q[qi] = acc;
      g_gin[(wb * 64 + n) * 192 + 128 + hh * 16 + ch] = acc;  // merge_heads(q)
    } else if (p == 1) g_k[qi] = acc;
    else g_v[qi] = acc;
  }
}

// ---------------- K2: 6 cross-exposure shifted-window attentions -----------------
__device__ __forceinline__ int rid3(int p) { return (p < 248) ? 0 : ((p < 252) ? 1 : 2); }

__global__ void k2_attn() {
  const int e_of[6]  = {0, 0, 1, 1, 2, 2};
  const int kv_of[6] = {1, 2, 0, 2, 1, 0};
  const int sl_of[6] = {0, 1, 0, 1, 0, 1};
  int w = blockIdx.x, hh = blockIdx.y, z = blockIdx.z;
  int e = e_of[z], ekv = kv_of[z], sl = sl_of[z];
  __shared__ float sq[1024], sk[1024], sv[1024];
  __shared__ float satt[64 * 65];
  int t = threadIdx.x;                         // 64 threads: one per query token
  long qb = ((long)(e * 1024 + w) * 4 + hh) * 1024;
  long kb = ((long)(ekv * 1024 + w) * 4 + hh) * 1024;
  for (int idx = t; idx < 1024; idx += 64) {
    sq[idx] = g_q[qb + idx];
    sk[idx] = g_k[kb + idx];
    sv[idx] = g_v[kb + idx];
  }
  __syncthreads();
  int n = t, i = n >> 3, j = n & 7;
  int wh = w >> 5, ww = w & 31;
  int ra = rid3(wh * 8 + i) * 3 + rid3(ww * 8 + j);
  float q[16];
#pragma unroll
  for (int c = 0; c < 16; c++) q[c] = sq[n * 16 + c];
  float mx = -1e30f;
  for (int m = 0; m < 64; m++) {
    float s = 0.f;
#pragma unroll
    for (int c = 0; c < 16; c++) s += q[c] * sk[m * 16 + c];
    s *= 0.125f;                                // SCALE = FNUM^-0.5
    int rb = rid3(wh * 8 + (m >> 3)) * 3 + rid3(ww * 8 + (m & 7));
    if (rb != ra) s -= 100.f;                   // swin shift mask
    satt[n * 65 + m] = s;
    mx = fmaxf(mx, s);
  }
  float sum = 0.f;
  for (int m = 0; m < 64; m++) {
    float pv = expf(satt[n * 65 + m] - mx);
    satt[n * 65 + m] = pv;
    sum += pv;
  }
  float inv = 1.f / sum;
  float acc[16];
#pragma unroll
  for (int c = 0; c < 16; c++) acc[c] = 0.f;
  for (int m = 0; m < 64; m++) {
    float a = satt[n * 65 + m];
#pragma unroll
    for (int c = 0; c < 16; c++) acc[c] += a * sv[m * 16 + c];
  }
  long gb = ((long)(e * 1024 + w) * 64 + n) * 192 + sl * 64 + hh * 16;
#pragma unroll
  for (int c = 0; c < 16; c++) g_gin[gb + c] = acc[c] * inv;
}

// ---------------- K3: per-exposure GEGLU (192 -> 64) -----------------------------
__global__ void k3_geglu(const float* __restrict__ w11, const float* __restrict__ b11,
                         const float* __restrict__ w12, const float* __restrict__ b12,
                         const float* __restrict__ w2, const float* __restrict__ b2) {
  extern __shared__ float sm3[];
  float* sgin = sm3;              // 64*192
  float* st = sm3 + 64 * 192;     // 64*64
  int blk = blockIdx.x;
  int e = blk >> 10;
  const float* W11 = w11 + e * 192 * 64;
  const float* W12 = w12 + e * 192 * 64;
  const float* W2 = w2 + e * 64 * 64;
  const float* B11 = b11 + e * 64;
  const float* B12 = b12 + e * 64;
  const float* B2 = b2 + e * 64;
  long gbase = (long)blk * (64L * 192);
  for (int idx = threadIdx.x; idx < 64 * 192; idx += 256) sgin[idx] = g_gin[gbase + idx];
  __syncthreads();
  for (int o = threadIdx.x; o < 4096; o += 256) {
    int n = o >> 6, f = o & 63;
    float a = B11[f], g = B12[f];
#pragma unroll 4
    for (int c = 0; c < 192; c++) {
      float xv = sgin[n * 192 + c];
      a += xv * W11[c * 64 + f];
      g += xv * W12[c * 64 + f];
    }
    float ge = 0.5f * a * (1.f + erff(a * 0.70710678118654752f));
    st[o] = ge * g;
  }
  __syncthreads();
  long ybase = (long)blk * 4096L;
  for (int o = threadIdx.x; o < 4096; o += 256) {
    int n = o >> 6, f = o & 63;
    float acc = B2[f];
#pragma unroll
    for (int c = 0; c < 64; c++) acc += st[n * 64 + c] * W2[c * 64 + f];
    g_y[ybase + o] = acc;
  }
}

// ---------------- K4: window reverse + conv1x1 (192x192) + roll +4 + residual ----
__global__ void k4_conv11(const float* __restrict__ x) {
  extern __shared__ float s2[];   // [c=192][n=64] padded stride 65 -> 192*65 floats
  int wwin = blockIdx.x;
  int wh = wwin >> 5, ww = wwin & 31;
  for (int idx = threadIdx.x; idx < 3 * 4096; idx += 256) {
    int e = idx >> 12;
    int r = idx & 4095;
    int n = r >> 6, f = r & 63;
    s2[(e * 64 + f) * 65 + n] = g_y[((long)(e * 1024 + wwin)) * 4096 + r];
  }
  __syncthreads();
  for (int o = threadIdx.x; o < 64 * 192; o += 256) {
    int n = o & 63, oc = o >> 6;   // lanes vary n -> smem conflict-free, weight broadcast
    float acc = 0.f;
#pragma unroll 4
    for (int c = 0; c < 192; c++) acc += s2[c * 65 + n] * g_wt192[c * 192 + oc];
    int i = n >> 3, j = n & 7;
    int hp = (wh * 8 + i + 4) & 255;   // roll(+4,+4)
    int wp = (ww * 8 + j + 4) & 255;
    int gi = oc * 65536 + hp * 256 + wp;
    g_xres[gi] = acc + x[gi];
  }
}

// ---------------- K5: per-pixel LN2(192) + ff_in (192 -> 768) --------------------
// block = 64 contiguous pixels of one row; 8 warps, each warp owns o%8==warp,
// register-blocked 8 outputs x 2 pixels per weight load.
__global__ void k5_ln_ffin(const float* __restrict__ ln2w, const float* __restrict__ ln2b) {
  extern __shared__ float sxn[];   // 192*64
  __shared__ float red[512];
  __shared__ float smean[64], srstd[64];
  int blk = blockIdx.x;
  int h = blk >> 2;
  int w0 = (blk & 3) * 64;
  int pix0 = h * 256 + w0;
  int t = threadIdx.x;
  for (int idx = t; idx < 12288; idx += 256) {
    int c = idx >> 6, p = idx & 63;
    sxn[idx] = g_xres[c * 65536 + pix0 + p];
  }
  __syncthreads();
  {
    int p = t & 63, g = t >> 6;       // 4 groups over channels
    float s = 0.f, s2 = 0.f;
    for (int c = g; c < 192; c += 4) { float v = sxn[c * 64 + p]; s += v; s2 += v * v; }
    red[g * 64 + p] = s;
    red[256 + g * 64 + p] = s2;
  }
  __syncthreads();
  if (t < 64) {
    float s = red[t] + red[64 + t] + red[128 + t] + red[192 + t];
    float s2 = red[256 + t] + red[320 + t] + red[384 + t] + red[448 + t];
    float m = s * (1.f / 192.f);
    float var = s2 * (1.f / 192.f) - m * m;
    smean[t] = m;
    srstd[t] = rsqrtf(var + 1e-5f);
  }
  __syncthreads();
  for (int idx = t; idx < 12288; idx += 256) {
    int c = idx >> 6, p = idx & 63;
    sxn[idx] = (sxn[idx] - smean[p]) * srstd[p] * ln2w[c] + ln2b[c];
  }
  __syncthreads();
  int lane = t & 31, wa = t >> 5;
  int p0 = lane, p1 = lane + 32;
  for (int ob = 0; ob < 96; ob += 8) {
    float a0[8], a1[8];
#pragma unroll
    for (int oi = 0; oi < 8; oi++) { a0[oi] = 0.f; a1[oi] = 0.f; }
    for (int c = 0; c < 192; c++) {
      float x0 = sxn[c * 64 + p0];
      float x1 = sxn[c * 64 + p1];
#pragma unroll
      for (int oi = 0; oi < 8; oi++) {
        float wv = g_wtin[c * 768 + wa + (ob + oi) * 8];
        a0[oi] += x0 * wv;
        a1[oi] += x1 * wv;
      }
    }
#pragma unroll
    for (int oi = 0; oi < 8; oi++) {
      int o = wa + (ob + oi) * 8;
      g_hb[o * 65536 + pix0 + p0] = a0[oi];
      g_hb[o * 65536 + pix0 + p1] = a1[oi];
    }
  }
}

// ---------------- K6: depthwise 3x3 (pad 1) + gelu(g1)*g2 ------------------------
__global__ void k6_dw(const float* __restrict__ dw) {
  int w = threadIdx.x;
  int h = blockIdx.x;
  int c = blockIdx.y;
  const float* f0 = dw + c * 9;
  const float* f1 = dw + (c + 384) * 9;
  const float* p0 = g_hb + c * 65536;
  const float* p1 = g_hb + (c + 384) * 65536;
  float a = 0.f, b = 0.f;
#pragma unroll
  for (int dh = 0; dh < 3; dh++) {
    int hh = h + dh - 1;
    if (hh < 0 || hh > 255) continue;
#pragma unroll
    for (int dwi = 0; dwi < 3; dwi++) {
      int wp = w + dwi - 1;
      if (wp < 0 || wp > 255) continue;
      a += p0[hh * 256 + wp] * f0[dh * 3 + dwi];
      b += p1[hh * 256 + wp] * f1[dh * 3 + dwi];
    }
  }
  float ge = 0.5f * a * (1.f + erff(a * 0.70710678118654752f));
  g_gb[c * 65536 + h * 256 + w] = ge * b;
}

// ---------------- K7: ff_out (384 -> 192) + residual -> d_out --------------------
__global__ void k7_ffout(float* __restrict__ out) {
  extern __shared__ float sg[];    // 384*64
  int blk = blockIdx.x;
  int h = blk >> 2;
  int w0 = (blk & 3) * 64;
  int pix0 = h * 256 + w0;
  int t = threadIdx.x;
  for (int idx = t; idx < 24576; idx += 256) {
    int c = idx >> 6, p = idx & 63;
    sg[idx] = g_gb[c * 65536 + pix0 + p];
  }
  __syncthreads();
  int lane = t & 31, wa = t >> 5;
  int p0 = lane, p1 = lane + 32;
  for (int ob = 0; ob < 24; ob += 8) {
    float a0[8], a1[8];
#pragma unroll
    for (int oi = 0; oi < 8; oi++) { a0[oi] = 0.f; a1[oi] = 0.f; }
    for (int c = 0; c < 384; c++) {
      float x0 = sg[c * 64 + p0];
      float x1 = sg[c * 64 + p1];
#pragma unroll
      for (int oi = 0; oi < 8; oi++) {
        float wv = g_wtout[c * 192 + wa + (ob + oi) * 8];
        a0[oi] += x0 * wv;
        a1[oi] += x1 * wv;
      }
    }
#pragma unroll
    for (int oi = 0; oi < 8; oi++) {
      int o = wa + (ob + oi) * 8;
      int i0 = o * 65536 + pix0 + p0;
      int i1 = o * 65536 + pix0 + p1;
      out[i0] = g_xres[i0] + a0[oi];
      out[i1] = g_xres[i1] + a1[oi];
    }
  }
}

// ---------------- host launcher --------------------------------------------------
extern "C" void kernel_launch(void* const* d_in, const int* in_sizes, int n_in,
                              void* d_out, int out_size) {
  const float* x    = (const float*)d_in[0];
  const float* ln1w = (const float*)d_in[1];
  const float* ln1b = (const float*)d_in[2];
  const float* ln2w = (const float*)d_in[3];
  const float* ln2b = (const float*)d_in[4];
  const float* wqkv = (const float*)d_in[5];
  const float* w11  = (const float*)d_in[6];
  const float* b11  = (const float*)d_in[7];
  const float* w12  = (const float*)d_in[8];
  const float* b12  = (const float*)d_in[9];
  const float* w2   = (const float*)d_in[10];
  const float* b2   = (const float*)d_in[11];
  const float* c11  = (const float*)d_in[12];
  const float* ffin = (const float*)d_in[13];
  const float* ffdw = (const float*)d_in[14];
  const float* ffou = (const float*)d_in[15];
  float* out = (float*)d_out;

  cudaFuncSetAttribute(k3_geglu, cudaFuncAttributeMaxDynamicSharedMemorySize, (64 * 192 + 64 * 64) * 4);
  cudaFuncSetAttribute(k4_conv11, cudaFuncAttributeMaxDynamicSharedMemorySize, 192 * 65 * 4);
  cudaFuncSetAttribute(k5_ln_ffin, cudaFuncAttributeMaxDynamicSharedMemorySize, 192 * 64 * 4);
  cudaFuncSetAttribute(k7_ffout, cudaFuncAttributeMaxDynamicSharedMemorySize, 384 * 64 * 4);

  kpos<<<1, 64>>>();
  ktrans_all<<<(768 * 192 + 255) / 256, 256>>>(c11, ffin, ffou);
  k1_qkv<<<3072, 256>>>(x, ln1w, ln1b, wqkv);
  {
    dim3 g2(1024, 4, 6);
    k2_attn<<<g2, 64>>>();
  }
  k3_geglu<<<3072, 256, (64 * 192 + 64 * 64) * 4>>>(w11, b11, w12, b12, w2, b2);
  k4_conv11<<<1024, 256, 192 * 65 * 4>>>(x);
  k5_ln_ffin<<<1024, 256, 192 * 64 * 4>>>(ln2w, ln2b);
  {
    dim3 g6(256, 384);
    k6_dw<<<g6, 256>>>(ffdw);
  }
  k7_ffout<<<1024, 256, 384 * 64 * 4>>>(out);
}

// round 2
// speedup vs baseline: 1.3872x; 1.3872x over previous
#include <cuda_runtime.h>
#include <math.h>

typedef unsigned long long ull;

// ---------------- packed f32x2 helpers (sm_100+ PTX, ptxas never auto-emits) ----
__device__ __forceinline__ ull fma2(ull a, ull b, ull c) {
  ull d;
  asm("fma.rn.f32x2 %0, %1, %2, %3;" : "=l"(d) : "l"(a), "l"(b), "l"(c));
  return d;
}
__device__ __forceinline__ ull pk2(float x, float y) {
  ull r;
  asm("mov.b64 %0, {%1, %2};" : "=l"(r) : "f"(x), "f"(y));
  return r;
}
__device__ __forceinline__ float2 up2(ull a) {
  float2 f;
  asm("mov.b64 {%0, %1}, %2;" : "=f"(f.x), "=f"(f.y) : "l"(a));
  return f;
}

// ---------------- static device scratch (no allocations allowed) ----------------
__device__ float g_pos[64 * 64];
__device__ float g_q[3 * 1024 * 4 * 64 * 16];
__device__ float g_k[3 * 1024 * 4 * 64 * 16];
__device__ float g_v[3 * 1024 * 4 * 64 * 16];
__device__ float g_gin[3 * 1024 * 64 * 192];   // GEGLU inputs: [attA|attB|mergedQ]
__device__ float g_y[3 * 1024 * 64 * 64];      // GEGLU outputs
__device__ float g_xres[192 * 65536];          // residual after conv1x1 + x0
__device__ float g_hb[768 * 65536];            // ff_in output
__device__ float g_gb[384 * 65536];            // gelu(dw(g1))*dw(g2)
__device__ float g_wt192[192 * 192];           // conv11_w transposed (i-major, o fast)
__device__ float g_wtin[192 * 768];            // ff_in_w transposed
__device__ float g_wtout[384 * 192];           // ff_out_w transposed

// ---------------- K0a: DETR-style sine positional encoding -----------------------
__global__ void kpos() {
  int n = threadIdx.x;
  int i = n >> 3, j = n & 7;
  double scale = 6.283185307179586476925286766559;
  double yv = (double)(i + 1) / (8.0 + 1e-6) * scale;
  double xv = (double)(j + 1) / (8.0 + 1e-6) * scale;
  for (int c = 0; c < 64; c++) {
    double base = (c < 32) ? yv : xv;
    int k = (c < 32) ? c : (c - 32);
    double dt = pow(10000.0, (double)(k >> 1) / 16.0);
    double v = base / dt;
    g_pos[n * 64 + c] = (float)(((k & 1) == 0) ? sin(v) : cos(v));
  }
}

// ---------------- K0b: weight transposes for 'oi' einsums ------------------------
__global__ void ktrans_all(const float* __restrict__ c11,
                           const float* __restrict__ ffin,
                           const float* __restrict__ ffout) {
  int idx = blockIdx.x * 256 + threadIdx.x;
  if (idx < 192 * 192) { int r = idx / 192, c = idx - r * 192; g_wt192[c * 192 + r] = c11[idx]; }
  if (idx < 768 * 192) { int r = idx / 192, c = idx - r * 192; g_wtin[c * 768 + r] = ffin[idx]; }
  if (idx < 192 * 384) { int r = idx / 384, c = idx - r * 384; g_wtout[c * 192 + r] = ffout[idx]; }
}

// ---------------- K1: shift+window + LN1 + pos + QKV GEMM (packed) ---------------
// dyn smem: sx[64*65] | snT[64*66] | sout[192*65]
__global__ void k1_qkv(const float* __restrict__ x, const float* __restrict__ ln1w,
                       const float* __restrict__ ln1b, const float* __restrict__ wqkv) {
  extern __shared__ float sm1[];
  float* sx = sm1;               // [n][c] stride 65
  float* snT = sm1 + 4160;       // [c][n] stride 66
  float* sout = sm1 + 8384;      // [jc][n] stride 65
  int blk = blockIdx.x;
  int e = blk >> 10, wwin = blk & 1023;
  int wh = wwin >> 5, ww = wwin & 31;
  int t = threadIdx.x;
  for (int idx = t; idx < 4096; idx += 256) {
    int c = idx >> 6, n = idx & 63;
    int i = n >> 3, j = n & 7;
    int h0 = (wh * 8 + i + 4) & 255;
    int w0 = (ww * 8 + j + 4) & 255;
    sx[n * 65 + c] = x[((e * 64 + c) * 256 + h0) * 256 + w0];
  }
  __syncthreads();
  if (t < 64) {
    int n = t;
    float m = 0.f;
#pragma unroll
    for (int c = 0; c < 64; c++) m += sx[n * 65 + c];
    m *= (1.f / 64.f);
    float v = 0.f;
#pragma unroll
    for (int c = 0; c < 64; c++) { float d = sx[n * 65 + c] - m; v += d * d; }
    v *= (1.f / 64.f);
    float rs = rsqrtf(v + 1e-5f);
    for (int c = 0; c < 64; c++)
      snT[c * 66 + n] = (sx[n * 65 + c] - m) * rs * ln1w[c] + ln1b[c] + g_pos[n * 64 + c];
  }
  __syncthreads();
  int wa = t >> 5, lane = t & 31, n0 = lane * 2;
  for (int pass = 0; pass < 3; pass++) {
    int jc0 = pass * 64 + wa * 8;
    ull acc[4][2];
#pragma unroll
    for (int a = 0; a < 4; a++) { acc[a][0] = 0ULL; acc[a][1] = 0ULL; }
#pragma unroll 4
    for (int c = 0; c < 64; c++) {
      ulonglong2 wA = *(const ulonglong2*)(wqkv + c * 192 + jc0);
      ulonglong2 wB = *(const ulonglong2*)(wqkv + c * 192 + jc0 + 4);
      float2 xv = *(const float2*)&snT[c * 66 + n0];
      ull x0 = pk2(xv.x, xv.x), x1 = pk2(xv.y, xv.y);
      acc[0][0] = fma2(x0, wA.x, acc[0][0]); acc[0][1] = fma2(x1, wA.x, acc[0][1]);
      acc[1][0] = fma2(x0, wA.y, acc[1][0]); acc[1][1] = fma2(x1, wA.y, acc[1][1]);
      acc[2][0] = fma2(x0, wB.x, acc[2][0]); acc[2][1] = fma2(x1, wB.x, acc[2][1]);
      acc[3][0] = fma2(x0, wB.y, acc[3][0]); acc[3][1] = fma2(x1, wB.y, acc[3][1]);
    }
#pragma unroll
    for (int a = 0; a < 4; a++) {
#pragma unroll
      for (int ni = 0; ni < 2; ni++) {
        float2 f = up2(acc[a][ni]);
        sout[(jc0 + a * 2) * 65 + n0 + ni] = f.x;
        sout[(jc0 + a * 2 + 1) * 65 + n0 + ni] = f.y;
      }
    }
  }
  __syncthreads();
  long wb = (long)(e * 1024 + wwin);
  for (int idx = t; idx < 12288; idx += 256) {
    int ch = idx & 15, n = (idx >> 4) & 63, hh = (idx >> 10) & 3, p = idx >> 12;
    int jc = p * 64 + ch * 4 + hh;
    float vv = sout[jc * 65 + n];
    long qi = (wb * 4 + hh) * 1024 + n * 16 + ch;
    if (p == 0) g_q[qi] = vv;
    else if (p == 1) g_k[qi] = vv;
    else g_v[qi] = vv;
  }
  for (int idx = t; idx < 4096; idx += 256) {
    int c2 = idx & 63, n = idx >> 6;
    int hh = c2 >> 4, ch = c2 & 15;
    g_gin[(wb * 64 + n) * 192 + 128 + c2] = sout[(ch * 4 + hh) * 65 + n];
  }
}

// ---------------- K2: 6 cross-exposure shifted-window attentions (packed) --------
__device__ __forceinline__ int rid3(int p) { return (p < 248) ? 0 : ((p < 252) ? 1 : 2); }

// dyn smem: sk[4096] | sv[4096] | satt[64*256]
__global__ void k2_attn() {
  extern __shared__ float sm2[];
  float* sk = sm2;
  float* sv = sm2 + 4096;
  float* satt = sm2 + 8192;
  const int e_of[6]  = {0, 0, 1, 1, 2, 2};
  const int kv_of[6] = {1, 2, 0, 2, 1, 0};
  const int sl_of[6] = {0, 1, 0, 1, 0, 1};
  int w = blockIdx.x, z = blockIdx.y;
  int e = e_of[z], ekv = kv_of[z], sl = sl_of[z];
  int t = threadIdx.x;
  int hh = t >> 6, n = t & 63;
  long kb = (long)(ekv * 1024 + w) * 4096;
  for (int idx = t; idx < 4096; idx += 256) {
    sk[idx] = g_k[kb + idx];
    sv[idx] = g_v[kb + idx];
  }
  long qb = (long)(e * 1024 + w) * 4096 + hh * 1024 + n * 16;
  const ulonglong2* qg = (const ulonglong2*)(g_q + qb);
  ulonglong2 q01 = qg[0], q23 = qg[1], q45 = qg[2], q67 = qg[3];
  ull qp[8] = {q01.x, q01.y, q23.x, q23.y, q45.x, q45.y, q67.x, q67.y};
  __syncthreads();
  int i = n >> 3, j = n & 7;
  int wh = w >> 5, ww = w & 31;
  int ra = rid3(wh * 8 + i) * 3 + rid3(ww * 8 + j);
  float mx = -1e30f;
  const ull* skp = (const ull*)sk;
  for (int m = 0; m < 64; m++) {
    const ull* kr = skp + (hh * 1024 + m * 16) / 2;
    ull s2 = 0ULL;
#pragma unroll
    for (int c4 = 0; c4 < 8; c4++) s2 = fma2(qp[c4], kr[c4], s2);
    float2 sf = up2(s2);
    float s = (sf.x + sf.y) * 0.125f;
    int rb = rid3(wh * 8 + (m >> 3)) * 3 + rid3(ww * 8 + (m & 7));
    if (rb != ra) s -= 100.f;
    satt[m * 256 + t] = s;
    mx = fmaxf(mx, s);
  }
  float sum = 0.f;
  ull acc[8];
#pragma unroll
  for (int c4 = 0; c4 < 8; c4++) acc[c4] = 0ULL;
  const ull* svp = (const ull*)sv;
  for (int m = 0; m < 64; m++) {
    float p = __expf(satt[m * 256 + t] - mx);
    sum += p;
    ull pp = pk2(p, p);
    const ull* vr = svp + (hh * 1024 + m * 16) / 2;
#pragma unroll
    for (int c4 = 0; c4 < 8; c4++) acc[c4] = fma2(pp, vr[c4], acc[c4]);
  }
  float inv = 1.f / sum;
  long gb = ((long)(e * 1024 + w) * 64 + n) * 192 + sl * 64 + hh * 16;
#pragma unroll
  for (int c4 = 0; c4 < 8; c4++) {
    float2 f = up2(acc[c4]);
    g_gin[gb + c4 * 2] = f.x * inv;
    g_gin[gb + c4 * 2 + 1] = f.y * inv;
  }
}

// ---------------- K3: per-exposure GEGLU (192 -> 64), packed ---------------------
// dyn smem: sx[192*66] | st[64*66]
__global__ void k3_geglu(const float* __restrict__ w11, const float* __restrict__ b11,
                         const float* __restrict__ w12, const float* __restrict__ b12,
                         const float* __restrict__ w2, const float* __restrict__ b2) {
  extern __shared__ float sm3[];
  float* sx = sm3;             // [c][n] stride 66
  float* st = sm3 + 192 * 66;  // [c2][n] stride 66
  int blk = blockIdx.x;
  int e = blk >> 10;
  const float* W11 = w11 + e * 12288;
  const float* W12 = w12 + e * 12288;
  const float* W2 = w2 + e * 4096;
  const float* B11 = b11 + e * 64;
  const float* B12 = b12 + e * 64;
  const float* B2 = b2 + e * 64;
  int t = threadIdx.x;
  long gbase = (long)blk * 12288;
  for (int idx = t; idx < 12288; idx += 256) {
    int nn = idx / 192, c = idx - nn * 192;
    sx[c * 66 + nn] = g_gin[gbase + idx];
  }
  __syncthreads();
  int wa = t >> 5, lane = t & 31, n0 = lane * 2;
  int f0 = wa * 8;
  ull a[4][2], g[4][2];
#pragma unroll
  for (int k = 0; k < 4; k++) {
    ull bi = pk2(B11[f0 + k * 2], B11[f0 + k * 2 + 1]);
    ull gi = pk2(B12[f0 + k * 2], B12[f0 + k * 2 + 1]);
    a[k][0] = bi; a[k][1] = bi;
    g[k][0] = gi; g[k][1] = gi;
  }
#pragma unroll 4
  for (int c = 0; c < 192; c++) {
    ulonglong2 wA = *(const ulonglong2*)(W11 + c * 64 + f0);
    ulonglong2 wB = *(const ulonglong2*)(W11 + c * 64 + f0 + 4);
    ulonglong2 vA = *(const ulonglong2*)(W12 + c * 64 + f0);
    ulonglong2 vB = *(const ulonglong2*)(W12 + c * 64 + f0 + 4);
    float2 xv = *(const float2*)&sx[c * 66 + n0];
    ull x0 = pk2(xv.x, xv.x), x1 = pk2(xv.y, xv.y);
    a[0][0] = fma2(x0, wA.x, a[0][0]); a[0][1] = fma2(x1, wA.x, a[0][1]);
    a[1][0] = fma2(x0, wA.y, a[1][0]); a[1][1] = fma2(x1, wA.y, a[1][1]);
    a[2][0] = fma2(x0, wB.x, a[2][0]); a[2][1] = fma2(x1, wB.x, a[2][1]);
    a[3][0] = fma2(x0, wB.y, a[3][0]); a[3][1] = fma2(x1, wB.y, a[3][1]);
    g[0][0] = fma2(x0, vA.x, g[0][0]); g[0][1] = fma2(x1, vA.x, g[0][1]);
    g[1][0] = fma2(x0, vA.y, g[1][0]); g[1][1] = fma2(x1, vA.y, g[1][1]);
    g[2][0] = fma2(x0, vB.x, g[2][0]); g[2][1] = fma2(x1, vB.x, g[2][1]);
    g[3][0] = fma2(x0, vB.y, g[3][0]); g[3][1] = fma2(x1, vB.y, g[3][1]);
  }
#pragma unroll
  for (int k = 0; k < 4; k++) {
#pragma unroll
    for (int ni = 0; ni < 2; ni++) {
      float2 av = up2(a[k][ni]);
      float2 gv = up2(g[k][ni]);
      float t0 = 0.5f * av.x * (1.f + erff(av.x * 0.70710678118654752f)) * gv.x;
      float t1 = 0.5f * av.y * (1.f + erff(av.y * 0.70710678118654752f)) * gv.y;
      st[(f0 + k * 2) * 66 + n0 + ni] = t0;
      st[(f0 + k * 2 + 1) * 66 + n0 + ni] = t1;
    }
  }
  __syncthreads();
  ull acc[4][2];
#pragma unroll
  for (int k = 0; k < 4; k++) {
    ull bi = pk2(B2[f0 + k * 2], B2[f0 + k * 2 + 1]);
    acc[k][0] = bi; acc[k][1] = bi;
  }
#pragma unroll 4
  for (int c = 0; c < 64; c++) {
    ulonglong2 wA = *(const ulonglong2*)(W2 + c * 64 + f0);
    ulonglong2 wB = *(const ulonglong2*)(W2 + c * 64 + f0 + 4);
    float2 xv = *(const float2*)&st[c * 66 + n0];
    ull x0 = pk2(xv.x, xv.x), x1 = pk2(xv.y, xv.y);
    acc[0][0] = fma2(x0, wA.x, acc[0][0]); acc[0][1] = fma2(x1, wA.x, acc[0][1]);
    acc[1][0] = fma2(x0, wA.y, acc[1][0]); acc[1][1] = fma2(x1, wA.y, acc[1][1]);
    acc[2][0] = fma2(x0, wB.x, acc[2][0]); acc[2][1] = fma2(x1, wB.x, acc[2][1]);
    acc[3][0] = fma2(x0, wB.y, acc[3][0]); acc[3][1] = fma2(x1, wB.y, acc[3][1]);
  }
  long ybase = (long)blk * 4096;
#pragma unroll
  for (int ni = 0; ni < 2; ni++) {
    float2 u0 = up2(acc[0][ni]);
    float2 u1 = up2(acc[1][ni]);
    float2 u2 = up2(acc[2][ni]);
    float2 u3 = up2(acc[3][ni]);
    float4 o0 = make_float4(u0.x, u0.y, u1.x, u1.y);
    float4 o1 = make_float4(u2.x, u2.y, u3.x, u3.y);
    *(float4*)&g_y[ybase + (n0 + ni) * 64 + f0] = o0;
    *(float4*)&g_y[ybase + (n0 + ni) * 64 + f0 + 4] = o1;
  }
}

// ---------------- K4: window reverse + conv1x1 + roll +4 + residual, packed ------
// dyn smem: s2[192*66]
__global__ void k4_conv11(const float* __restrict__ x) {
  extern __shared__ float s2m[];
  int wwin = blockIdx.x;
  int wh = wwin >> 5, ww = wwin & 31;
  int t = threadIdx.x;
  for (int idx = t; idx < 12288; idx += 256) {
    int e = idx >> 12;
    int r = idx & 4095;
    int nn = r >> 6, f = r & 63;
    s2m[(e * 64 + f) * 66 + nn] = g_y[(long)(e * 1024 + wwin) * 4096 + r];
  }
  __syncthreads();
  int wa = t >> 5, lane = t & 31, n0 = lane * 2;
  for (int pass = 0; pass < 3; pass++) {
    int oc0 = pass * 64 + wa * 8;
    ull acc[4][2];
#pragma unroll
    for (int k = 0; k < 4; k++) { acc[k][0] = 0ULL; acc[k][1] = 0ULL; }
#pragma unroll 4
    for (int c = 0; c < 192; c++) {
      ulonglong2 wA = *(const ulonglong2*)(g_wt192 + c * 192 + oc0);
      ulonglong2 wB = *(const ulonglong2*)(g_wt192 + c * 192 + oc0 + 4);
      float2 xv = *(const float2*)&s2m[c * 66 + n0];
      ull x0 = pk2(xv.x, xv.x), x1 = pk2(xv.y, xv.y);
      acc[0][0] = fma2(x0, wA.x, acc[0][0]); acc[0][1] = fma2(x1, wA.x, acc[0][1]);
      acc[1][0] = fma2(x0, wA.y, acc[1][0]); acc[1][1] = fma2(x1, wA.y, acc[1][1]);
      acc[2][0] = fma2(x0, wB.x, acc[2][0]); acc[2][1] = fma2(x1, wB.x, acc[2][1]);
      acc[3][0] = fma2(x0, wB.y, acc[3][0]); acc[3][1] = fma2(x1, wB.y, acc[3][1]);
    }
#pragma unroll
    for (int ni = 0; ni < 2; ni++) {
      int nn = n0 + ni;
      int i = nn >> 3, j = nn & 7;
      int hp = (wh * 8 + i + 4) & 255;
      int wp = (ww * 8 + j + 4) & 255;
      int pixel = hp * 256 + wp;
#pragma unroll
      for (int k = 0; k < 4; k++) {
        float2 u = up2(acc[k][ni]);
        int gi0 = (oc0 + k * 2) * 65536 + pixel;
        int gi1 = (oc0 + k * 2 + 1) * 65536 + pixel;
        g_xres[gi0] = u.x + x[gi0];
        g_xres[gi1] = u.y + x[gi1];
      }
    }
  }
}

// ---------------- K5: per-pixel LN2(192) + ff_in (192 -> 768), packed ------------
// dyn smem: sxn[192*128]
__global__ void k5_ln_ffin(const float* __restrict__ ln2w, const float* __restrict__ ln2b) {
  extern __shared__ float sxn[];
  __shared__ float red[256], red2[256], smean[128], srstd[128];
  int blk = blockIdx.x;
  int h = blk >> 1;
  int w0 = (blk & 1) * 128;
  int pix0 = h * 256 + w0;
  int t = threadIdx.x;
  for (int idx = t; idx < 24576; idx += 256) {
    int c = idx >> 7, p = idx & 127;
    sxn[idx] = g_xres[c * 65536 + pix0 + p];
  }
  __syncthreads();
  {
    int p = t & 127, g = t >> 7;
    float s = 0.f, s2v = 0.f;
    for (int c = g; c < 192; c += 2) { float v = sxn[c * 128 + p]; s += v; s2v += v * v; }
    red[t] = s;
    red2[t] = s2v;
  }
  __syncthreads();
  if (t < 128) {
    float s = red[t] + red[t + 128];
    float s2v = red2[t] + red2[t + 128];
    float m = s * (1.f / 192.f);
    float var = s2v * (1.f / 192.f) - m * m;
    smean[t] = m;
    srstd[t] = rsqrtf(var + 1e-5f);
  }
  __syncthreads();
  for (int idx = t; idx < 24576; idx += 256) {
    int c = idx >> 7, p = idx & 127;
    sxn[idx] = (sxn[idx] - smean[p]) * srstd[p] * ln2w[c] + ln2b[c];
  }
  __syncthreads();
  int wa = t >> 5, lane = t & 31;
  int p4 = lane * 4;
  for (int ob = 0; ob < 12; ob++) {
    int o0 = (ob * 8 + wa) * 8;
    ull acc[4][4];
#pragma unroll
    for (int k = 0; k < 4; k++)
#pragma unroll
      for (int pi = 0; pi < 4; pi++) acc[k][pi] = 0ULL;
#pragma unroll 2
    for (int c = 0; c < 192; c++) {
      ulonglong2 wA = *(const ulonglong2*)(g_wtin + c * 768 + o0);
      ulonglong2 wB = *(const ulonglong2*)(g_wtin + c * 768 + o0 + 4);
      float4 xv = *(const float4*)&sxn[c * 128 + p4];
      ull x0 = pk2(xv.x, xv.x), x1 = pk2(xv.y, xv.y);
      ull x2 = pk2(xv.z, xv.z), x3 = pk2(xv.w, xv.w);
      acc[0][0] = fma2(x0, wA.x, acc[0][0]); acc[0][1] = fma2(x1, wA.x, acc[0][1]);
      acc[0][2] = fma2(x2, wA.x, acc[0][2]); acc[0][3] = fma2(x3, wA.x, acc[0][3]);
      acc[1][0] = fma2(x0, wA.y, acc[1][0]); acc[1][1] = fma2(x1, wA.y, acc[1][1]);
      acc[1][2] = fma2(x2, wA.y, acc[1][2]); acc[1][3] = fma2(x3, wA.y, acc[1][3]);
      acc[2][0] = fma2(x0, wB.x, acc[2][0]); acc[2][1] = fma2(x1, wB.x, acc[2][1]);
      acc[2][2] = fma2(x2, wB.x, acc[2][2]); acc[2][3] = fma2(x3, wB.x, acc[2][3]);
      acc[3][0] = fma2(x0, wB.y, acc[3][0]); acc[3][1] = fma2(x1, wB.y, acc[3][1]);
      acc[3][2] = fma2(x2, wB.y, acc[3][2]); acc[3][3] = fma2(x3, wB.y, acc[3][3]);
    }
#pragma unroll
    for (int k = 0; k < 4; k++) {
      float2 u0 = up2(acc[k][0]);
      float2 u1 = up2(acc[k][1]);
      float2 u2 = up2(acc[k][2]);
      float2 u3 = up2(acc[k][3]);
      float4 ve = make_float4(u0.x, u1.x, u2.x, u3.x);
      float4 vo = make_float4(u0.y, u1.y, u2.y, u3.y);
      *(float4*)&g_hb[(o0 + k * 2) * 65536 + pix0 + p4] = ve;
      *(float4*)&g_hb[(o0 + k * 2 + 1) * 65536 + pix0 + p4] = vo;
    }
  }
}

// ---------------- K6: depthwise 3x3 (pad 1) + gelu(g1)*g2 ------------------------
__global__ void k6_dw(const float* __restrict__ dw) {
  int w = threadIdx.x;
  int h = blockIdx.x;
  int c = blockIdx.y;
  const float* f0 = dw + c * 9;
  const float* f1 = dw + (c + 384) * 9;
  const float* p0 = g_hb + c * 65536;
  const float* p1 = g_hb + (c + 384) * 65536;
  float a = 0.f, b = 0.f;
#pragma unroll
  for (int dh = 0; dh < 3; dh++) {
    int hh = h + dh - 1;
    if (hh < 0 || hh > 255) continue;
#pragma unroll
    for (int dwi = 0; dwi < 3; dwi++) {
      int wp = w + dwi - 1;
      if (wp < 0 || wp > 255) continue;
      a += p0[hh * 256 + wp] * f0[dh * 3 + dwi];
      b += p1[hh * 256 + wp] * f1[dh * 3 + dwi];
    }
  }
  float ge = 0.5f * a * (1.f + erff(a * 0.70710678118654752f));
  g_gb[c * 65536 + h * 256 + w] = ge * b;
}

// ---------------- K7: ff_out (384 -> 192) + residual -> d_out, packed ------------
// dyn smem: sg[384*64]
__global__ void k7_ffout(float* __restrict__ out) {
  extern __shared__ float sg[];
  int blk = blockIdx.x;
  int h = blk >> 2;
  int w0 = (blk & 3) * 64;
  int pix0 = h * 256 + w0;
  int t = threadIdx.x;
  for (int idx = t; idx < 24576; idx += 256) {
    int c = idx >> 6, p = idx & 63;
    sg[idx] = g_gb[c * 65536 + pix0 + p];
  }
  __syncthreads();
  int wa = t >> 5, lane = t & 31;
  int p2 = lane * 2;
  for (int ob = 0; ob < 3; ob++) {
    int o0 = (ob * 8 + wa) * 8;
    ull acc[4][2];
#pragma unroll
    for (int k = 0; k < 4; k++) { acc[k][0] = 0ULL; acc[k][1] = 0ULL; }
#pragma unroll 4
    for (int c = 0; c < 384; c++) {
      ulonglong2 wA = *(const ulonglong2*)(g_wtout + c * 192 + o0);
      ulonglong2 wB = *(const ulonglong2*)(g_wtout + c * 192 + o0 + 4);
      float2 xv = *(const float2*)&sg[c * 64 + p2];
      ull x0 = pk2(xv.x, xv.x), x1 = pk2(xv.y, xv.y);
      acc[0][0] = fma2(x0, wA.x, acc[0][0]); acc[0][1] = fma2(x1, wA.x, acc[0][1]);
      acc[1][0] = fma2(x0, wA.y, acc[1][0]); acc[1][1] = fma2(x1, wA.y, acc[1][1]);
      acc[2][0] = fma2(x0, wB.x, acc[2][0]); acc[2][1] = fma2(x1, wB.x, acc[2][1]);
      acc[3][0] = fma2(x0, wB.y, acc[3][0]); acc[3][1] = fma2(x1, wB.y, acc[3][1]);
    }
#pragma unroll
    for (int k = 0; k < 4; k++) {
      float2 u0 = up2(acc[k][0]);
      float2 u1 = up2(acc[k][1]);
      int oa = o0 + k * 2, ob2 = o0 + k * 2 + 1;
      int ia = oa * 65536 + pix0 + p2;
      int ib = ob2 * 65536 + pix0 + p2;
      float2 ra = *(const float2*)&g_xres[ia];
      float2 rb = *(const float2*)&g_xres[ib];
      float2 va = make_float2(ra.x + u0.x, ra.y + u1.x);
      float2 vb = make_float2(rb.x + u0.y, rb.y + u1.y);
      *(float2*)&out[ia] = va;
      *(float2*)&out[ib] = vb;
    }
  }
}

// ---------------- host launcher --------------------------------------------------
extern "C" void kernel_launch(void* const* d_in, const int* in_sizes, int n_in,
                              void* d_out, int out_size) {
  const float* x    = (const float*)d_in[0];
  const float* ln1w = (const float*)d_in[1];
  const float* ln1b = (const float*)d_in[2];
  const float* ln2w = (const float*)d_in[3];
  const float* ln2b = (const float*)d_in[4];
  const float* wqkv = (const float*)d_in[5];
  const float* w11  = (const float*)d_in[6];
  const float* b11  = (const float*)d_in[7];
  const float* w12  = (const float*)d_in[8];
  const float* b12  = (const float*)d_in[9];
  const float* w2   = (const float*)d_in[10];
  const float* b2   = (const float*)d_in[11];
  const float* c11  = (const float*)d_in[12];
  const float* ffin = (const float*)d_in[13];
  const float* ffdw = (const float*)d_in[14];
  const float* ffou = (const float*)d_in[15];
  float* out = (float*)d_out;

  const int smem1 = (4160 + 4224 + 192 * 65) * 4;       // 83456
  const int smem2 = (8192 + 64 * 256) * 4;              // 98304
  const int smem3 = (192 * 66 + 64 * 66) * 4;           // 67584
  const int smem4 = (192 * 66) * 4;                     // 50688
  const int smem5 = (192 * 128) * 4;                    // 98304
  const int smem7 = (384 * 64) * 4;                     // 98304
  cudaFuncSetAttribute(k1_qkv, cudaFuncAttributeMaxDynamicSharedMemorySize, smem1);
  cudaFuncSetAttribute(k2_attn, cudaFuncAttributeMaxDynamicSharedMemorySize, smem2);
  cudaFuncSetAttribute(k3_geglu, cudaFuncAttributeMaxDynamicSharedMemorySize, smem3);
  cudaFuncSetAttribute(k4_conv11, cudaFuncAttributeMaxDynamicSharedMemorySize, smem4);
  cudaFuncSetAttribute(k5_ln_ffin, cudaFuncAttributeMaxDynamicSharedMemorySize, smem5);
  cudaFuncSetAttribute(k7_ffout, cudaFuncAttributeMaxDynamicSharedMemorySize, smem7);

  kpos<<<1, 64>>>();
  ktrans_all<<<(768 * 192 + 255) / 256, 256>>>(c11, ffin, ffou);
  k1_qkv<<<3072, 256, smem1>>>(x, ln1w, ln1b, wqkv);
  {
    dim3 g2(1024, 6);
    k2_attn<<<g2, 256, smem2>>>();
  }
  k3_geglu<<<3072, 256, smem3>>>(w11, b11, w12, b12, w2, b2);
  k4_conv11<<<1024, 256, smem4>>>(x);
  k5_ln_ffin<<<512, 256, smem5>>>(ln2w, ln2b);
  {
    dim3 g6(256, 384);
    k6_dw<<<g6, 256>>>(ffdw);
  }
  k7_ffout<<<1024, 256, smem7>>>(out);
}

// round 3
// speedup vs baseline: 1.6842x; 1.2141x over previous
#include <cuda_runtime.h>
#include <math.h>

typedef unsigned long long ull;

// ---------------- packed f32x2 helpers ------------------------------------------
__device__ __forceinline__ ull fma2(ull a, ull b, ull c) {
  ull d;
  asm("fma.rn.f32x2 %0, %1, %2, %3;" : "=l"(d) : "l"(a), "l"(b), "l"(c));
  return d;
}
__device__ __forceinline__ ull pk2(float x, float y) {
  ull r;
  asm("mov.b64 %0, {%1, %2};" : "=l"(r) : "f"(x), "f"(y));
  return r;
}
__device__ __forceinline__ float2 up2(ull a) {
  float2 f;
  asm("mov.b64 {%0, %1}, %2;" : "=f"(f.x), "=f"(f.y) : "l"(a));
  return f;
}

// ---------------- static device scratch ------------------------------------------
__device__ float g_pos[64 * 64];
__device__ float g_q[3 * 1024 * 4 * 64 * 16];
__device__ float g_k[3 * 1024 * 4 * 64 * 16];
__device__ float g_v[3 * 1024 * 4 * 64 * 16];
__device__ float g_gin[3 * 1024 * 64 * 192];
__device__ float g_y[3 * 1024 * 64 * 64];
__device__ float g_xres[192 * 65536];
__device__ float g_hb[768 * 65536];
__device__ float g_gb[384 * 65536];
__device__ float g_wt192[192 * 192];
__device__ float g_wtin[192 * 768];
__device__ float g_wtout[384 * 192];

// ---------------- K0a: sine positional encoding ----------------------------------
__global__ void kpos() {
  int n = threadIdx.x;
  int i = n >> 3, j = n & 7;
  double scale = 6.283185307179586476925286766559;
  double yv = (double)(i + 1) / (8.0 + 1e-6) * scale;
  double xv = (double)(j + 1) / (8.0 + 1e-6) * scale;
  for (int c = 0; c < 64; c++) {
    double base = (c < 32) ? yv : xv;
    int k = (c < 32) ? c : (c - 32);
    double dt = pow(10000.0, (double)(k >> 1) / 16.0);
    double v = base / dt;
    g_pos[n * 64 + c] = (float)(((k & 1) == 0) ? sin(v) : cos(v));
  }
}

// ---------------- K0b: weight transposes -----------------------------------------
__global__ void ktrans_all(const float* __restrict__ c11,
                           const float* __restrict__ ffin,
                           const float* __restrict__ ffout) {
  int idx = blockIdx.x * 256 + threadIdx.x;
  if (idx < 192 * 192) { int r = idx / 192, c = idx - r * 192; g_wt192[c * 192 + r] = c11[idx]; }
  if (idx < 768 * 192) { int r = idx / 192, c = idx - r * 192; g_wtin[c * 768 + r] = ffin[idx]; }
  if (idx < 192 * 384) { int r = idx / 384, c = idx - r * 384; g_wtout[c * 192 + r] = ffout[idx]; }
}

// ---------------- K1: shift+window + LN1 + pos + QKV GEMM ------------------------
__global__ void k1_qkv(const float* __restrict__ x, const float* __restrict__ ln1w,
                       const float* __restrict__ ln1b, const float* __restrict__ wqkv) {
  extern __shared__ float sm1[];
  float* sx = sm1;               // [n][c] stride 65
  float* snT = sm1 + 4160;       // [c][n] stride 66
  float* sout = sm1 + 8384;      // [jc][n] stride 65
  int blk = blockIdx.x;
  int e = blk >> 10, wwin = blk & 1023;
  int wh = wwin >> 5, ww = wwin & 31;
  int t = threadIdx.x;
  for (int idx = t; idx < 4096; idx += 256) {
    int c = idx >> 6, n = idx & 63;
    int i = n >> 3, j = n & 7;
    int h0 = (wh * 8 + i + 4) & 255;
    int w0 = (ww * 8 + j + 4) & 255;
    sx[n * 65 + c] = x[((e * 64 + c) * 256 + h0) * 256 + w0];
  }
  __syncthreads();
  if (t < 64) {
    int n = t;
    float m = 0.f;
#pragma unroll
    for (int c = 0; c < 64; c++) m += sx[n * 65 + c];
    m *= (1.f / 64.f);
    float v = 0.f;
#pragma unroll
    for (int c = 0; c < 64; c++) { float d = sx[n * 65 + c] - m; v += d * d; }
    v *= (1.f / 64.f);
    float rs = rsqrtf(v + 1e-5f);
    for (int c = 0; c < 64; c++)
      snT[c * 66 + n] = (sx[n * 65 + c] - m) * rs * ln1w[c] + ln1b[c] + g_pos[n * 64 + c];
  }
  __syncthreads();
  int wa = t >> 5, lane = t & 31, n0 = lane * 2;
  for (int pass = 0; pass < 3; pass++) {
    int jc0 = pass * 64 + wa * 8;
    ull acc[4][2];
#pragma unroll
    for (int a = 0; a < 4; a++) { acc[a][0] = 0ULL; acc[a][1] = 0ULL; }
#pragma unroll 4
    for (int c = 0; c < 64; c++) {
      ulonglong2 wA = *(const ulonglong2*)(wqkv + c * 192 + jc0);
      ulonglong2 wB = *(const ulonglong2*)(wqkv + c * 192 + jc0 + 4);
      float2 xv = *(const float2*)&snT[c * 66 + n0];
      ull x0 = pk2(xv.x, xv.x), x1 = pk2(xv.y, xv.y);
      acc[0][0] = fma2(x0, wA.x, acc[0][0]); acc[0][1] = fma2(x1, wA.x, acc[0][1]);
      acc[1][0] = fma2(x0, wA.y, acc[1][0]); acc[1][1] = fma2(x1, wA.y, acc[1][1]);
      acc[2][0] = fma2(x0, wB.x, acc[2][0]); acc[2][1] = fma2(x1, wB.x, acc[2][1]);
      acc[3][0] = fma2(x0, wB.y, acc[3][0]); acc[3][1] = fma2(x1, wB.y, acc[3][1]);
    }
#pragma unroll
    for (int a = 0; a < 4; a++) {
#pragma unroll
      for (int ni = 0; ni < 2; ni++) {
        float2 f = up2(acc[a][ni]);
        sout[(jc0 + a * 2) * 65 + n0 + ni] = f.x;
        sout[(jc0 + a * 2 + 1) * 65 + n0 + ni] = f.y;
      }
    }
  }
  __syncthreads();
  long wb = (long)(e * 1024 + wwin);
  for (int idx = t; idx < 12288; idx += 256) {
    int ch = idx & 15, n = (idx >> 4) & 63, hh = (idx >> 10) & 3, p = idx >> 12;
    int jc = p * 64 + ch * 4 + hh;
    float vv = sout[jc * 65 + n];
    long qi = (wb * 4 + hh) * 1024 + n * 16 + ch;
    if (p == 0) g_q[qi] = vv;
    else if (p == 1) g_k[qi] = vv;
    else g_v[qi] = vv;
  }
  for (int idx = t; idx < 4096; idx += 256) {
    int c2 = idx & 63, n = idx >> 6;
    int hh = c2 >> 4, ch = c2 & 15;
    g_gin[(wb * 64 + n) * 192 + 128 + c2] = sout[(ch * 4 + hh) * 65 + n];
  }
}

// ---------------- K2: 6 cross-exposure attentions, single-pass, 2 queries/thread -
// block 128 threads = 4 heads x 32 lanes; thread owns queries lane, lane+32.
// dyn smem: sk[4096] | sv[4096] (32KB)
__global__ void k2_attn() {
  extern __shared__ float sm2[];
  float* sk = sm2;
  float* sv = sm2 + 4096;
  const int e_of[6]  = {0, 0, 1, 1, 2, 2};
  const int kv_of[6] = {1, 2, 0, 2, 1, 0};
  const int sl_of[6] = {0, 1, 0, 1, 0, 1};
  int w = blockIdx.x, z = blockIdx.y;
  int e = e_of[z], ekv = kv_of[z], sl = sl_of[z];
  int t = threadIdx.x;
  int hh = t >> 5, lane = t & 31;
  long kb = (long)(ekv * 1024 + w) * 4096;
  for (int idx = t; idx < 1024; idx += 128) {
    *(float4*)&sk[idx * 4] = *(const float4*)&g_k[kb + idx * 4];
    *(float4*)&sv[idx * 4] = *(const float4*)&g_v[kb + idx * 4];
  }
  long qbase = (long)(e * 1024 + w) * 4096 + hh * 1024;
  ull qa[8], qb[8];
  {
    const ulonglong2* qg = (const ulonglong2*)(g_q + qbase + lane * 16);
    ulonglong2 a0 = qg[0], a1 = qg[1], a2 = qg[2], a3 = qg[3];
    qa[0] = a0.x; qa[1] = a0.y; qa[2] = a1.x; qa[3] = a1.y;
    qa[4] = a2.x; qa[5] = a2.y; qa[6] = a3.x; qa[7] = a3.y;
    const ulonglong2* qh = (const ulonglong2*)(g_q + qbase + (lane + 32) * 16);
    ulonglong2 b0 = qh[0], b1 = qh[1], b2 = qh[2], b3 = qh[3];
    qb[0] = b0.x; qb[1] = b0.y; qb[2] = b1.x; qb[3] = b1.y;
    qb[4] = b2.x; qb[5] = b2.y; qb[6] = b3.x; qb[7] = b3.y;
  }
  __syncthreads();
  int wh = w >> 5, ww = w & 31;
  int na = lane, nb = lane + 32;
  // Swin shift mask as 64-bit word: bit m set -> masked (-100)
  ull mA = 0ULL, mB = 0ULL;
  if (wh == 31) {
    mA |= ((na >> 3) < 4) ? 0xFFFFFFFF00000000ULL : 0x00000000FFFFFFFFULL;
    mB |= ((nb >> 3) < 4) ? 0xFFFFFFFF00000000ULL : 0x00000000FFFFFFFFULL;
  }
  if (ww == 31) {
    mA |= ((na & 7) < 4) ? 0xF0F0F0F0F0F0F0F0ULL : 0x0F0F0F0F0F0F0F0FULL;
    mB |= ((nb & 7) < 4) ? 0xF0F0F0F0F0F0F0F0ULL : 0x0F0F0F0F0F0F0F0FULL;
  }
  float suma = 0.f, sumb = 0.f;
  ull acca[8], accb[8];
#pragma unroll
  for (int c = 0; c < 8; c++) { acca[c] = 0ULL; accb[c] = 0ULL; }
  const ulonglong2* skp2 = (const ulonglong2*)(sk + hh * 1024);
  const ulonglong2* svp2 = (const ulonglong2*)(sv + hh * 1024);
#pragma unroll 4
  for (int m = 0; m < 64; m++) {
    ulonglong2 k0 = skp2[m * 4], k1 = skp2[m * 4 + 1];
    ulonglong2 k2 = skp2[m * 4 + 2], k3 = skp2[m * 4 + 3];
    ull da = 0ULL, db = 0ULL;
    da = fma2(qa[0], k0.x, da); db = fma2(qb[0], k0.x, db);
    da = fma2(qa[1], k0.y, da); db = fma2(qb[1], k0.y, db);
    da = fma2(qa[2], k1.x, da); db = fma2(qb[2], k1.x, db);
    da = fma2(qa[3], k1.y, da); db = fma2(qb[3], k1.y, db);
    da = fma2(qa[4], k2.x, da); db = fma2(qb[4], k2.x, db);
    da = fma2(qa[5], k2.y, da); db = fma2(qb[5], k2.y, db);
    da = fma2(qa[6], k3.x, da); db = fma2(qb[6], k3.x, db);
    da = fma2(qa[7], k3.y, da); db = fma2(qb[7], k3.y, db);
    float2 fa = up2(da), fb = up2(db);
    float sa = (fa.x + fa.y) * 0.125f;
    float sb = (fb.x + fb.y) * 0.125f;
    if ((mA >> m) & 1) sa -= 100.f;
    if ((mB >> m) & 1) sb -= 100.f;
    float pa = __expf(sa), pb = __expf(sb);
    suma += pa; sumb += pb;
    ull ppa = pk2(pa, pa), ppb = pk2(pb, pb);
    ulonglong2 v0 = svp2[m * 4], v1 = svp2[m * 4 + 1];
    ulonglong2 v2 = svp2[m * 4 + 2], v3 = svp2[m * 4 + 3];
    acca[0] = fma2(ppa, v0.x, acca[0]); accb[0] = fma2(ppb, v0.x, accb[0]);
    acca[1] = fma2(ppa, v0.y, acca[1]); accb[1] = fma2(ppb, v0.y, accb[1]);
    acca[2] = fma2(ppa, v1.x, acca[2]); accb[2] = fma2(ppb, v1.x, accb[2]);
    acca[3] = fma2(ppa, v1.y, acca[3]); accb[3] = fma2(ppb, v1.y, accb[3]);
    acca[4] = fma2(ppa, v2.x, acca[4]); accb[4] = fma2(ppb, v2.x, accb[4]);
    acca[5] = fma2(ppa, v2.y, acca[5]); accb[5] = fma2(ppb, v2.y, accb[5]);
    acca[6] = fma2(ppa, v3.x, acca[6]); accb[6] = fma2(ppb, v3.x, accb[6]);
    acca[7] = fma2(ppa, v3.y, acca[7]); accb[7] = fma2(ppb, v3.y, accb[7]);
  }
  float inva = 1.f / suma, invb = 1.f / sumb;
  long gba = ((long)(e * 1024 + w) * 64 + na) * 192 + sl * 64 + hh * 16;
  long gbb = ((long)(e * 1024 + w) * 64 + nb) * 192 + sl * 64 + hh * 16;
#pragma unroll
  for (int c4 = 0; c4 < 4; c4++) {
    float2 u0 = up2(acca[c4 * 2]);
    float2 u1 = up2(acca[c4 * 2 + 1]);
    *(float4*)&g_gin[gba + c4 * 4] = make_float4(u0.x * inva, u0.y * inva, u1.x * inva, u1.y * inva);
    float2 w0 = up2(accb[c4 * 2]);
    float2 w1 = up2(accb[c4 * 2 + 1]);
    *(float4*)&g_gin[gbb + c4 * 4] = make_float4(w0.x * invb, w0.y * invb, w1.x * invb, w1.y * invb);
  }
}

// ---------------- K3: per-exposure GEGLU (192 -> 64), smem reuse -----------------
// dyn smem: sx[192*66] (reused as st[64*66] for the second GEMM)
__global__ void k3_geglu(const float* __restrict__ w11, const float* __restrict__ b11,
                         const float* __restrict__ w12, const float* __restrict__ b12,
                         const float* __restrict__ w2, const float* __restrict__ b2) {
  extern __shared__ float sm3[];
  float* sx = sm3;
  int blk = blockIdx.x;
  int e = blk >> 10;
  const float* W11 = w11 + e * 12288;
  const float* W12 = w12 + e * 12288;
  const float* W2 = w2 + e * 4096;
  const float* B11 = b11 + e * 64;
  const float* B12 = b12 + e * 64;
  const float* B2 = b2 + e * 64;
  int t = threadIdx.x;
  long gbase = (long)blk * 12288;
  for (int idx = t; idx < 12288; idx += 256) {
    int nn = idx / 192, c = idx - nn * 192;
    sx[c * 66 + nn] = g_gin[gbase + idx];
  }
  __syncthreads();
  int wa = t >> 5, lane = t & 31, n0 = lane * 2;
  int f0 = wa * 8;
  ull a[4][2], g[4][2];
#pragma unroll
  for (int k = 0; k < 4; k++) {
    ull bi = pk2(B11[f0 + k * 2], B11[f0 + k * 2 + 1]);
    ull gi = pk2(B12[f0 + k * 2], B12[f0 + k * 2 + 1]);
    a[k][0] = bi; a[k][1] = bi;
    g[k][0] = gi; g[k][1] = gi;
  }
#pragma unroll 4
  for (int c = 0; c < 192; c++) {
    ulonglong2 wA = *(const ulonglong2*)(W11 + c * 64 + f0);
    ulonglong2 wB = *(const ulonglong2*)(W11 + c * 64 + f0 + 4);
    ulonglong2 vA = *(const ulonglong2*)(W12 + c * 64 + f0);
    ulonglong2 vB = *(const ulonglong2*)(W12 + c * 64 + f0 + 4);
    float2 xv = *(const float2*)&sx[c * 66 + n0];
    ull x0 = pk2(xv.x, xv.x), x1 = pk2(xv.y, xv.y);
    a[0][0] = fma2(x0, wA.x, a[0][0]); a[0][1] = fma2(x1, wA.x, a[0][1]);
    a[1][0] = fma2(x0, wA.y, a[1][0]); a[1][1] = fma2(x1, wA.y, a[1][1]);
    a[2][0] = fma2(x0, wB.x, a[2][0]); a[2][1] = fma2(x1, wB.x, a[2][1]);
    a[3][0] = fma2(x0, wB.y, a[3][0]); a[3][1] = fma2(x1, wB.y, a[3][1]);
    g[0][0] = fma2(x0, vA.x, g[0][0]); g[0][1] = fma2(x1, vA.x, g[0][1]);
    g[1][0] = fma2(x0, vA.y, g[1][0]); g[1][1] = fma2(x1, vA.y, g[1][1]);
    g[2][0] = fma2(x0, vB.x, g[2][0]); g[2][1] = fma2(x1, vB.x, g[2][1]);
    g[3][0] = fma2(x0, vB.y, g[3][0]); g[3][1] = fma2(x1, vB.y, g[3][1]);
  }
  float tv[4][2][2];
#pragma unroll
  for (int k = 0; k < 4; k++) {
#pragma unroll
    for (int ni = 0; ni < 2; ni++) {
      float2 av = up2(a[k][ni]);
      float2 gv = up2(g[k][ni]);
      tv[k][ni][0] = 0.5f * av.x * (1.f + erff(av.x * 0.70710678118654752f)) * gv.x;
      tv[k][ni][1] = 0.5f * av.y * (1.f + erff(av.y * 0.70710678118654752f)) * gv.y;
    }
  }
  __syncthreads();
  float* st = sm3;   // reuse
#pragma unroll
  for (int k = 0; k < 4; k++) {
#pragma unroll
    for (int ni = 0; ni < 2; ni++) {
      st[(f0 + k * 2) * 66 + n0 + ni] = tv[k][ni][0];
      st[(f0 + k * 2 + 1) * 66 + n0 + ni] = tv[k][ni][1];
    }
  }
  __syncthreads();
  ull acc[4][2];
#pragma unroll
  for (int k = 0; k < 4; k++) {
    ull bi = pk2(B2[f0 + k * 2], B2[f0 + k * 2 + 1]);
    acc[k][0] = bi; acc[k][1] = bi;
  }
#pragma unroll 4
  for (int c = 0; c < 64; c++) {
    ulonglong2 wA = *(const ulonglong2*)(W2 + c * 64 + f0);
    ulonglong2 wB = *(const ulonglong2*)(W2 + c * 64 + f0 + 4);
    float2 xv = *(const float2*)&st[c * 66 + n0];
    ull x0 = pk2(xv.x, xv.x), x1 = pk2(xv.y, xv.y);
    acc[0][0] = fma2(x0, wA.x, acc[0][0]); acc[0][1] = fma2(x1, wA.x, acc[0][1]);
    acc[1][0] = fma2(x0, wA.y, acc[1][0]); acc[1][1] = fma2(x1, wA.y, acc[1][1]);
    acc[2][0] = fma2(x0, wB.x, acc[2][0]); acc[2][1] = fma2(x1, wB.x, acc[2][1]);
    acc[3][0] = fma2(x0, wB.y, acc[3][0]); acc[3][1] = fma2(x1, wB.y, acc[3][1]);
  }
  long ybase = (long)blk * 4096;
#pragma unroll
  for (int ni = 0; ni < 2; ni++) {
    float2 u0 = up2(acc[0][ni]);
    float2 u1 = up2(acc[1][ni]);
    float2 u2 = up2(acc[2][ni]);
    float2 u3 = up2(acc[3][ni]);
    *(float4*)&g_y[ybase + (n0 + ni) * 64 + f0] = make_float4(u0.x, u0.y, u1.x, u1.y);
    *(float4*)&g_y[ybase + (n0 + ni) * 64 + f0 + 4] = make_float4(u2.x, u2.y, u3.x, u3.y);
  }
}

// ---------------- K4: window reverse + conv1x1 + roll +4 + residual --------------
__global__ void k4_conv11(const float* __restrict__ x) {
  extern __shared__ float s2m[];
  int wwin = blockIdx.x;
  int wh = wwin >> 5, ww = wwin & 31;
  int t = threadIdx.x;
  for (int idx = t; idx < 12288; idx += 256) {
    int e = idx >> 12;
    int r = idx & 4095;
    int nn = r >> 6, f = r & 63;
    s2m[(e * 64 + f) * 66 + nn] = g_y[(long)(e * 1024 + wwin) * 4096 + r];
  }
  __syncthreads();
  int wa = t >> 5, lane = t & 31, n0 = lane * 2;
  for (int pass = 0; pass < 3; pass++) {
    int oc0 = pass * 64 + wa * 8;
    ull acc[4][2];
#pragma unroll
    for (int k = 0; k < 4; k++) { acc[k][0] = 0ULL; acc[k][1] = 0ULL; }
#pragma unroll 4
    for (int c = 0; c < 192; c++) {
      ulonglong2 wA = *(const ulonglong2*)(g_wt192 + c * 192 + oc0);
      ulonglong2 wB = *(const ulonglong2*)(g_wt192 + c * 192 + oc0 + 4);
      float2 xv = *(const float2*)&s2m[c * 66 + n0];
      ull x0 = pk2(xv.x, xv.x), x1 = pk2(xv.y, xv.y);
      acc[0][0] = fma2(x0, wA.x, acc[0][0]); acc[0][1] = fma2(x1, wA.x, acc[0][1]);
      acc[1][0] = fma2(x0, wA.y, acc[1][0]); acc[1][1] = fma2(x1, wA.y, acc[1][1]);
      acc[2][0] = fma2(x0, wB.x, acc[2][0]); acc[2][1] = fma2(x1, wB.x, acc[2][1]);
      acc[3][0] = fma2(x0, wB.y, acc[3][0]); acc[3][1] = fma2(x1, wB.y, acc[3][1]);
    }
#pragma unroll
    for (int ni = 0; ni < 2; ni++) {
      int nn = n0 + ni;
      int i = nn >> 3, j = nn & 7;
      int hp = (wh * 8 + i + 4) & 255;
      int wp = (ww * 8 + j + 4) & 255;
      int pixel = hp * 256 + wp;
#pragma unroll
      for (int k = 0; k < 4; k++) {
        float2 u = up2(acc[k][ni]);
        int gi0 = (oc0 + k * 2) * 65536 + pixel;
        int gi1 = (oc0 + k * 2 + 1) * 65536 + pixel;
        g_xres[gi0] = u.x + x[gi0];
        g_xres[gi1] = u.y + x[gi1];
      }
    }
  }
}

// ---------------- K5: per-pixel LN2(192) + ff_in (192 -> 768) --------------------
// 64 pixels per block (48KB smem), 16 outputs x 2 pixels per thread.
__global__ void k5_ln_ffin(const float* __restrict__ ln2w, const float* __restrict__ ln2b) {
  extern __shared__ float sxn[];   // 192*64
  __shared__ float red[256], red2[256], smean[64], srstd[64];
  int blk = blockIdx.x;
  int h = blk >> 2;
  int w0 = (blk & 3) * 64;
  int pix0 = h * 256 + w0;
  int t = threadIdx.x;
  for (int idx = t; idx < 12288; idx += 256) {
    int c = idx >> 6, p = idx & 63;
    sxn[idx] = g_xres[c * 65536 + pix0 + p];
  }
  __syncthreads();
  {
    int p = t & 63, g = t >> 6;
    float s = 0.f, s2v = 0.f;
    for (int c = g; c < 192; c += 4) { float v = sxn[c * 64 + p]; s += v; s2v += v * v; }
    red[t] = s;
    red2[t] = s2v;
  }
  __syncthreads();
  if (t < 64) {
    float s = red[t] + red[64 + t] + red[128 + t] + red[192 + t];
    float s2v = red2[t] + red2[64 + t] + red2[128 + t] + red2[192 + t];
    float m = s * (1.f / 192.f);
    float var = s2v * (1.f / 192.f) - m * m;
    smean[t] = m;
    srstd[t] = rsqrtf(var + 1e-5f);
  }
  __syncthreads();
  for (int idx = t; idx < 12288; idx += 256) {
    int c = idx >> 6, p = idx & 63;
    sxn[idx] = (sxn[idx] - smean[p]) * srstd[p] * ln2w[c] + ln2b[c];
  }
  __syncthreads();
  int wa = t >> 5, lane = t & 31;
  int p2 = lane * 2;
  for (int ob = 0; ob < 6; ob++) {
    int o0 = (ob * 8 + wa) * 16;
    ull acc[8][2];
#pragma unroll
    for (int k = 0; k < 8; k++) { acc[k][0] = 0ULL; acc[k][1] = 0ULL; }
#pragma unroll 2
    for (int c = 0; c < 192; c++) {
      ulonglong2 wA = *(const ulonglong2*)(g_wtin + c * 768 + o0);
      ulonglong2 wB = *(const ulonglong2*)(g_wtin + c * 768 + o0 + 4);
      ulonglong2 wC = *(const ulonglong2*)(g_wtin + c * 768 + o0 + 8);
      ulonglong2 wD = *(const ulonglong2*)(g_wtin + c * 768 + o0 + 12);
      float2 xv = *(const float2*)&sxn[c * 64 + p2];
      ull x0 = pk2(xv.x, xv.x), x1 = pk2(xv.y, xv.y);
      acc[0][0] = fma2(x0, wA.x, acc[0][0]); acc[0][1] = fma2(x1, wA.x, acc[0][1]);
      acc[1][0] = fma2(x0, wA.y, acc[1][0]); acc[1][1] = fma2(x1, wA.y, acc[1][1]);
      acc[2][0] = fma2(x0, wB.x, acc[2][0]); acc[2][1] = fma2(x1, wB.x, acc[2][1]);
      acc[3][0] = fma2(x0, wB.y, acc[3][0]); acc[3][1] = fma2(x1, wB.y, acc[3][1]);
      acc[4][0] = fma2(x0, wC.x, acc[4][0]); acc[4][1] = fma2(x1, wC.x, acc[4][1]);
      acc[5][0] = fma2(x0, wC.y, acc[5][0]); acc[5][1] = fma2(x1, wC.y, acc[5][1]);
      acc[6][0] = fma2(x0, wD.x, acc[6][0]); acc[6][1] = fma2(x1, wD.x, acc[6][1]);
      acc[7][0] = fma2(x0, wD.y, acc[7][0]); acc[7][1] = fma2(x1, wD.y, acc[7][1]);
    }
#pragma unroll
    for (int k = 0; k < 8; k++) {
      float2 u0 = up2(acc[k][0]);
      float2 u1 = up2(acc[k][1]);
      *(float2*)&g_hb[(o0 + k * 2) * 65536 + pix0 + p2] = make_float2(u0.x, u1.x);
      *(float2*)&g_hb[(o0 + k * 2 + 1) * 65536 + pix0 + p2] = make_float2(u0.y, u1.y);
    }
  }
}

// ---------------- K6: depthwise 3x3 (pad 1) + gelu(g1)*g2, 4 rows/block ----------
__global__ void k6_dw(const float* __restrict__ dw) {
  __shared__ float s0[6][258];
  __shared__ float s1[6][258];
  int h0 = blockIdx.x * 4;
  int c = blockIdx.y;
  int t = threadIdx.x;
  const float* p0 = g_hb + c * 65536;
  const float* p1 = g_hb + (c + 384) * 65536;
  for (int idx = t; idx < 6 * 258; idx += 256) {
    int r = idx / 258, cc = idx - r * 258;
    int hh = h0 - 1 + r, wp = cc - 1;
    float v0 = 0.f, v1 = 0.f;
    if (hh >= 0 && hh < 256 && wp >= 0 && wp < 256) {
      v0 = p0[hh * 256 + wp];
      v1 = p1[hh * 256 + wp];
    }
    s0[r][cc] = v0;
    s1[r][cc] = v1;
  }
  float f0r[9], f1r[9];
#pragma unroll
  for (int k = 0; k < 9; k++) { f0r[k] = dw[c * 9 + k]; f1r[k] = dw[(c + 384) * 9 + k]; }
  __syncthreads();
  int w = t;
#pragma unroll
  for (int r = 0; r < 4; r++) {
    float a = 0.f, b = 0.f;
#pragma unroll
    for (int dh = 0; dh < 3; dh++) {
#pragma unroll
      for (int dwi = 0; dwi < 3; dwi++) {
        a += s0[r + dh][w + dwi] * f0r[dh * 3 + dwi];
        b += s1[r + dh][w + dwi] * f1r[dh * 3 + dwi];
      }
    }
    float ge = 0.5f * a * (1.f + erff(a * 0.70710678118654752f));
    g_gb[c * 65536 + (h0 + r) * 256 + w] = ge * b;
  }
}

// ---------------- K7: ff_out (384 -> 192) + residual, 32 pixels/block ------------
__global__ void k7_ffout(float* __restrict__ out) {
  extern __shared__ float sg[];   // 384*32
  int blk = blockIdx.x;
  int h = blk >> 3;
  int w0 = (blk & 7) * 32;
  int pix0 = h * 256 + w0;
  int t = threadIdx.x;
  for (int idx = t; idx < 12288; idx += 256) {
    int c = idx >> 5, p = idx & 31;
    sg[idx] = g_gb[c * 65536 + pix0 + p];
  }
  __syncthreads();
  int wa = t >> 5, lane = t & 31;
  int p = lane;
  for (int ob = 0; ob < 3; ob++) {
    int o0 = (ob * 8 + wa) * 8;
    ull acc[4];
#pragma unroll
    for (int k = 0; k < 4; k++) acc[k] = 0ULL;
#pragma unroll 4
    for (int c = 0; c < 384; c++) {
      ulonglong2 wA = *(const ulonglong2*)(g_wtout + c * 192 + o0);
      ulonglong2 wB = *(const ulonglong2*)(g_wtout + c * 192 + o0 + 4);
      float xv = sg[c * 32 + p];
      ull x0 = pk2(xv, xv);
      acc[0] = fma2(x0, wA.x, acc[0]);
      acc[1] = fma2(x0, wA.y, acc[1]);
      acc[2] = fma2(x0, wB.x, acc[2]);
      acc[3] = fma2(x0, wB.y, acc[3]);
    }
#pragma unroll
    for (int k = 0; k < 4; k++) {
      float2 u = up2(acc[k]);
      int ia = (o0 + k * 2) * 65536 + pix0 + p;
      int ib = (o0 + k * 2 + 1) * 65536 + pix0 + p;
      out[ia] = g_xres[ia] + u.x;
      out[ib] = g_xres[ib] + u.y;
    }
  }
}

// ---------------- host launcher --------------------------------------------------
extern "C" void kernel_launch(void* const* d_in, const int* in_sizes, int n_in,
                              void* d_out, int out_size) {
  const float* x    = (const float*)d_in[0];
  const float* ln1w = (const float*)d_in[1];
  const float* ln1b = (const float*)d_in[2];
  const float* ln2w = (const float*)d_in[3];
  const float* ln2b = (const float*)d_in[4];
  const float* wqkv = (const float*)d_in[5];
  const float* w11  = (const float*)d_in[6];
  const float* b11  = (const float*)d_in[7];
  const float* w12  = (const float*)d_in[8];
  const float* b12  = (const float*)d_in[9];
  const float* w2   = (const float*)d_in[10];
  const float* b2   = (const float*)d_in[11];
  const float* c11  = (const float*)d_in[12];
  const float* ffin = (const float*)d_in[13];
  const float* ffdw = (const float*)d_in[14];
  const float* ffou = (const float*)d_in[15];
  float* out = (float*)d_out;

  const int smem1 = (4160 + 4224 + 192 * 65) * 4;       // 83456
  const int smem2 = 8192 * 4;                           // 32768
  const int smem3 = (192 * 66) * 4;                     // 50688
  const int smem4 = (192 * 66) * 4;                     // 50688
  const int smem5 = (192 * 64) * 4;                     // 49152
  const int smem7 = (384 * 32) * 4;                     // 49152
  cudaFuncSetAttribute(k1_qkv, cudaFuncAttributeMaxDynamicSharedMemorySize, smem1);
  cudaFuncSetAttribute(k2_attn, cudaFuncAttributeMaxDynamicSharedMemorySize, smem2);
  cudaFuncSetAttribute(k3_geglu, cudaFuncAttributeMaxDynamicSharedMemorySize, smem3);
  cudaFuncSetAttribute(k4_conv11, cudaFuncAttributeMaxDynamicSharedMemorySize, smem4);
  cudaFuncSetAttribute(k5_ln_ffin, cudaFuncAttributeMaxDynamicSharedMemorySize, smem5);
  cudaFuncSetAttribute(k7_ffout, cudaFuncAttributeMaxDynamicSharedMemorySize, smem7);

  kpos<<<1, 64>>>();
  ktrans_all<<<(768 * 192 + 255) / 256, 256>>>(c11, ffin, ffou);
  k1_qkv<<<3072, 256, smem1>>>(x, ln1w, ln1b, wqkv);
  {
    dim3 g2(1024, 6);
    k2_attn<<<g2, 128, smem2>>>();
  }
  k3_geglu<<<3072, 256, smem3>>>(w11, b11, w12, b12, w2, b2);
  k4_conv11<<<1024, 256, smem4>>>(x);
  k5_ln_ffin<<<1024, 256, smem5>>>(ln2w, ln2b);
  {
    dim3 g6(64, 384);
    k6_dw<<<g6, 256>>>(ffdw);
  }
  k7_ffout<<<2048, 256, smem7>>>(out);
}

// round 4
// speedup vs baseline: 2.9701x; 1.7636x over previous
#include <cuda_runtime.h>
#include <math.h>

typedef unsigned long long ull;

// ---------------- packed f32x2 helpers ------------------------------------------
__device__ __forceinline__ ull fma2(ull a, ull b, ull c) {
  ull d;
  asm("fma.rn.f32x2 %0, %1, %2, %3;" : "=l"(d) : "l"(a), "l"(b), "l"(c));
  return d;
}
__device__ __forceinline__ ull pk2(float x, float y) {
  ull r;
  asm("mov.b64 %0, {%1, %2};" : "=l"(r) : "f"(x), "f"(y));
  return r;
}
__device__ __forceinline__ float2 up2(ull a) {
  float2 f;
  asm("mov.b64 {%0, %1}, %2;" : "=f"(f.x), "=f"(f.y) : "l"(a));
  return f;
}

// ---------------- tf32 helpers ----------------------------------------------------
__device__ __forceinline__ unsigned tf32r(float v) {
  unsigned r;
  asm("cvt.rna.tf32.f32 %0, %1;" : "=r"(r) : "f"(v));
  return r;
}
__device__ __forceinline__ void mma_tf32(float& c0, float& c1, float& c2, float& c3,
                                         unsigned a0, unsigned a1, unsigned a2, unsigned a3,
                                         unsigned b0, unsigned b1) {
  asm volatile(
      "mma.sync.aligned.m16n8k8.row.col.f32.tf32.tf32.f32 "
      "{%0,%1,%2,%3},{%4,%5,%6,%7},{%8,%9},{%0,%1,%2,%3};"
      : "+f"(c0), "+f"(c1), "+f"(c2), "+f"(c3)
      : "r"(a0), "r"(a1), "r"(a2), "r"(a3), "r"(b0), "r"(b1));
}

// ---------------- static device scratch ------------------------------------------
__device__ float g_pos[64 * 64];
__device__ float g_q[3 * 1024 * 4 * 64 * 16];
__device__ float g_k[3 * 1024 * 4 * 64 * 16];
__device__ float g_v[3 * 1024 * 4 * 64 * 16];
__device__ float g_gin[3 * 1024 * 64 * 192];
__device__ float g_y[3 * 1024 * 64 * 64];
__device__ float g_xres[192 * 65536];
__device__ float g_hb[768 * 65536];
__device__ float g_gb[384 * 65536];
__device__ float g_wt192[192 * 192];
// packed tf32 weight fragments: [ntile][kiter][lane] -> (b0 | b1<<32)
__device__ ull g_wp_in[96 * 24 * 32];     // ff_in  (K=192, N=768)
__device__ ull g_wp_out[24 * 48 * 32];    // ff_out (K=384, N=192)
__device__ ull g_wp11[3 * 8 * 24 * 32];   // me_w11 (K=192, N=64) per exposure
__device__ ull g_wp12[3 * 8 * 24 * 32];   // me_w12
__device__ ull g_wp2[3 * 8 * 8 * 32];     // me_w2  (K=64,  N=64)

// ---------------- K0a: sine positional encoding ----------------------------------
__global__ void kpos() {
  int n = threadIdx.x;
  int i = n >> 3, j = n & 7;
  double scale = 6.283185307179586476925286766559;
  double yv = (double)(i + 1) / (8.0 + 1e-6) * scale;
  double xv = (double)(j + 1) / (8.0 + 1e-6) * scale;
  for (int c = 0; c < 64; c++) {
    double base = (c < 32) ? yv : xv;
    int k = (c < 32) ? c : (c - 32);
    double dt = pow(10000.0, (double)(k >> 1) / 16.0);
    double v = base / dt;
    g_pos[n * 64 + c] = (float)(((k & 1) == 0) ? sin(v) : cos(v));
  }
}

// ---------------- K0b: weight transpose (c11) + tf32 fragment packing ------------
__global__ void kpack(const float* __restrict__ c11, const float* __restrict__ ffin,
                      const float* __restrict__ ffout, const float* __restrict__ w11,
                      const float* __restrict__ w12, const float* __restrict__ w2) {
  int idx = blockIdx.x * 256 + threadIdx.x;
  if (idx < 192 * 192) {
    int r = idx / 192, c = idx - r * 192;
    g_wt192[c * 192 + r] = c11[idx];
  }
  // ff_in: source [o=768][k=192]; 96 ntiles, 24 kiters
  if (idx < 96 * 24 * 32) {
    int lane = idx & 31, kit = (idx >> 5) % 24, nt = idx / (32 * 24);
    int o = nt * 8 + (lane >> 2), k = kit * 8 + (lane & 3);
    unsigned lo = tf32r(ffin[o * 192 + k]);
    unsigned hi = tf32r(ffin[o * 192 + k + 4]);
    g_wp_in[idx] = (ull)lo | ((ull)hi << 32);
  }
  // ff_out: source [o=192][k=384]; 24 ntiles, 48 kiters
  if (idx < 24 * 48 * 32) {
    int lane = idx & 31, kit = (idx >> 5) % 48, nt = idx / (32 * 48);
    int o = nt * 8 + (lane >> 2), k = kit * 8 + (lane & 3);
    unsigned lo = tf32r(ffout[o * 384 + k]);
    unsigned hi = tf32r(ffout[o * 384 + k + 4]);
    g_wp_out[idx] = (ull)lo | ((ull)hi << 32);
  }
  // me_w11 / me_w12: source [e][k=192][f=64]; per e: 8 ntiles, 24 kiters
  if (idx < 3 * 8 * 24 * 32) {
    int e = idx / 6144, r = idx % 6144;
    int lane = r & 31, kit = (r >> 5) % 24, nt = r / (32 * 24);
    int f = nt * 8 + (lane >> 2), k = kit * 8 + (lane & 3);
    const float* Wa = w11 + e * 12288;
    const float* Wb = w12 + e * 12288;
    g_wp11[idx] = (ull)tf32r(Wa[k * 64 + f]) | ((ull)tf32r(Wa[(k + 4) * 64 + f]) << 32);
    g_wp12[idx] = (ull)tf32r(Wb[k * 64 + f]) | ((ull)tf32r(Wb[(k + 4) * 64 + f]) << 32);
  }
  // me_w2: source [e][k=64][f=64]; per e: 8 ntiles, 8 kiters
  if (idx < 3 * 8 * 8 * 32) {
    int e = idx / 2048, r = idx % 2048;
    int lane = r & 31, kit = (r >> 5) % 8, nt = r / (32 * 8);
    int f = nt * 8 + (lane >> 2), k = kit * 8 + (lane & 3);
    const float* Wa = w2 + e * 4096;
    g_wp2[idx] = (ull)tf32r(Wa[k * 64 + f]) | ((ull)tf32r(Wa[(k + 4) * 64 + f]) << 32);
  }
}

// ---------------- K1: shift+window + LN1 + pos + QKV GEMM (scalar packed) --------
__global__ void k1_qkv(const float* __restrict__ x, const float* __restrict__ ln1w,
                       const float* __restrict__ ln1b, const float* __restrict__ wqkv) {
  extern __shared__ float sm1[];
  float* sx = sm1;               // [n][c] stride 65
  float* snT = sm1 + 4160;       // [c][n] stride 66
  float* sout = sm1 + 8384;      // [jc][n] stride 65
  int blk = blockIdx.x;
  int e = blk >> 10, wwin = blk & 1023;
  int wh = wwin >> 5, ww = wwin & 31;
  int t = threadIdx.x;
  for (int idx = t; idx < 4096; idx += 256) {
    int c = idx >> 6, n = idx & 63;
    int i = n >> 3, j = n & 7;
    int h0 = (wh * 8 + i + 4) & 255;
    int w0 = (ww * 8 + j + 4) & 255;
    sx[n * 65 + c] = x[((e * 64 + c) * 256 + h0) * 256 + w0];
  }
  __syncthreads();
  if (t < 64) {
    int n = t;
    float m = 0.f;
#pragma unroll
    for (int c = 0; c < 64; c++) m += sx[n * 65 + c];
    m *= (1.f / 64.f);
    float v = 0.f;
#pragma unroll
    for (int c = 0; c < 64; c++) { float d = sx[n * 65 + c] - m; v += d * d; }
    v *= (1.f / 64.f);
    float rs = rsqrtf(v + 1e-5f);
    for (int c = 0; c < 64; c++)
      snT[c * 66 + n] = (sx[n * 65 + c] - m) * rs * ln1w[c] + ln1b[c] + g_pos[n * 64 + c];
  }
  __syncthreads();
  int wa = t >> 5, lane = t & 31, n0 = lane * 2;
  for (int pass = 0; pass < 3; pass++) {
    int jc0 = pass * 64 + wa * 8;
    ull acc[4][2];
#pragma unroll
    for (int a = 0; a < 4; a++) { acc[a][0] = 0ULL; acc[a][1] = 0ULL; }
#pragma unroll 4
    for (int c = 0; c < 64; c++) {
      ulonglong2 wA = *(const ulonglong2*)(wqkv + c * 192 + jc0);
      ulonglong2 wB = *(const ulonglong2*)(wqkv + c * 192 + jc0 + 4);
      float2 xv = *(const float2*)&snT[c * 66 + n0];
      ull x0 = pk2(xv.x, xv.x), x1 = pk2(xv.y, xv.y);
      acc[0][0] = fma2(x0, wA.x, acc[0][0]); acc[0][1] = fma2(x1, wA.x, acc[0][1]);
      acc[1][0] = fma2(x0, wA.y, acc[1][0]); acc[1][1] = fma2(x1, wA.y, acc[1][1]);
      acc[2][0] = fma2(x0, wB.x, acc[2][0]); acc[2][1] = fma2(x1, wB.x, acc[2][1]);
      acc[3][0] = fma2(x0, wB.y, acc[3][0]); acc[3][1] = fma2(x1, wB.y, acc[3][1]);
    }
#pragma unroll
    for (int a = 0; a < 4; a++) {
#pragma unroll
      for (int ni = 0; ni < 2; ni++) {
        float2 f = up2(acc[a][ni]);
        sout[(jc0 + a * 2) * 65 + n0 + ni] = f.x;
        sout[(jc0 + a * 2 + 1) * 65 + n0 + ni] = f.y;
      }
    }
  }
  __syncthreads();
  long wb = (long)(e * 1024 + wwin);
  for (int idx = t; idx < 12288; idx += 256) {
    int ch = idx & 15, n = (idx >> 4) & 63, hh = (idx >> 10) & 3, p = idx >> 12;
    int jc = p * 64 + ch * 4 + hh;
    float vv = sout[jc * 65 + n];
    long qi = (wb * 4 + hh) * 1024 + n * 16 + ch;
    if (p == 0) g_q[qi] = vv;
    else if (p == 1) g_k[qi] = vv;
    else g_v[qi] = vv;
  }
  for (int idx = t; idx < 4096; idx += 256) {
    int c2 = idx & 63, n = idx >> 6;
    int hh = c2 >> 4, ch = c2 & 15;
    g_gin[(wb * 64 + n) * 192 + 128 + c2] = sout[(ch * 4 + hh) * 65 + n];
  }
}

// ---------------- K2: 6 cross-exposure attentions (single-pass, packed) ----------
__global__ void k2_attn() {
  extern __shared__ float sm2[];
  float* sk = sm2;
  float* sv = sm2 + 4096;
  const int e_of[6]  = {0, 0, 1, 1, 2, 2};
  const int kv_of[6] = {1, 2, 0, 2, 1, 0};
  const int sl_of[6] = {0, 1, 0, 1, 0, 1};
  int w = blockIdx.x, z = blockIdx.y;
  int e = e_of[z], ekv = kv_of[z], sl = sl_of[z];
  int t = threadIdx.x;
  int hh = t >> 5, lane = t & 31;
  long kb = (long)(ekv * 1024 + w) * 4096;
  for (int idx = t; idx < 1024; idx += 128) {
    *(float4*)&sk[idx * 4] = *(const float4*)&g_k[kb + idx * 4];
    *(float4*)&sv[idx * 4] = *(const float4*)&g_v[kb + idx * 4];
  }
  long qbase = (long)(e * 1024 + w) * 4096 + hh * 1024;
  ull qa[8], qb[8];
  {
    const ulonglong2* qg = (const ulonglong2*)(g_q + qbase + lane * 16);
    ulonglong2 a0 = qg[0], a1 = qg[1], a2 = qg[2], a3 = qg[3];
    qa[0] = a0.x; qa[1] = a0.y; qa[2] = a1.x; qa[3] = a1.y;
    qa[4] = a2.x; qa[5] = a2.y; qa[6] = a3.x; qa[7] = a3.y;
    const ulonglong2* qh = (const ulonglong2*)(g_q + qbase + (lane + 32) * 16);
    ulonglong2 b0 = qh[0], b1 = qh[1], b2 = qh[2], b3 = qh[3];
    qb[0] = b0.x; qb[1] = b0.y; qb[2] = b1.x; qb[3] = b1.y;
    qb[4] = b2.x; qb[5] = b2.y; qb[6] = b3.x; qb[7] = b3.y;
  }
  __syncthreads();
  int wh = w >> 5, ww = w & 31;
  int na = lane, nb = lane + 32;
  ull mA = 0ULL, mB = 0ULL;
  if (wh == 31) {
    mA |= ((na >> 3) < 4) ? 0xFFFFFFFF00000000ULL : 0x00000000FFFFFFFFULL;
    mB |= ((nb >> 3) < 4) ? 0xFFFFFFFF00000000ULL : 0x00000000FFFFFFFFULL;
  }
  if (ww == 31) {
    mA |= ((na & 7) < 4) ? 0xF0F0F0F0F0F0F0F0ULL : 0x0F0F0F0F0F0F0F0FULL;
    mB |= ((nb & 7) < 4) ? 0xF0F0F0F0F0F0F0F0ULL : 0x0F0F0F0F0F0F0F0FULL;
  }
  float suma = 0.f, sumb = 0.f;
  ull acca[8], accb[8];
#pragma unroll
  for (int c = 0; c < 8; c++) { acca[c] = 0ULL; accb[c] = 0ULL; }
  const ulonglong2* skp2 = (const ulonglong2*)(sk + hh * 1024);
  const ulonglong2* svp2 = (const ulonglong2*)(sv + hh * 1024);
#pragma unroll 4
  for (int m = 0; m < 64; m++) {
    ulonglong2 k0 = skp2[m * 4], k1 = skp2[m * 4 + 1];
    ulonglong2 k2 = skp2[m * 4 + 2], k3 = skp2[m * 4 + 3];
    ull da = 0ULL, db = 0ULL;
    da = fma2(qa[0], k0.x, da); db = fma2(qb[0], k0.x, db);
    da = fma2(qa[1], k0.y, da); db = fma2(qb[1], k0.y, db);
    da = fma2(qa[2], k1.x, da); db = fma2(qb[2], k1.x, db);
    da = fma2(qa[3], k1.y, da); db = fma2(qb[3], k1.y, db);
    da = fma2(qa[4], k2.x, da); db = fma2(qb[4], k2.x, db);
    da = fma2(qa[5], k2.y, da); db = fma2(qb[5], k2.y, db);
    da = fma2(qa[6], k3.x, da); db = fma2(qb[6], k3.x, db);
    da = fma2(qa[7], k3.y, da); db = fma2(qb[7], k3.y, db);
    float2 fa = up2(da), fb = up2(db);
    float sa = (fa.x + fa.y) * 0.125f;
    float sb = (fb.x + fb.y) * 0.125f;
    if ((mA >> m) & 1) sa -= 100.f;
    if ((mB >> m) & 1) sb -= 100.f;
    float p = __expf(sa), pq = __expf(sb);
    suma += p; sumb += pq;
    ull ppa = pk2(p, p), ppb = pk2(pq, pq);
    ulonglong2 v0 = svp2[m * 4], v1 = svp2[m * 4 + 1];
    ulonglong2 v2 = svp2[m * 4 + 2], v3 = svp2[m * 4 + 3];
    acca[0] = fma2(ppa, v0.x, acca[0]); accb[0] = fma2(ppb, v0.x, accb[0]);
    acca[1] = fma2(ppa, v0.y, acca[1]); accb[1] = fma2(ppb, v0.y, accb[1]);
    acca[2] = fma2(ppa, v1.x, acca[2]); accb[2] = fma2(ppb, v1.x, accb[2]);
    acca[3] = fma2(ppa, v1.y, acca[3]); accb[3] = fma2(ppb, v1.y, accb[3]);
    acca[4] = fma2(ppa, v2.x, acca[4]); accb[4] = fma2(ppb, v2.x, accb[4]);
    acca[5] = fma2(ppa, v2.y, acca[5]); accb[5] = fma2(ppb, v2.y, accb[5]);
    acca[6] = fma2(ppa, v3.x, acca[6]); accb[6] = fma2(ppb, v3.x, accb[6]);
    acca[7] = fma2(ppa, v3.y, acca[7]); accb[7] = fma2(ppb, v3.y, accb[7]);
  }
  float inva = 1.f / suma, invb = 1.f / sumb;
  long gba = ((long)(e * 1024 + w) * 64 + na) * 192 + sl * 64 + hh * 16;
  long gbb = ((long)(e * 1024 + w) * 64 + nb) * 192 + sl * 64 + hh * 16;
#pragma unroll
  for (int c4 = 0; c4 < 4; c4++) {
    float2 u0 = up2(acca[c4 * 2]);
    float2 u1 = up2(acca[c4 * 2 + 1]);
    *(float4*)&g_gin[gba + c4 * 4] = make_float4(u0.x * inva, u0.y * inva, u1.x * inva, u1.y * inva);
    float2 w0 = up2(accb[c4 * 2]);
    float2 w1 = up2(accb[c4 * 2 + 1]);
    *(float4*)&g_gin[gbb + c4 * 4] = make_float4(w0.x * invb, w0.y * invb, w1.x * invb, w1.y * invb);
  }
}

// ---------------- K3: per-exposure GEGLU via tf32 MMA ----------------------------
// block = (e, window). dyn smem: sgin[64*196] (tf32 bits). static: st[64*68].
__global__ void k3_geglu(const float* __restrict__ b11, const float* __restrict__ b12,
                         const float* __restrict__ b2) {
  extern __shared__ float sgin_f[];
  unsigned* sgin = (unsigned*)sgin_f;
  __shared__ float st[64 * 68];
  unsigned* stu = (unsigned*)st;
  int blk = blockIdx.x;
  int e = blk >> 10;
  int t = threadIdx.x;
  long gbase = (long)blk * 12288;
  for (int idx = t; idx < 12288; idx += 256) {
    int nn = idx / 192, c = idx - nn * 192;
    sgin[nn * 196 + c] = tf32r(g_gin[gbase + idx]);
  }
  __syncthreads();
  int wa = t >> 5, lane = t & 31;
  int mt = wa & 3, nh = wa >> 2;
  int arow = mt * 16 + (lane >> 2);
  int acol = lane & 3;
  int ccol0 = 2 * (lane & 3);
  // GEMM1: gin(64x192) @ w11 and @ w12 -> a, g (64x64 each)
  float a1[4][4], g1[4][4];
#pragma unroll
  for (int j = 0; j < 4; j++) {
    int o = (nh * 4 + j) * 8 + ccol0;
    float ba0 = b11[e * 64 + o], ba1 = b11[e * 64 + o + 1];
    float bg0 = b12[e * 64 + o], bg1 = b12[e * 64 + o + 1];
    a1[j][0] = ba0; a1[j][1] = ba1; a1[j][2] = ba0; a1[j][3] = ba1;
    g1[j][0] = bg0; g1[j][1] = bg1; g1[j][2] = bg0; g1[j][3] = bg1;
  }
  const ull* W11 = g_wp11 + e * 6144;
  const ull* W12 = g_wp12 + e * 6144;
  for (int kit = 0; kit < 24; kit++) {
    int kc = kit * 8 + acol;
    unsigned A0 = sgin[arow * 196 + kc];
    unsigned A1 = sgin[(arow + 8) * 196 + kc];
    unsigned A2 = sgin[arow * 196 + kc + 4];
    unsigned A3 = sgin[(arow + 8) * 196 + kc + 4];
#pragma unroll
    for (int j = 0; j < 4; j++) {
      int ntile = nh * 4 + j;
      ull wv = W11[(ntile * 24 + kit) * 32 + lane];
      mma_tf32(a1[j][0], a1[j][1], a1[j][2], a1[j][3], A0, A1, A2, A3,
               (unsigned)wv, (unsigned)(wv >> 32));
      ull wv2 = W12[(ntile * 24 + kit) * 32 + lane];
      mma_tf32(g1[j][0], g1[j][1], g1[j][2], g1[j][3], A0, A1, A2, A3,
               (unsigned)wv2, (unsigned)(wv2 >> 32));
    }
  }
  // gelu(a)*g -> st (tf32 bits), layout [token n][feature f] stride 68
#pragma unroll
  for (int j = 0; j < 4; j++) {
    int fb = (nh * 4 + j) * 8 + ccol0;
    int r0 = mt * 16 + (lane >> 2);
#pragma unroll
    for (int rr = 0; rr < 2; rr++) {
      int row = r0 + rr * 8;
      float av0 = a1[j][rr * 2], av1 = a1[j][rr * 2 + 1];
      float gv0 = g1[j][rr * 2], gv1 = g1[j][rr * 2 + 1];
      float t0 = 0.5f * av0 * (1.f + erff(av0 * 0.70710678118654752f)) * gv0;
      float t1 = 0.5f * av1 * (1.f + erff(av1 * 0.70710678118654752f)) * gv1;
      stu[row * 68 + fb] = tf32r(t0);
      stu[row * 68 + fb + 1] = tf32r(t1);
    }
  }
  __syncthreads();
  // GEMM2: t(64x64) @ w2 -> y (64x64)
  float y2[4][4];
#pragma unroll
  for (int j = 0; j < 4; j++) {
    int o = (nh * 4 + j) * 8 + ccol0;
    float b0 = b2[e * 64 + o], b1v = b2[e * 64 + o + 1];
    y2[j][0] = b0; y2[j][1] = b1v; y2[j][2] = b0; y2[j][3] = b1v;
  }
  const ull* W2 = g_wp2 + e * 2048;
  for (int kit = 0; kit < 8; kit++) {
    int kc = kit * 8 + acol;
    unsigned A0 = stu[arow * 68 + kc];
    unsigned A1 = stu[(arow + 8) * 68 + kc];
    unsigned A2 = stu[arow * 68 + kc + 4];
    unsigned A3 = stu[(arow + 8) * 68 + kc + 4];
#pragma unroll
    for (int j = 0; j < 4; j++) {
      int ntile = nh * 4 + j;
      ull wv = W2[(ntile * 8 + kit) * 32 + lane];
      mma_tf32(y2[j][0], y2[j][1], y2[j][2], y2[j][3], A0, A1, A2, A3,
               (unsigned)wv, (unsigned)(wv >> 32));
    }
  }
  __syncthreads();
  // stage y to st (as plain f32) then coalesced store
#pragma unroll
  for (int j = 0; j < 4; j++) {
    int fb = (nh * 4 + j) * 8 + ccol0;
    int r0 = mt * 16 + (lane >> 2);
#pragma unroll
    for (int rr = 0; rr < 2; rr++) {
      int row = r0 + rr * 8;
      st[row * 68 + fb] = y2[j][rr * 2];
      st[row * 68 + fb + 1] = y2[j][rr * 2 + 1];
    }
  }
  __syncthreads();
  long ybase = (long)blk * 4096;
  for (int idx = t; idx < 4096; idx += 256) {
    int nn = idx >> 6, f = idx & 63;
    g_y[ybase + idx] = st[nn * 68 + f];
  }
}

// ---------------- K4: window reverse + conv1x1 + roll +4 + residual (scalar) -----
__global__ void k4_conv11(const float* __restrict__ x) {
  extern __shared__ float s2m[];
  int wwin = blockIdx.x;
  int wh = wwin >> 5, ww = wwin & 31;
  int t = threadIdx.x;
  for (int idx = t; idx < 12288; idx += 256) {
    int e = idx >> 12;
    int r = idx & 4095;
    int nn = r >> 6, f = r & 63;
    s2m[(e * 64 + f) * 66 + nn] = g_y[(long)(e * 1024 + wwin) * 4096 + r];
  }
  __syncthreads();
  int wa = t >> 5, lane = t & 31, n0 = lane * 2;
  for (int pass = 0; pass < 3; pass++) {
    int oc0 = pass * 64 + wa * 8;
    ull acc[4][2];
#pragma unroll
    for (int k = 0; k < 4; k++) { acc[k][0] = 0ULL; acc[k][1] = 0ULL; }
#pragma unroll 4
    for (int c = 0; c < 192; c++) {
      ulonglong2 wA = *(const ulonglong2*)(g_wt192 + c * 192 + oc0);
      ulonglong2 wB = *(const ulonglong2*)(g_wt192 + c * 192 + oc0 + 4);
      float2 xv = *(const float2*)&s2m[c * 66 + n0];
      ull x0 = pk2(xv.x, xv.x), x1 = pk2(xv.y, xv.y);
      acc[0][0] = fma2(x0, wA.x, acc[0][0]); acc[0][1] = fma2(x1, wA.x, acc[0][1]);
      acc[1][0] = fma2(x0, wA.y, acc[1][0]); acc[1][1] = fma2(x1, wA.y, acc[1][1]);
      acc[2][0] = fma2(x0, wB.x, acc[2][0]); acc[2][1] = fma2(x1, wB.x, acc[2][1]);
      acc[3][0] = fma2(x0, wB.y, acc[3][0]); acc[3][1] = fma2(x1, wB.y, acc[3][1]);
    }
#pragma unroll
    for (int ni = 0; ni < 2; ni++) {
      int nn = n0 + ni;
      int i = nn >> 3, j = nn & 7;
      int hp = (wh * 8 + i + 4) & 255;
      int wp = (ww * 8 + j + 4) & 255;
      int pixel = hp * 256 + wp;
#pragma unroll
      for (int k = 0; k < 4; k++) {
        float2 u = up2(acc[k][ni]);
        int gi0 = (oc0 + k * 2) * 65536 + pixel;
        int gi1 = (oc0 + k * 2 + 1) * 65536 + pixel;
        g_xres[gi0] = u.x + x[gi0];
        g_xres[gi1] = u.y + x[gi1];
      }
    }
  }
}

// ---------------- K5: LN2 + ff_in (192->768) via tf32 MMA ------------------------
// block = 64 pixels. dyn smem: sxn[64*196]. static: sfl[2][64*66].
__global__ void k5_ln_ffin(const float* __restrict__ ln2w, const float* __restrict__ ln2b) {
  extern __shared__ float sxn[];
  unsigned* sxnu = (unsigned*)sxn;
  __shared__ float red[256], red2[256], smean[64], srstd[64];
  __shared__ float sfl[2][64 * 66];
  int blk = blockIdx.x;
  int h = blk >> 2;
  int w0 = (blk & 3) * 64;
  int pix0 = h * 256 + w0;
  int t = threadIdx.x;
  for (int idx = t; idx < 12288; idx += 256) {
    int c = idx >> 6, p = idx & 63;
    sxn[p * 196 + c] = g_xres[c * 65536 + pix0 + p];
  }
  __syncthreads();
  {
    int p = t & 63, g = t >> 6;
    float s = 0.f, s2v = 0.f;
    for (int c = g; c < 192; c += 4) { float v = sxn[p * 196 + c]; s += v; s2v += v * v; }
    red[t] = s;
    red2[t] = s2v;
  }
  __syncthreads();
  if (t < 64) {
    float s = red[t] + red[64 + t] + red[128 + t] + red[192 + t];
    float s2v = red2[t] + red2[64 + t] + red2[128 + t] + red2[192 + t];
    float m = s * (1.f / 192.f);
    float var = s2v * (1.f / 192.f) - m * m;
    smean[t] = m;
    srstd[t] = rsqrtf(var + 1e-5f);
  }
  __syncthreads();
  for (int idx = t; idx < 12288; idx += 256) {
    int c = idx >> 6, p = idx & 63;
    float v = (sxn[p * 196 + c] - smean[p]) * srstd[p] * ln2w[c] + ln2b[c];
    sxnu[p * 196 + c] = tf32r(v);
  }
  __syncthreads();
  int wa = t >> 5, lane = t & 31;
  int mt = wa & 3, nh = wa >> 2;
  int arow = mt * 16 + (lane >> 2);
  int acol = lane & 3;
  int ccol0 = 2 * (lane & 3);
  for (int ch = 0; ch < 6; ch++) {
    float acc[8][4];
#pragma unroll
    for (int j = 0; j < 8; j++)
#pragma unroll
      for (int r = 0; r < 4; r++) acc[j][r] = 0.f;
    for (int kit = 0; kit < 24; kit++) {
      int kc = kit * 8 + acol;
      unsigned A0 = sxnu[arow * 196 + kc];
      unsigned A1 = sxnu[(arow + 8) * 196 + kc];
      unsigned A2 = sxnu[arow * 196 + kc + 4];
      unsigned A3 = sxnu[(arow + 8) * 196 + kc + 4];
#pragma unroll
      for (int j = 0; j < 8; j++) {
        int ntile = nh * 48 + ch * 8 + j;
        ull wv = g_wp_in[(ntile * 24 + kit) * 32 + lane];
        mma_tf32(acc[j][0], acc[j][1], acc[j][2], acc[j][3], A0, A1, A2, A3,
                 (unsigned)wv, (unsigned)(wv >> 32));
      }
    }
#pragma unroll
    for (int j = 0; j < 8; j++) {
      int ol = j * 8 + ccol0;
      int r0 = mt * 16 + (lane >> 2);
      sfl[nh][ol * 66 + r0] = acc[j][0];
      sfl[nh][(ol + 1) * 66 + r0] = acc[j][1];
      sfl[nh][ol * 66 + r0 + 8] = acc[j][2];
      sfl[nh][(ol + 1) * 66 + r0 + 8] = acc[j][3];
    }
    __syncthreads();
    for (int idx = t; idx < 8192; idx += 256) {
      int g = idx >> 12, ol = (idx >> 6) & 63, p = idx & 63;
      int o = g * 384 + ch * 64 + ol;
      g_hb[o * 65536 + pix0 + p] = sfl[g][ol * 66 + p];
    }
    __syncthreads();
  }
}

// ---------------- K6: depthwise 3x3 + gelu(g1)*g2, 4 rows/block ------------------
__global__ void k6_dw(const float* __restrict__ dw) {
  __shared__ float s0[6][258];
  __shared__ float s1[6][258];
  int h0 = blockIdx.x * 4;
  int c = blockIdx.y;
  int t = threadIdx.x;
  const float* p0 = g_hb + c * 65536;
  const float* p1 = g_hb + (c + 384) * 65536;
  for (int idx = t; idx < 6 * 258; idx += 256) {
    int r = idx / 258, cc = idx - r * 258;
    int hh = h0 - 1 + r, wp = cc - 1;
    float v0 = 0.f, v1 = 0.f;
    if (hh >= 0 && hh < 256 && wp >= 0 && wp < 256) {
      v0 = p0[hh * 256 + wp];
      v1 = p1[hh * 256 + wp];
    }
    s0[r][cc] = v0;
    s1[r][cc] = v1;
  }
  float f0r[9], f1r[9];
#pragma unroll
  for (int k = 0; k < 9; k++) { f0r[k] = dw[c * 9 + k]; f1r[k] = dw[(c + 384) * 9 + k]; }
  __syncthreads();
  int w = t;
#pragma unroll
  for (int r = 0; r < 4; r++) {
    float a = 0.f, b = 0.f;
#pragma unroll
    for (int dh = 0; dh < 3; dh++) {
#pragma unroll
      for (int dwi = 0; dwi < 3; dwi++) {
        a += s0[r + dh][w + dwi] * f0r[dh * 3 + dwi];
        b += s1[r + dh][w + dwi] * f1r[dh * 3 + dwi];
      }
    }
    float ge = 0.5f * a * (1.f + erff(a * 0.70710678118654752f));
    g_gb[c * 65536 + (h0 + r) * 256 + w] = ge * b;
  }
}

// ---------------- K7: ff_out (384->192) + residual via tf32 MMA ------------------
// block = 32 pixels. dyn smem: sxn[32*388]. static: sfl[4][16*34].
__global__ void k7_ffout(float* __restrict__ out) {
  extern __shared__ float sA_f[];
  unsigned* sA = (unsigned*)sA_f;
  __shared__ float sfl[4][16 * 34];
  int blk = blockIdx.x;
  int h = blk >> 3;
  int w0 = (blk & 7) * 32;
  int pix0 = h * 256 + w0;
  int t = threadIdx.x;
  for (int idx = t; idx < 12288; idx += 256) {
    int c = idx >> 5, p = idx & 31;
    sA[p * 388 + c] = tf32r(g_gb[c * 65536 + pix0 + p]);
  }
  __syncthreads();
  int wa = t >> 5, lane = t & 31;
  int mt = wa & 1, nq = wa >> 1;
  int arow = mt * 16 + (lane >> 2);
  int acol = lane & 3;
  int ccol0 = 2 * (lane & 3);
  float acc[6][4];
#pragma unroll
  for (int j = 0; j < 6; j++)
#pragma unroll
    for (int r = 0; r < 4; r++) acc[j][r] = 0.f;
  for (int kit = 0; kit < 48; kit++) {
    int kc = kit * 8 + acol;
    unsigned A0 = sA[arow * 388 + kc];
    unsigned A1 = sA[(arow + 8) * 388 + kc];
    unsigned A2 = sA[arow * 388 + kc + 4];
    unsigned A3 = sA[(arow + 8) * 388 + kc + 4];
#pragma unroll
    for (int j = 0; j < 6; j++) {
      int ntile = nq * 6 + j;
      ull wv = g_wp_out[(ntile * 48 + kit) * 32 + lane];
      mma_tf32(acc[j][0], acc[j][1], acc[j][2], acc[j][3], A0, A1, A2, A3,
               (unsigned)wv, (unsigned)(wv >> 32));
    }
  }
  for (int v = 0; v < 3; v++) {
#pragma unroll
    for (int jj = 0; jj < 2; jj++) {
      int j = v * 2 + jj;
      int ol = jj * 8 + ccol0;
      int r0 = mt * 16 + (lane >> 2);
      sfl[nq][ol * 34 + r0] = acc[j][0];
      sfl[nq][(ol + 1) * 34 + r0] = acc[j][1];
      sfl[nq][ol * 34 + r0 + 8] = acc[j][2];
      sfl[nq][(ol + 1) * 34 + r0 + 8] = acc[j][3];
    }
    __syncthreads();
    for (int idx = t; idx < 2048; idx += 256) {
      int g = idx >> 9, ol = (idx >> 5) & 15, p = idx & 31;
      int o = g * 48 + v * 16 + ol;
      int gi = o * 65536 + pix0 + p;
      out[gi] = g_xres[gi] + sfl[g][ol * 34 + p];
    }
    __syncthreads();
  }
}

// ---------------- host launcher --------------------------------------------------
extern "C" void kernel_launch(void* const* d_in, const int* in_sizes, int n_in,
                              void* d_out, int out_size) {
  const float* x    = (const float*)d_in[0];
  const float* ln1w = (const float*)d_in[1];
  const float* ln1b = (const float*)d_in[2];
  const float* ln2w = (const float*)d_in[3];
  const float* ln2b = (const float*)d_in[4];
  const float* wqkv = (const float*)d_in[5];
  const float* w11  = (const float*)d_in[6];
  const float* b11  = (const float*)d_in[7];
  const float* w12  = (const float*)d_in[8];
  const float* b12  = (const float*)d_in[9];
  const float* w2   = (const float*)d_in[10];
  const float* b2   = (const float*)d_in[11];
  const float* c11  = (const float*)d_in[12];
  const float* ffin = (const float*)d_in[13];
  const float* ffdw = (const float*)d_in[14];
  const float* ffou = (const float*)d_in[15];
  float* out = (float*)d_out;

  const int smem1 = (4160 + 4224 + 192 * 65) * 4;   // 83456
  const int smem2 = 8192 * 4;                       // 32768
  const int smem3 = (64 * 196) * 4;                 // 50176
  const int smem4 = (192 * 66) * 4;                 // 50688
  const int smem5 = (64 * 196) * 4;                 // 50176
  const int smem7 = (32 * 388) * 4;                 // 49664
  cudaFuncSetAttribute(k1_qkv, cudaFuncAttributeMaxDynamicSharedMemorySize, smem1);
  cudaFuncSetAttribute(k2_attn, cudaFuncAttributeMaxDynamicSharedMemorySize, smem2);
  cudaFuncSetAttribute(k3_geglu, cudaFuncAttributeMaxDynamicSharedMemorySize, smem3);
  cudaFuncSetAttribute(k4_conv11, cudaFuncAttributeMaxDynamicSharedMemorySize, smem4);
  cudaFuncSetAttribute(k5_ln_ffin, cudaFuncAttributeMaxDynamicSharedMemorySize, smem5);
  cudaFuncSetAttribute(k7_ffout, cudaFuncAttributeMaxDynamicSharedMemorySize, smem7);

  kpos<<<1, 64>>>();
  kpack<<<288, 256>>>(c11, ffin, ffou, w11, w12, w2);
  k1_qkv<<<3072, 256, smem1>>>(x, ln1w, ln1b, wqkv);
  {
    dim3 g2(1024, 6);
    k2_attn<<<g2, 128, smem2>>>();
  }
  k3_geglu<<<3072, 256, smem3>>>(b11, b12, b2);
  k4_conv11<<<1024, 256, smem4>>>(x);
  k5_ln_ffin<<<1024, 256, smem5>>>(ln2w, ln2b);
  {
    dim3 g6(64, 384);
    k6_dw<<<g6, 256>>>(ffdw);
  }
  k7_ffout<<<2048, 256, smem7>>>(out);
}

// round 5
// speedup vs baseline: 3.1948x; 1.0757x over previous
#include <cuda_runtime.h>
#include <math.h>

typedef unsigned long long ull;

// ---------------- packed f32x2 helpers ------------------------------------------
__device__ __forceinline__ ull fma2(ull a, ull b, ull c) {
  ull d;
  asm("fma.rn.f32x2 %0, %1, %2, %3;" : "=l"(d) : "l"(a), "l"(b), "l"(c));
  return d;
}
__device__ __forceinline__ ull pk2(float x, float y) {
  ull r;
  asm("mov.b64 %0, {%1, %2};" : "=l"(r) : "f"(x), "f"(y));
  return r;
}
__device__ __forceinline__ float2 up2(ull a) {
  float2 f;
  asm("mov.b64 {%0, %1}, %2;" : "=f"(f.x), "=f"(f.y) : "l"(a));
  return f;
}

// ---------------- tf32 helpers ----------------------------------------------------
__device__ __forceinline__ unsigned tf32r(float v) {
  unsigned r;
  asm("cvt.rna.tf32.f32 %0, %1;" : "=r"(r) : "f"(v));
  return r;
}
__device__ __forceinline__ void mma_tf32(float& c0, float& c1, float& c2, float& c3,
                                         unsigned a0, unsigned a1, unsigned a2, unsigned a3,
                                         unsigned b0, unsigned b1) {
  asm volatile(
      "mma.sync.aligned.m16n8k8.row.col.f32.tf32.tf32.f32 "
      "{%0,%1,%2,%3},{%4,%5,%6,%7},{%8,%9},{%0,%1,%2,%3};"
      : "+f"(c0), "+f"(c1), "+f"(c2), "+f"(c3)
      : "r"(a0), "r"(a1), "r"(a2), "r"(a3), "r"(b0), "r"(b1));
}

// ---------------- static device scratch ------------------------------------------
__device__ float g_pos[64 * 64];
__device__ float g_q[3 * 1024 * 4 * 64 * 16];
__device__ float g_k[3 * 1024 * 4 * 64 * 16];
__device__ float g_v[3 * 1024 * 4 * 64 * 16];
__device__ float g_gin[3 * 1024 * 64 * 192];
__device__ float g_y[3 * 1024 * 64 * 64];
__device__ float g_xres[192 * 65536];
__device__ float g_hb[768 * 65536];
__device__ float g_gb[384 * 65536];
// packed tf32 weight fragments: [ntile][kiter][lane] -> (b0 | b1<<32)
__device__ ull g_wp_in[96 * 24 * 32];     // ff_in  (K=192, N=768)
__device__ ull g_wp_out[24 * 48 * 32];    // ff_out (K=384, N=192)
__device__ ull g_wp11[3 * 8 * 24 * 32];   // me_w11 (K=192, N=64) per exposure
__device__ ull g_wp12[3 * 8 * 24 * 32];   // me_w12
__device__ ull g_wp2[3 * 8 * 8 * 32];     // me_w2  (K=64,  N=64)
__device__ ull g_wpqkv[24 * 8 * 32];      // w_qkv  (K=64,  N=192)
__device__ ull g_wp192[24 * 24 * 32];     // conv11 (K=192, N=192)

// ---------------- K0a: sine positional encoding ----------------------------------
__global__ void kpos() {
  int n = threadIdx.x;
  int i = n >> 3, j = n & 7;
  double scale = 6.283185307179586476925286766559;
  double yv = (double)(i + 1) / (8.0 + 1e-6) * scale;
  double xv = (double)(j + 1) / (8.0 + 1e-6) * scale;
  for (int c = 0; c < 64; c++) {
    double base = (c < 32) ? yv : xv;
    int k = (c < 32) ? c : (c - 32);
    double dt = pow(10000.0, (double)(k >> 1) / 16.0);
    double v = base / dt;
    g_pos[n * 64 + c] = (float)(((k & 1) == 0) ? sin(v) : cos(v));
  }
}

// ---------------- K0b: tf32 fragment packing -------------------------------------
__global__ void kpack(const float* __restrict__ c11, const float* __restrict__ ffin,
                      const float* __restrict__ ffout, const float* __restrict__ w11,
                      const float* __restrict__ w12, const float* __restrict__ w2,
                      const float* __restrict__ wqkv) {
  int idx = blockIdx.x * 256 + threadIdx.x;
  // ff_in: source [o=768][k=192]
  if (idx < 96 * 24 * 32) {
    int lane = idx & 31, kit = (idx >> 5) % 24, nt = idx / (32 * 24);
    int o = nt * 8 + (lane >> 2), k = kit * 8 + (lane & 3);
    g_wp_in[idx] = (ull)tf32r(ffin[o * 192 + k]) | ((ull)tf32r(ffin[o * 192 + k + 4]) << 32);
  }
  // ff_out: source [o=192][k=384]
  if (idx < 24 * 48 * 32) {
    int lane = idx & 31, kit = (idx >> 5) % 48, nt = idx / (32 * 48);
    int o = nt * 8 + (lane >> 2), k = kit * 8 + (lane & 3);
    g_wp_out[idx] = (ull)tf32r(ffout[o * 384 + k]) | ((ull)tf32r(ffout[o * 384 + k + 4]) << 32);
  }
  // me_w11 / me_w12: source [e][k=192][f=64]
  if (idx < 3 * 8 * 24 * 32) {
    int e = idx / 6144, r = idx % 6144;
    int lane = r & 31, kit = (r >> 5) % 24, nt = r / (32 * 24);
    int f = nt * 8 + (lane >> 2), k = kit * 8 + (lane & 3);
    const float* Wa = w11 + e * 12288;
    const float* Wb = w12 + e * 12288;
    g_wp11[idx] = (ull)tf32r(Wa[k * 64 + f]) | ((ull)tf32r(Wa[(k + 4) * 64 + f]) << 32);
    g_wp12[idx] = (ull)tf32r(Wb[k * 64 + f]) | ((ull)tf32r(Wb[(k + 4) * 64 + f]) << 32);
  }
  // me_w2: source [e][k=64][f=64]
  if (idx < 3 * 8 * 8 * 32) {
    int e = idx / 2048, r = idx % 2048;
    int lane = r & 31, kit = (r >> 5) % 8, nt = r / (32 * 8);
    int f = nt * 8 + (lane >> 2), k = kit * 8 + (lane & 3);
    const float* Wa = w2 + e * 4096;
    g_wp2[idx] = (ull)tf32r(Wa[k * 64 + f]) | ((ull)tf32r(Wa[(k + 4) * 64 + f]) << 32);
  }
  // w_qkv: source [k=64][n=192]
  if (idx < 24 * 8 * 32) {
    int lane = idx & 31, kit = (idx >> 5) % 8, nt = idx / (32 * 8);
    int n = nt * 8 + (lane >> 2), k = kit * 8 + (lane & 3);
    g_wpqkv[idx] = (ull)tf32r(wqkv[k * 192 + n]) | ((ull)tf32r(wqkv[(k + 4) * 192 + n]) << 32);
  }
  // conv11: source [o=192][k=192] (already o-major, k contiguous)
  if (idx < 24 * 24 * 32) {
    int lane = idx & 31, kit = (idx >> 5) % 24, nt = idx / (32 * 24);
    int o = nt * 8 + (lane >> 2), k = kit * 8 + (lane & 3);
    g_wp192[idx] = (ull)tf32r(c11[o * 192 + k]) | ((ull)tf32r(c11[o * 192 + k + 4]) << 32);
  }
}

// ---------------- K1: shift+window + LN1 + pos + QKV GEMM via tf32 MMA -----------
// dyn smem (overlapped in time): sx[64*65] @0 | snT-bits[64*68] @4160 | sout[192*65] @0
__global__ void k1_qkv(const float* __restrict__ x, const float* __restrict__ ln1w,
                       const float* __restrict__ ln1b) {
  extern __shared__ float sm1[];
  float* sx = sm1;
  unsigned* snT = (unsigned*)(sm1 + 4160);   // [n][c] stride 68
  float* sout = sm1;                          // [jc][n] stride 65 (written post-MMA)
  __shared__ float smean[64], srstd[64];
  int blk = blockIdx.x;
  int e = blk >> 10, wwin = blk & 1023;
  int wh = wwin >> 5, ww = wwin & 31;
  int t = threadIdx.x;
  for (int idx = t; idx < 4096; idx += 256) {
    int c = idx >> 6, n = idx & 63;
    int i = n >> 3, j = n & 7;
    int h0 = (wh * 8 + i + 4) & 255;
    int w0 = (ww * 8 + j + 4) & 255;
    sx[n * 65 + c] = x[((e * 64 + c) * 256 + h0) * 256 + w0];
  }
  __syncthreads();
  if (t < 64) {
    int n = t;
    float m = 0.f;
#pragma unroll
    for (int c = 0; c < 64; c++) m += sx[n * 65 + c];
    m *= (1.f / 64.f);
    float v = 0.f;
#pragma unroll
    for (int c = 0; c < 64; c++) { float d = sx[n * 65 + c] - m; v += d * d; }
    v *= (1.f / 64.f);
    smean[n] = m;
    srstd[n] = rsqrtf(v + 1e-5f);
  }
  __syncthreads();
  for (int idx = t; idx < 4096; idx += 256) {
    int c = idx & 63, n = idx >> 6;
    float v = (sx[n * 65 + c] - smean[n]) * srstd[n] * ln1w[c] + ln1b[c] + g_pos[n * 64 + c];
    snT[n * 68 + c] = tf32r(v);
  }
  __syncthreads();
  int wa = t >> 5, lane = t & 31;
  int mt = wa & 3, ng = wa >> 2;
  int arow = mt * 16 + (lane >> 2);
  int acol = lane & 3;
  int ccol0 = 2 * (lane & 3);
  float acc[12][4];
#pragma unroll
  for (int j = 0; j < 12; j++)
#pragma unroll
    for (int r = 0; r < 4; r++) acc[j][r] = 0.f;
  for (int kit = 0; kit < 8; kit++) {
    int kc = kit * 8 + acol;
    unsigned A0 = snT[arow * 68 + kc];
    unsigned A1 = snT[(arow + 8) * 68 + kc];
    unsigned A2 = snT[arow * 68 + kc + 4];
    unsigned A3 = snT[(arow + 8) * 68 + kc + 4];
#pragma unroll
    for (int j = 0; j < 12; j++) {
      int nt = ng * 12 + j;
      ull wv = g_wpqkv[(nt * 8 + kit) * 32 + lane];
      mma_tf32(acc[j][0], acc[j][1], acc[j][2], acc[j][3], A0, A1, A2, A3,
               (unsigned)wv, (unsigned)(wv >> 32));
    }
  }
  __syncthreads();   // all MMA reads of snT done before sout overwrites
#pragma unroll
  for (int j = 0; j < 12; j++) {
    int jc = (ng * 12 + j) * 8 + ccol0;
    int r0 = mt * 16 + (lane >> 2);
    sout[jc * 65 + r0] = acc[j][0];
    sout[(jc + 1) * 65 + r0] = acc[j][1];
    sout[jc * 65 + r0 + 8] = acc[j][2];
    sout[(jc + 1) * 65 + r0 + 8] = acc[j][3];
  }
  __syncthreads();
  long wb = (long)(e * 1024 + wwin);
  for (int idx = t; idx < 12288; idx += 256) {
    int ch = idx & 15, n = (idx >> 4) & 63, hh = (idx >> 10) & 3, p = idx >> 12;
    int jc = p * 64 + ch * 4 + hh;
    float vv = sout[jc * 65 + n];
    long qi = (wb * 4 + hh) * 1024 + n * 16 + ch;
    if (p == 0) g_q[qi] = vv;
    else if (p == 1) g_k[qi] = vv;
    else g_v[qi] = vv;
  }
  for (int idx = t; idx < 4096; idx += 256) {
    int c2 = idx & 63, n = idx >> 6;
    int hh = c2 >> 4, ch = c2 & 15;
    g_gin[(wb * 64 + n) * 192 + 128 + c2] = sout[(ch * 4 + hh) * 65 + n];
  }
}

// ---------------- K2: 6 cross-exposure attentions (single-pass, packed) ----------
__global__ void k2_attn() {
  extern __shared__ float sm2[];
  float* sk = sm2;
  float* sv = sm2 + 4096;
  const int e_of[6]  = {0, 0, 1, 1, 2, 2};
  const int kv_of[6] = {1, 2, 0, 2, 1, 0};
  const int sl_of[6] = {0, 1, 0, 1, 0, 1};
  int w = blockIdx.x, z = blockIdx.y;
  int e = e_of[z], ekv = kv_of[z], sl = sl_of[z];
  int t = threadIdx.x;
  int hh = t >> 5, lane = t & 31;
  long kb = (long)(ekv * 1024 + w) * 4096;
  for (int idx = t; idx < 1024; idx += 128) {
    *(float4*)&sk[idx * 4] = *(const float4*)&g_k[kb + idx * 4];
    *(float4*)&sv[idx * 4] = *(const float4*)&g_v[kb + idx * 4];
  }
  long qbase = (long)(e * 1024 + w) * 4096 + hh * 1024;
  ull qa[8], qb[8];
  {
    const ulonglong2* qg = (const ulonglong2*)(g_q + qbase + lane * 16);
    ulonglong2 a0 = qg[0], a1 = qg[1], a2 = qg[2], a3 = qg[3];
    qa[0] = a0.x; qa[1] = a0.y; qa[2] = a1.x; qa[3] = a1.y;
    qa[4] = a2.x; qa[5] = a2.y; qa[6] = a3.x; qa[7] = a3.y;
    const ulonglong2* qh = (const ulonglong2*)(g_q + qbase + (lane + 32) * 16);
    ulonglong2 b0 = qh[0], b1 = qh[1], b2 = qh[2], b3 = qh[3];
    qb[0] = b0.x; qb[1] = b0.y; qb[2] = b1.x; qb[3] = b1.y;
    qb[4] = b2.x; qb[5] = b2.y; qb[6] = b3.x; qb[7] = b3.y;
  }
  __syncthreads();
  int wh = w >> 5, ww = w & 31;
  int na = lane, nb = lane + 32;
  ull mA = 0ULL, mB = 0ULL;
  if (wh == 31) {
    mA |= ((na >> 3) < 4) ? 0xFFFFFFFF00000000ULL : 0x00000000FFFFFFFFULL;
    mB |= ((nb >> 3) < 4) ? 0xFFFFFFFF00000000ULL : 0x00000000FFFFFFFFULL;
  }
  if (ww == 31) {
    mA |= ((na & 7) < 4) ? 0xF0F0F0F0F0F0F0F0ULL : 0x0F0F0F0F0F0F0F0FULL;
    mB |= ((nb & 7) < 4) ? 0xF0F0F0F0F0F0F0F0ULL : 0x0F0F0F0F0F0F0F0FULL;
  }
  float suma = 0.f, sumb = 0.f;
  ull acca[8], accb[8];
#pragma unroll
  for (int c = 0; c < 8; c++) { acca[c] = 0ULL; accb[c] = 0ULL; }
  const ulonglong2* skp2 = (const ulonglong2*)(sk + hh * 1024);
  const ulonglong2* svp2 = (const ulonglong2*)(sv + hh * 1024);
#pragma unroll 4
  for (int m = 0; m < 64; m++) {
    ulonglong2 k0 = skp2[m * 4], k1 = skp2[m * 4 + 1];
    ulonglong2 k2 = skp2[m * 4 + 2], k3 = skp2[m * 4 + 3];
    ull da = 0ULL, db = 0ULL;
    da = fma2(qa[0], k0.x, da); db = fma2(qb[0], k0.x, db);
    da = fma2(qa[1], k0.y, da); db = fma2(qb[1], k0.y, db);
    da = fma2(qa[2], k1.x, da); db = fma2(qb[2], k1.x, db);
    da = fma2(qa[3], k1.y, da); db = fma2(qb[3], k1.y, db);
    da = fma2(qa[4], k2.x, da); db = fma2(qb[4], k2.x, db);
    da = fma2(qa[5], k2.y, da); db = fma2(qb[5], k2.y, db);
    da = fma2(qa[6], k3.x, da); db = fma2(qb[6], k3.x, db);
    da = fma2(qa[7], k3.y, da); db = fma2(qb[7], k3.y, db);
    float2 fa = up2(da), fb = up2(db);
    float sa = (fa.x + fa.y) * 0.125f;
    float sb = (fb.x + fb.y) * 0.125f;
    if ((mA >> m) & 1) sa -= 100.f;
    if ((mB >> m) & 1) sb -= 100.f;
    float p = __expf(sa), pq = __expf(sb);
    suma += p; sumb += pq;
    ull ppa = pk2(p, p), ppb = pk2(pq, pq);
    ulonglong2 v0 = svp2[m * 4], v1 = svp2[m * 4 + 1];
    ulonglong2 v2 = svp2[m * 4 + 2], v3 = svp2[m * 4 + 3];
    acca[0] = fma2(ppa, v0.x, acca[0]); accb[0] = fma2(ppb, v0.x, accb[0]);
    acca[1] = fma2(ppa, v0.y, acca[1]); accb[1] = fma2(ppb, v0.y, accb[1]);
    acca[2] = fma2(ppa, v1.x, acca[2]); accb[2] = fma2(ppb, v1.x, accb[2]);
    acca[3] = fma2(ppa, v1.y, acca[3]); accb[3] = fma2(ppb, v1.y, accb[3]);
    acca[4] = fma2(ppa, v2.x, acca[4]); accb[4] = fma2(ppb, v2.x, accb[4]);
    acca[5] = fma2(ppa, v2.y, acca[5]); accb[5] = fma2(ppb, v2.y, accb[5]);
    acca[6] = fma2(ppa, v3.x, acca[6]); accb[6] = fma2(ppb, v3.x, accb[6]);
    acca[7] = fma2(ppa, v3.y, acca[7]); accb[7] = fma2(ppb, v3.y, accb[7]);
  }
  float inva = 1.f / suma, invb = 1.f / sumb;
  long gba = ((long)(e * 1024 + w) * 64 + na) * 192 + sl * 64 + hh * 16;
  long gbb = ((long)(e * 1024 + w) * 64 + nb) * 192 + sl * 64 + hh * 16;
#pragma unroll
  for (int c4 = 0; c4 < 4; c4++) {
    float2 u0 = up2(acca[c4 * 2]);
    float2 u1 = up2(acca[c4 * 2 + 1]);
    *(float4*)&g_gin[gba + c4 * 4] = make_float4(u0.x * inva, u0.y * inva, u1.x * inva, u1.y * inva);
    float2 w0 = up2(accb[c4 * 2]);
    float2 w1 = up2(accb[c4 * 2 + 1]);
    *(float4*)&g_gin[gbb + c4 * 4] = make_float4(w0.x * invb, w0.y * invb, w1.x * invb, w1.y * invb);
  }
}

// ---------------- K3: per-exposure GEGLU via tf32 MMA ----------------------------
__global__ void k3_geglu(const float* __restrict__ b11, const float* __restrict__ b12,
                         const float* __restrict__ b2) {
  extern __shared__ float sgin_f[];
  unsigned* sgin = (unsigned*)sgin_f;
  __shared__ float st[64 * 68];
  unsigned* stu = (unsigned*)st;
  int blk = blockIdx.x;
  int e = blk >> 10;
  int t = threadIdx.x;
  long gbase = (long)blk * 12288;
  for (int idx = t; idx < 12288; idx += 256) {
    int nn = idx / 192, c = idx - nn * 192;
    sgin[nn * 196 + c] = tf32r(g_gin[gbase + idx]);
  }
  __syncthreads();
  int wa = t >> 5, lane = t & 31;
  int mt = wa & 3, nh = wa >> 2;
  int arow = mt * 16 + (lane >> 2);
  int acol = lane & 3;
  int ccol0 = 2 * (lane & 3);
  float a1[4][4], g1[4][4];
#pragma unroll
  for (int j = 0; j < 4; j++) {
    int o = (nh * 4 + j) * 8 + ccol0;
    float ba0 = b11[e * 64 + o], ba1 = b11[e * 64 + o + 1];
    float bg0 = b12[e * 64 + o], bg1 = b12[e * 64 + o + 1];
    a1[j][0] = ba0; a1[j][1] = ba1; a1[j][2] = ba0; a1[j][3] = ba1;
    g1[j][0] = bg0; g1[j][1] = bg1; g1[j][2] = bg0; g1[j][3] = bg1;
  }
  const ull* W11 = g_wp11 + e * 6144;
  const ull* W12 = g_wp12 + e * 6144;
  for (int kit = 0; kit < 24; kit++) {
    int kc = kit * 8 + acol;
    unsigned A0 = sgin[arow * 196 + kc];
    unsigned A1 = sgin[(arow + 8) * 196 + kc];
    unsigned A2 = sgin[arow * 196 + kc + 4];
    unsigned A3 = sgin[(arow + 8) * 196 + kc + 4];
#pragma unroll
    for (int j = 0; j < 4; j++) {
      int ntile = nh * 4 + j;
      ull wv = W11[(ntile * 24 + kit) * 32 + lane];
      mma_tf32(a1[j][0], a1[j][1], a1[j][2], a1[j][3], A0, A1, A2, A3,
               (unsigned)wv, (unsigned)(wv >> 32));
      ull wv2 = W12[(ntile * 24 + kit) * 32 + lane];
      mma_tf32(g1[j][0], g1[j][1], g1[j][2], g1[j][3], A0, A1, A2, A3,
               (unsigned)wv2, (unsigned)(wv2 >> 32));
    }
  }
#pragma unroll
  for (int j = 0; j < 4; j++) {
    int fb = (nh * 4 + j) * 8 + ccol0;
    int r0 = mt * 16 + (lane >> 2);
#pragma unroll
    for (int rr = 0; rr < 2; rr++) {
      int row = r0 + rr * 8;
      float av0 = a1[j][rr * 2], av1 = a1[j][rr * 2 + 1];
      float gv0 = g1[j][rr * 2], gv1 = g1[j][rr * 2 + 1];
      float t0 = 0.5f * av0 * (1.f + erff(av0 * 0.70710678118654752f)) * gv0;
      float t1 = 0.5f * av1 * (1.f + erff(av1 * 0.70710678118654752f)) * gv1;
      stu[row * 68 + fb] = tf32r(t0);
      stu[row * 68 + fb + 1] = tf32r(t1);
    }
  }
  __syncthreads();
  float y2[4][4];
#pragma unroll
  for (int j = 0; j < 4; j++) {
    int o = (nh * 4 + j) * 8 + ccol0;
    float b0 = b2[e * 64 + o], b1v = b2[e * 64 + o + 1];
    y2[j][0] = b0; y2[j][1] = b1v; y2[j][2] = b0; y2[j][3] = b1v;
  }
  const ull* W2 = g_wp2 + e * 2048;
  for (int kit = 0; kit < 8; kit++) {
    int kc = kit * 8 + acol;
    unsigned A0 = stu[arow * 68 + kc];
    unsigned A1 = stu[(arow + 8) * 68 + kc];
    unsigned A2 = stu[arow * 68 + kc + 4];
    unsigned A3 = stu[(arow + 8) * 68 + kc + 4];
#pragma unroll
    for (int j = 0; j < 4; j++) {
      int ntile = nh * 4 + j;
      ull wv = W2[(ntile * 8 + kit) * 32 + lane];
      mma_tf32(y2[j][0], y2[j][1], y2[j][2], y2[j][3], A0, A1, A2, A3,
               (unsigned)wv, (unsigned)(wv >> 32));
    }
  }
  __syncthreads();
#pragma unroll
  for (int j = 0; j < 4; j++) {
    int fb = (nh * 4 + j) * 8 + ccol0;
    int r0 = mt * 16 + (lane >> 2);
#pragma unroll
    for (int rr = 0; rr < 2; rr++) {
      int row = r0 + rr * 8;
      st[row * 68 + fb] = y2[j][rr * 2];
      st[row * 68 + fb + 1] = y2[j][rr * 2 + 1];
    }
  }
  __syncthreads();
  long ybase = (long)blk * 4096;
  for (int idx = t; idx < 4096; idx += 256) {
    int nn = idx >> 6, f = idx & 63;
    g_y[ybase + idx] = st[nn * 68 + f];
  }
}

// ---------------- K4: window reverse + conv1x1 + roll + residual via tf32 MMA ----
// dyn smem (overlapped): sa-bits[64 n][196 c] @0 ; sres[192 oc][65 n] @0 (post-MMA)
__global__ void k4_conv11(const float* __restrict__ x) {
  extern __shared__ float sm4[];
  unsigned* sa = (unsigned*)sm4;
  float* sres = sm4;
  int wwin = blockIdx.x;
  int wh = wwin >> 5, ww = wwin & 31;
  int t = threadIdx.x;
  for (int idx = t; idx < 12288; idx += 256) {
    int e = idx >> 12, r = idx & 4095;
    int nn = r >> 6, f = r & 63;
    sa[nn * 196 + e * 64 + f] = tf32r(g_y[(long)(e * 1024 + wwin) * 4096 + r]);
  }
  __syncthreads();
  int wa = t >> 5, lane = t & 31;
  int mt = wa & 3, ng = wa >> 2;
  int arow = mt * 16 + (lane >> 2);
  int acol = lane & 3;
  int ccol0 = 2 * (lane & 3);
  float acc[12][4];
#pragma unroll
  for (int j = 0; j < 12; j++)
#pragma unroll
    for (int r = 0; r < 4; r++) acc[j][r] = 0.f;
  for (int kit = 0; kit < 24; kit++) {
    int kc = kit * 8 + acol;
    unsigned A0 = sa[arow * 196 + kc];
    unsigned A1 = sa[(arow + 8) * 196 + kc];
    unsigned A2 = sa[arow * 196 + kc + 4];
    unsigned A3 = sa[(arow + 8) * 196 + kc + 4];
#pragma unroll
    for (int j = 0; j < 12; j++) {
      int nt = ng * 12 + j;
      ull wv = g_wp192[(nt * 24 + kit) * 32 + lane];
      mma_tf32(acc[j][0], acc[j][1], acc[j][2], acc[j][3], A0, A1, A2, A3,
               (unsigned)wv, (unsigned)(wv >> 32));
    }
  }
  __syncthreads();
#pragma unroll
  for (int j = 0; j < 12; j++) {
    int oc = (ng * 12 + j) * 8 + ccol0;
    int r0 = mt * 16 + (lane >> 2);
    sres[oc * 65 + r0] = acc[j][0];
    sres[(oc + 1) * 65 + r0] = acc[j][1];
    sres[oc * 65 + r0 + 8] = acc[j][2];
    sres[(oc + 1) * 65 + r0 + 8] = acc[j][3];
  }
  __syncthreads();
  for (int idx = t; idx < 12288; idx += 256) {
    int n = idx & 63, oc = idx >> 6;
    int i = n >> 3, j = n & 7;
    int hp = (wh * 8 + i + 4) & 255;
    int wp = (ww * 8 + j + 4) & 255;
    int gi = oc * 65536 + hp * 256 + wp;
    g_xres[gi] = sres[oc * 65 + n] + x[gi];
  }
}

// ---------------- K5: LN2 + ff_in (192->768) via tf32 MMA ------------------------
__global__ void k5_ln_ffin(const float* __restrict__ ln2w, const float* __restrict__ ln2b) {
  extern __shared__ float sxn[];
  unsigned* sxnu = (unsigned*)sxn;
  __shared__ float red[256], red2[256], smean[64], srstd[64];
  __shared__ float sfl[2][64 * 66];
  int blk = blockIdx.x;
  int h = blk >> 2;
  int w0 = (blk & 3) * 64;
  int pix0 = h * 256 + w0;
  int t = threadIdx.x;
  for (int idx = t; idx < 12288; idx += 256) {
    int c = idx >> 6, p = idx & 63;
    sxn[p * 196 + c] = g_xres[c * 65536 + pix0 + p];
  }
  __syncthreads();
  {
    int p = t & 63, g = t >> 6;
    float s = 0.f, s2v = 0.f;
    for (int c = g; c < 192; c += 4) { float v = sxn[p * 196 + c]; s += v; s2v += v * v; }
    red[t] = s;
    red2[t] = s2v;
  }
  __syncthreads();
  if (t < 64) {
    float s = red[t] + red[64 + t] + red[128 + t] + red[192 + t];
    float s2v = red2[t] + red2[64 + t] + red2[128 + t] + red2[192 + t];
    float m = s * (1.f / 192.f);
    float var = s2v * (1.f / 192.f) - m * m;
    smean[t] = m;
    srstd[t] = rsqrtf(var + 1e-5f);
  }
  __syncthreads();
  for (int idx = t; idx < 12288; idx += 256) {
    int c = idx >> 6, p = idx & 63;
    float v = (sxn[p * 196 + c] - smean[p]) * srstd[p] * ln2w[c] + ln2b[c];
    sxnu[p * 196 + c] = tf32r(v);
  }
  __syncthreads();
  int wa = t >> 5, lane = t & 31;
  int mt = wa & 3, nh = wa >> 2;
  int arow = mt * 16 + (lane >> 2);
  int acol = lane & 3;
  int ccol0 = 2 * (lane & 3);
  for (int ch = 0; ch < 6; ch++) {
    float acc[8][4];
#pragma unroll
    for (int j = 0; j < 8; j++)
#pragma unroll
      for (int r = 0; r < 4; r++) acc[j][r] = 0.f;
    for (int kit = 0; kit < 24; kit++) {
      int kc = kit * 8 + acol;
      unsigned A0 = sxnu[arow * 196 + kc];
      unsigned A1 = sxnu[(arow + 8) * 196 + kc];
      unsigned A2 = sxnu[arow * 196 + kc + 4];
      unsigned A3 = sxnu[(arow + 8) * 196 + kc + 4];
#pragma unroll
      for (int j = 0; j < 8; j++) {
        int ntile = nh * 48 + ch * 8 + j;
        ull wv = g_wp_in[(ntile * 24 + kit) * 32 + lane];
        mma_tf32(acc[j][0], acc[j][1], acc[j][2], acc[j][3], A0, A1, A2, A3,
                 (unsigned)wv, (unsigned)(wv >> 32));
      }
    }
#pragma unroll
    for (int j = 0; j < 8; j++) {
      int ol = j * 8 + ccol0;
      int r0 = mt * 16 + (lane >> 2);
      sfl[nh][ol * 66 + r0] = acc[j][0];
      sfl[nh][(ol + 1) * 66 + r0] = acc[j][1];
      sfl[nh][ol * 66 + r0 + 8] = acc[j][2];
      sfl[nh][(ol + 1) * 66 + r0 + 8] = acc[j][3];
    }
    __syncthreads();
    for (int idx = t; idx < 8192; idx += 256) {
      int g = idx >> 12, ol = (idx >> 6) & 63, p = idx & 63;
      int o = g * 384 + ch * 64 + ol;
      g_hb[o * 65536 + pix0 + p] = sfl[g][ol * 66 + p];
    }
    __syncthreads();
  }
}

// ---------------- K6: depthwise 3x3 + gelu(g1)*g2, 8 rows/block ------------------
__global__ void k6_dw(const float* __restrict__ dw) {
  __shared__ float s0[10][258];
  __shared__ float s1[10][258];
  int h0 = blockIdx.x * 8;
  int c = blockIdx.y;
  int t = threadIdx.x;
  const float* p0 = g_hb + c * 65536;
  const float* p1 = g_hb + (c + 384) * 65536;
  for (int idx = t; idx < 10 * 258; idx += 256) {
    int r = idx / 258, cc = idx - r * 258;
    int hh = h0 - 1 + r, wp = cc - 1;
    float v0 = 0.f, v1 = 0.f;
    if (hh >= 0 && hh < 256 && wp >= 0 && wp < 256) {
      v0 = p0[hh * 256 + wp];
      v1 = p1[hh * 256 + wp];
    }
    s0[r][cc] = v0;
    s1[r][cc] = v1;
  }
  float f0r[9], f1r[9];
#pragma unroll
  for (int k = 0; k < 9; k++) { f0r[k] = dw[c * 9 + k]; f1r[k] = dw[(c + 384) * 9 + k]; }
  __syncthreads();
  int w = t;
#pragma unroll
  for (int r = 0; r < 8; r++) {
    float a = 0.f, b = 0.f;
#pragma unroll
    for (int dh = 0; dh < 3; dh++) {
#pragma unroll
      for (int dwi = 0; dwi < 3; dwi++) {
        a += s0[r + dh][w + dwi] * f0r[dh * 3 + dwi];
        b += s1[r + dh][w + dwi] * f1r[dh * 3 + dwi];
      }
    }
    float ge = 0.5f * a * (1.f + erff(a * 0.70710678118654752f));
    g_gb[c * 65536 + (h0 + r) * 256 + w] = ge * b;
  }
}

// ---------------- K7: ff_out (384->192) + residual via tf32 MMA ------------------
__global__ void k7_ffout(float* __restrict__ out) {
  extern __shared__ float sA_f[];
  unsigned* sA = (unsigned*)sA_f;
  __shared__ float sfl[4][16 * 34];
  int blk = blockIdx.x;
  int h = blk >> 3;
  int w0 = (blk & 7) * 32;
  int pix0 = h * 256 + w0;
  int t = threadIdx.x;
  for (int idx = t; idx < 12288; idx += 256) {
    int c = idx >> 5, p = idx & 31;
    sA[p * 388 + c] = tf32r(g_gb[c * 65536 + pix0 + p]);
  }
  __syncthreads();
  int wa = t >> 5, lane = t & 31;
  int mt = wa & 1, nq = wa >> 1;
  int arow = mt * 16 + (lane >> 2);
  int acol = lane & 3;
  int ccol0 = 2 * (lane & 3);
  float acc[6][4];
#pragma unroll
  for (int j = 0; j < 6; j++)
#pragma unroll
    for (int r = 0; r < 4; r++) acc[j][r] = 0.f;
  for (int kit = 0; kit < 48; kit++) {
    int kc = kit * 8 + acol;
    unsigned A0 = sA[arow * 388 + kc];
    unsigned A1 = sA[(arow + 8) * 388 + kc];
    unsigned A2 = sA[arow * 388 + kc + 4];
    unsigned A3 = sA[(arow + 8) * 388 + kc + 4];
#pragma unroll
    for (int j = 0; j < 6; j++) {
      int ntile = nq * 6 + j;
      ull wv = g_wp_out[(ntile * 48 + kit) * 32 + lane];
      mma_tf32(acc[j][0], acc[j][1], acc[j][2], acc[j][3], A0, A1, A2, A3,
               (unsigned)wv, (unsigned)(wv >> 32));
    }
  }
  for (int v = 0; v < 3; v++) {
#pragma unroll
    for (int jj = 0; jj < 2; jj++) {
      int j = v * 2 + jj;
      int ol = jj * 8 + ccol0;
      int r0 = mt * 16 + (lane >> 2);
      sfl[nq][ol * 34 + r0] = acc[j][0];
      sfl[nq][(ol + 1) * 34 + r0] = acc[j][1];
      sfl[nq][ol * 34 + r0 + 8] = acc[j][2];
      sfl[nq][(ol + 1) * 34 + r0 + 8] = acc[j][3];
    }
    __syncthreads();
    for (int idx = t; idx < 2048; idx += 256) {
      int g = idx >> 9, ol = (idx >> 5) & 15, p = idx & 31;
      int o = g * 48 + v * 16 + ol;
      int gi = o * 65536 + pix0 + p;
      out[gi] = g_xres[gi] + sfl[g][ol * 34 + p];
    }
    __syncthreads();
  }
}

// ---------------- host launcher --------------------------------------------------
extern "C" void kernel_launch(void* const* d_in, const int* in_sizes, int n_in,
                              void* d_out, int out_size) {
  const float* x    = (const float*)d_in[0];
  const float* ln1w = (const float*)d_in[1];
  const float* ln1b = (const float*)d_in[2];
  const float* ln2w = (const float*)d_in[3];
  const float* ln2b = (const float*)d_in[4];
  const float* wqkv = (const float*)d_in[5];
  const float* w11  = (const float*)d_in[6];
  const float* b11  = (const float*)d_in[7];
  const float* w12  = (const float*)d_in[8];
  const float* b12  = (const float*)d_in[9];
  const float* w2   = (const float*)d_in[10];
  const float* b2   = (const float*)d_in[11];
  const float* c11  = (const float*)d_in[12];
  const float* ffin = (const float*)d_in[13];
  const float* ffdw = (const float*)d_in[14];
  const float* ffou = (const float*)d_in[15];
  float* out = (float*)d_out;

  const int smem1 = (192 * 65) * 4;                 // 49920 (overlapped regions)
  const int smem2 = 8192 * 4;                       // 32768
  const int smem3 = (64 * 196) * 4;                 // 50176
  const int smem4 = (64 * 196) * 4;                 // 50176
  const int smem5 = (64 * 196) * 4;                 // 50176
  const int smem7 = (32 * 388) * 4;                 // 49664
  cudaFuncSetAttribute(k1_qkv, cudaFuncAttributeMaxDynamicSharedMemorySize, smem1);
  cudaFuncSetAttribute(k2_attn, cudaFuncAttributeMaxDynamicSharedMemorySize, smem2);
  cudaFuncSetAttribute(k3_geglu, cudaFuncAttributeMaxDynamicSharedMemorySize, smem3);
  cudaFuncSetAttribute(k4_conv11, cudaFuncAttributeMaxDynamicSharedMemorySize, smem4);
  cudaFuncSetAttribute(k5_ln_ffin, cudaFuncAttributeMaxDynamicSharedMemorySize, smem5);
  cudaFuncSetAttribute(k7_ffout, cudaFuncAttributeMaxDynamicSharedMemorySize, smem7);

  kpos<<<1, 64>>>();
  kpack<<<288, 256>>>(c11, ffin, ffou, w11, w12, w2, wqkv);
  k1_qkv<<<3072, 256, smem1>>>(x, ln1w, ln1b);
  {
    dim3 g2(1024, 6);
    k2_attn<<<g2, 128, smem2>>>();
  }
  k3_geglu<<<3072, 256, smem3>>>(b11, b12, b2);
  k4_conv11<<<1024, 256, smem4>>>(x);
  k5_ln_ffin<<<1024, 256, smem5>>>(ln2w, ln2b);
  {
    dim3 g6(32, 384);
    k6_dw<<<g6, 256>>>(ffdw);
  }
  k7_ffout<<<2048, 256, smem7>>>(out);
}

// round 6
// speedup vs baseline: 5.9053x; 1.8484x over previous
#include <cuda_runtime.h>
#include <cuda_fp16.h>
#include <math.h>

typedef unsigned long long ull;

// ---------------- packed f32x2 helpers (attention) --------------------------------
__device__ __forceinline__ ull fma2(ull a, ull b, ull c) {
  ull d;
  asm("fma.rn.f32x2 %0, %1, %2, %3;" : "=l"(d) : "l"(a), "l"(b), "l"(c));
  return d;
}
__device__ __forceinline__ ull pk2(float x, float y) {
  ull r;
  asm("mov.b64 %0, {%1, %2};" : "=l"(r) : "f"(x), "f"(y));
  return r;
}
__device__ __forceinline__ float2 up2(ull a) {
  float2 f;
  asm("mov.b64 {%0, %1}, %2;" : "=f"(f.x), "=f"(f.y) : "l"(a));
  return f;
}

// ---------------- fp16 MMA helpers -------------------------------------------------
__device__ __forceinline__ unsigned h2pk(float a, float b) {
  __half2 h = __floats2half2_rn(a, b);
  return *(unsigned*)&h;
}
__device__ __forceinline__ void mma_f16(float* c, const unsigned* a, unsigned b0, unsigned b1) {
  asm volatile(
      "mma.sync.aligned.m16n8k16.row.col.f32.f16.f16.f32 "
      "{%0,%1,%2,%3},{%4,%5,%6,%7},{%8,%9},{%0,%1,%2,%3};"
      : "+f"(c[0]), "+f"(c[1]), "+f"(c[2]), "+f"(c[3])
      : "r"(a[0]), "r"(a[1]), "r"(a[2]), "r"(a[3]), "r"(b0), "r"(b1));
}
__device__ __forceinline__ float gelu_exact(float a) {
  return 0.5f * a * (1.f + erff(a * 0.70710678118654752f));
}

// ---------------- static device scratch --------------------------------------------
__device__ float g_pos[64 * 64];
__device__ float g_q[3 * 1024 * 4 * 64 * 16];
__device__ float g_k[3 * 1024 * 4 * 64 * 16];
__device__ float g_v[3 * 1024 * 4 * 64 * 16];
__device__ __half g_yh[3 * 1024 * 4096];
__device__ float g_xres[192 * 65536];
__device__ __half g_hbh[768 * 65536];
__device__ __half g_gbh[384 * 65536];
// packed fp16 weight fragments: [ntile][kit16][lane] -> (b0 | b1<<32)
__device__ ull g_wp_in[96 * 12 * 32];     // ff_in  (K=192, N=768)
__device__ ull g_wp_out[24 * 24 * 32];    // ff_out (K=384, N=192)
__device__ ull g_wp11[3 * 8 * 12 * 32];   // me_w11 (K=192, N=64)
__device__ ull g_wp12[3 * 8 * 12 * 32];   // me_w12
__device__ ull g_wp2[3 * 8 * 4 * 32];     // me_w2  (K=64,  N=64)
__device__ ull g_wpqkv[24 * 4 * 32];      // w_qkv  (K=64,  N=192)
__device__ ull g_wp192[24 * 12 * 32];     // conv11 (K=192, N=192)

// ---------------- K0a: sine positional encoding ------------------------------------
__global__ void kpos() {
  int n = threadIdx.x;
  int i = n >> 3, j = n & 7;
  double scale = 6.283185307179586476925286766559;
  double yv = (double)(i + 1) / (8.0 + 1e-6) * scale;
  double xv = (double)(j + 1) / (8.0 + 1e-6) * scale;
  for (int c = 0; c < 64; c++) {
    double base = (c < 32) ? yv : xv;
    int k = (c < 32) ? c : (c - 32);
    double dt = pow(10000.0, (double)(k >> 1) / 16.0);
    double v = base / dt;
    g_pos[n * 64 + c] = (float)(((k & 1) == 0) ? sin(v) : cos(v));
  }
}

// ---------------- K0b: fp16 fragment packing ---------------------------------------
__global__ void kpack(const float* __restrict__ c11, const float* __restrict__ ffin,
                      const float* __restrict__ ffout, const float* __restrict__ w11,
                      const float* __restrict__ w12, const float* __restrict__ w2,
                      const float* __restrict__ wqkv) {
  int idx = blockIdx.x * 256 + threadIdx.x;
  int lane = idx & 31;
  if (idx < 36864) {  // wp_in [96][12][32], src [o=768][k=192]
    int kit = (idx >> 5) % 12, nt = idx / 384;
    int o = nt * 8 + (lane >> 2), k0 = kit * 16 + (lane & 3) * 2;
    unsigned b0 = h2pk(ffin[o * 192 + k0], ffin[o * 192 + k0 + 1]);
    unsigned b1 = h2pk(ffin[o * 192 + k0 + 8], ffin[o * 192 + k0 + 9]);
    g_wp_in[idx] = (ull)b0 | ((ull)b1 << 32);
  }
  if (idx < 18432) {  // wp_out [24][24][32], src [o=192][k=384]
    int kit = (idx >> 5) % 24, nt = idx / 768;
    int o = nt * 8 + (lane >> 2), k0 = kit * 16 + (lane & 3) * 2;
    unsigned b0 = h2pk(ffout[o * 384 + k0], ffout[o * 384 + k0 + 1]);
    unsigned b1 = h2pk(ffout[o * 384 + k0 + 8], ffout[o * 384 + k0 + 9]);
    g_wp_out[idx] = (ull)b0 | ((ull)b1 << 32);
  }
  if (idx < 9216) {  // wp11/wp12 [3][8][12][32], src [e][k=192][f=64]
    int e = idx / 3072, r = idx % 3072;
    int kit = (r >> 5) % 12, nt = r / 384;
    int f = nt * 8 + (lane >> 2), k0 = kit * 16 + (lane & 3) * 2;
    const float* Wa = w11 + e * 12288;
    const float* Wb = w12 + e * 12288;
    unsigned a0 = h2pk(Wa[k0 * 64 + f], Wa[(k0 + 1) * 64 + f]);
    unsigned a1 = h2pk(Wa[(k0 + 8) * 64 + f], Wa[(k0 + 9) * 64 + f]);
    g_wp11[idx] = (ull)a0 | ((ull)a1 << 32);
    unsigned c0 = h2pk(Wb[k0 * 64 + f], Wb[(k0 + 1) * 64 + f]);
    unsigned c1 = h2pk(Wb[(k0 + 8) * 64 + f], Wb[(k0 + 9) * 64 + f]);
    g_wp12[idx] = (ull)c0 | ((ull)c1 << 32);
  }
  if (idx < 3072) {  // wp2 [3][8][4][32], src [e][k=64][f=64]
    int e = idx / 1024, r = idx % 1024;
    int kit = (r >> 5) % 4, nt = r / 128;
    int f = nt * 8 + (lane >> 2), k0 = kit * 16 + (lane & 3) * 2;
    const float* Wa = w2 + e * 4096;
    unsigned b0 = h2pk(Wa[k0 * 64 + f], Wa[(k0 + 1) * 64 + f]);
    unsigned b1 = h2pk(Wa[(k0 + 8) * 64 + f], Wa[(k0 + 9) * 64 + f]);
    g_wp2[idx] = (ull)b0 | ((ull)b1 << 32);
  }
  if (idx < 3072) {  // wpqkv [24][4][32], src [k=64][n=192]
    int kit = (idx >> 5) % 4, nt = idx / 128;
    int n = nt * 8 + (lane >> 2), k0 = kit * 16 + (lane & 3) * 2;
    unsigned b0 = h2pk(wqkv[k0 * 192 + n], wqkv[(k0 + 1) * 192 + n]);
    unsigned b1 = h2pk(wqkv[(k0 + 8) * 192 + n], wqkv[(k0 + 9) * 192 + n]);
    g_wpqkv[idx] = (ull)b0 | ((ull)b1 << 32);
  }
  if (idx < 9216) {  // wp192 [24][12][32], src [o=192][k=192]
    int kit = (idx >> 5) % 12, nt = idx / 384;
    int o = nt * 8 + (lane >> 2), k0 = kit * 16 + (lane & 3) * 2;
    unsigned b0 = h2pk(c11[o * 192 + k0], c11[o * 192 + k0 + 1]);
    unsigned b1 = h2pk(c11[o * 192 + k0 + 8], c11[o * 192 + k0 + 9]);
    g_wp192[idx] = (ull)b0 | ((ull)b1 << 32);
  }
}

// ---------------- K1: shift+window + LN1 + pos + QKV GEMM (fp16 MMA) ---------------
// dyn smem: sx f32 [64*65] @0 | snT h2 [64*36 uints] @16640B | sout f32 [192*65] @0 (post)
__global__ void k1_qkv(const float* __restrict__ x, const float* __restrict__ ln1w,
                       const float* __restrict__ ln1b) {
  extern __shared__ float sm1[];
  float* sx = sm1;
  unsigned* snT = (unsigned*)(sm1 + 4160);
  float* sout = sm1;
  __shared__ float smean[64], srstd[64];
  int blk = blockIdx.x;
  int e = blk >> 10, wwin = blk & 1023;
  int wh = wwin >> 5, ww = wwin & 31;
  int t = threadIdx.x;
  for (int idx = t; idx < 4096; idx += 256) {
    int c = idx >> 6, n = idx & 63;
    int i = n >> 3, j = n & 7;
    int h0 = (wh * 8 + i + 4) & 255;
    int w0 = (ww * 8 + j + 4) & 255;
    sx[n * 65 + c] = x[((e * 64 + c) * 256 + h0) * 256 + w0];
  }
  __syncthreads();
  if (t < 64) {
    int n = t;
    float m = 0.f;
#pragma unroll
    for (int c = 0; c < 64; c++) m += sx[n * 65 + c];
    m *= (1.f / 64.f);
    float v = 0.f;
#pragma unroll
    for (int c = 0; c < 64; c++) { float d = sx[n * 65 + c] - m; v += d * d; }
    v *= (1.f / 64.f);
    smean[n] = m;
    srstd[n] = rsqrtf(v + 1e-5f);
  }
  __syncthreads();
  for (int idx = t; idx < 2048; idx += 256) {
    int n = idx >> 5, kk = idx & 31;
    int c = kk * 2;
    float v0 = (sx[n * 65 + c] - smean[n]) * srstd[n] * ln1w[c] + ln1b[c] + g_pos[n * 64 + c];
    float v1 = (sx[n * 65 + c + 1] - smean[n]) * srstd[n] * ln1w[c + 1] + ln1b[c + 1] + g_pos[n * 64 + c + 1];
    snT[n * 36 + kk] = h2pk(v0, v1);
  }
  __syncthreads();
  int wa = t >> 5, lane = t & 31;
  int rq = lane >> 2, acol = lane & 3, ccol0 = 2 * acol;
  float acc[3][4][4];
#pragma unroll
  for (int j = 0; j < 3; j++)
#pragma unroll
    for (int mt = 0; mt < 4; mt++)
#pragma unroll
      for (int r = 0; r < 4; r++) acc[j][mt][r] = 0.f;
  for (int kit = 0; kit < 4; kit++) {
    unsigned A[4][4];
#pragma unroll
    for (int mt = 0; mt < 4; mt++) {
      int r = mt * 16 + rq;
      A[mt][0] = snT[r * 36 + kit * 8 + acol];
      A[mt][1] = snT[(r + 8) * 36 + kit * 8 + acol];
      A[mt][2] = snT[r * 36 + kit * 8 + acol + 4];
      A[mt][3] = snT[(r + 8) * 36 + kit * 8 + acol + 4];
    }
#pragma unroll
    for (int j = 0; j < 3; j++) {
      ull wv = g_wpqkv[((wa * 3 + j) * 4 + kit) * 32 + lane];
#pragma unroll
      for (int mt = 0; mt < 4; mt++)
        mma_f16(acc[j][mt], A[mt], (unsigned)wv, (unsigned)(wv >> 32));
    }
  }
  __syncthreads();
#pragma unroll
  for (int j = 0; j < 3; j++) {
    int jc = (wa * 3 + j) * 8 + ccol0;
#pragma unroll
    for (int mt = 0; mt < 4; mt++) {
      int r0 = mt * 16 + rq;
      sout[jc * 65 + r0] = acc[j][mt][0];
      sout[(jc + 1) * 65 + r0] = acc[j][mt][1];
      sout[jc * 65 + r0 + 8] = acc[j][mt][2];
      sout[(jc + 1) * 65 + r0 + 8] = acc[j][mt][3];
    }
  }
  __syncthreads();
  long wb = (long)(e * 1024 + wwin);
  for (int idx = t; idx < 12288; idx += 256) {
    int ch = idx & 15, n = (idx >> 4) & 63, hh = (idx >> 10) & 3, p = idx >> 12;
    int jc = p * 64 + ch * 4 + hh;
    float vv = sout[jc * 65 + n];
    long qi = (wb * 4 + hh) * 1024 + n * 16 + ch;
    if (p == 0) g_q[qi] = vv;
    else if (p == 1) g_k[qi] = vv;
    else g_v[qi] = vv;
  }
}

// ---------------- K23: fused 2-slot attention + GEGLU per (e, window) --------------
// dyn smem: skA@0, svA@4096, skB@8192, svB@12288 (floats) | sgin h2 [64*100 uints] @65536B
__global__ void k23_attn_geglu(const float* __restrict__ b11, const float* __restrict__ b12,
                               const float* __restrict__ b2) {
  extern __shared__ float sm2[];
  unsigned* sgin = (unsigned*)(sm2 + 16384);
  __shared__ unsigned stu[64 * 36];
  int w = blockIdx.x, e = blockIdx.y;
  const int ekvA_of[3] = {1, 0, 1};
  const int ekvB_of[3] = {2, 2, 0};
  int eA = ekvA_of[e], eB = ekvB_of[e];
  int t = threadIdx.x;
  int wa = t >> 5, lane = t & 31;
  long kbA = (long)(eA * 1024 + w) * 4096;
  long kbB = (long)(eB * 1024 + w) * 4096;
  long qb = (long)(e * 1024 + w) * 4096;
  for (int idx = t; idx < 1024; idx += 256) {
    *(float4*)&sm2[idx * 4] = *(const float4*)&g_k[kbA + idx * 4];
    *(float4*)&sm2[4096 + idx * 4] = *(const float4*)&g_v[kbA + idx * 4];
    *(float4*)&sm2[8192 + idx * 4] = *(const float4*)&g_k[kbB + idx * 4];
    *(float4*)&sm2[12288 + idx * 4] = *(const float4*)&g_v[kbB + idx * 4];
  }
  // merged-q into sgin features [128,192)
  for (int idx = t; idx < 1024; idx += 256) {
    int n = idx >> 4, pr = idx & 15;
    int hh = pr >> 2, ch = (pr & 3) * 4;
    float4 qv = *(const float4*)&g_q[qb + hh * 1024 + n * 16 + ch];
    sgin[n * 100 + 64 + pr * 2] = h2pk(qv.x, qv.y);
    sgin[n * 100 + 64 + pr * 2 + 1] = h2pk(qv.z, qv.w);
  }
  int grp = wa >> 2;     // 0 -> slot A, 1 -> slot B
  int hh = wa & 3;
  ull qa[8], qbr[8];
  {
    const ulonglong2* qg = (const ulonglong2*)(g_q + qb + hh * 1024 + lane * 16);
    ulonglong2 a0 = qg[0], a1 = qg[1], a2 = qg[2], a3 = qg[3];
    qa[0] = a0.x; qa[1] = a0.y; qa[2] = a1.x; qa[3] = a1.y;
    qa[4] = a2.x; qa[5] = a2.y; qa[6] = a3.x; qa[7] = a3.y;
    const ulonglong2* qh = (const ulonglong2*)(g_q + qb + hh * 1024 + (lane + 32) * 16);
    ulonglong2 b0 = qh[0], b1 = qh[1], b2v = qh[2], b3 = qh[3];
    qbr[0] = b0.x; qbr[1] = b0.y; qbr[2] = b1.x; qbr[3] = b1.y;
    qbr[4] = b2v.x; qbr[5] = b2v.y; qbr[6] = b3.x; qbr[7] = b3.y;
  }
  __syncthreads();
  // ---- attention (scalar packed fp32, single-pass softmax) ----
  {
    int wh = w >> 5, ww = w & 31;
    int na = lane, nb = lane + 32;
    ull mA = 0ULL, mB = 0ULL;
    if (wh == 31) {
      mA |= ((na >> 3) < 4) ? 0xFFFFFFFF00000000ULL : 0x00000000FFFFFFFFULL;
      mB |= ((nb >> 3) < 4) ? 0xFFFFFFFF00000000ULL : 0x00000000FFFFFFFFULL;
    }
    if (ww == 31) {
      mA |= ((na & 7) < 4) ? 0xF0F0F0F0F0F0F0F0ULL : 0x0F0F0F0F0F0F0F0FULL;
      mB |= ((nb & 7) < 4) ? 0xF0F0F0F0F0F0F0F0ULL : 0x0F0F0F0F0F0F0F0FULL;
    }
    float suma = 0.f, sumb = 0.f;
    ull acca[8], accb[8];
#pragma unroll
    for (int c = 0; c < 8; c++) { acca[c] = 0ULL; accb[c] = 0ULL; }
    const float* ksel = sm2 + grp * 8192;
    const ulonglong2* skp2 = (const ulonglong2*)(ksel + hh * 1024);
    const ulonglong2* svp2 = (const ulonglong2*)(ksel + 4096 + hh * 1024);
#pragma unroll 4
    for (int m = 0; m < 64; m++) {
      ulonglong2 k0 = skp2[m * 4], k1 = skp2[m * 4 + 1];
      ulonglong2 k2 = skp2[m * 4 + 2], k3 = skp2[m * 4 + 3];
      ull da = 0ULL, db = 0ULL;
      da = fma2(qa[0], k0.x, da); db = fma2(qbr[0], k0.x, db);
      da = fma2(qa[1], k0.y, da); db = fma2(qbr[1], k0.y, db);
      da = fma2(qa[2], k1.x, da); db = fma2(qbr[2], k1.x, db);
      da = fma2(qa[3], k1.y, da); db = fma2(qbr[3], k1.y, db);
      da = fma2(qa[4], k2.x, da); db = fma2(qbr[4], k2.x, db);
      da = fma2(qa[5], k2.y, da); db = fma2(qbr[5], k2.y, db);
      da = fma2(qa[6], k3.x, da); db = fma2(qbr[6], k3.x, db);
      da = fma2(qa[7], k3.y, da); db = fma2(qbr[7], k3.y, db);
      float2 fa = up2(da), fb = up2(db);
      float sa = (fa.x + fa.y) * 0.125f;
      float sb = (fb.x + fb.y) * 0.125f;
      if ((mA >> m) & 1) sa -= 100.f;
      if ((mB >> m) & 1) sb -= 100.f;
      float p = __expf(sa), pq = __expf(sb);
      suma += p; sumb += pq;
      ull ppa = pk2(p, p), ppb = pk2(pq, pq);
      ulonglong2 v0 = svp2[m * 4], v1 = svp2[m * 4 + 1];
      ulonglong2 v2 = svp2[m * 4 + 2], v3 = svp2[m * 4 + 3];
      acca[0] = fma2(ppa, v0.x, acca[0]); accb[0] = fma2(ppb, v0.x, accb[0]);
      acca[1] = fma2(ppa, v0.y, acca[1]); accb[1] = fma2(ppb, v0.y, accb[1]);
      acca[2] = fma2(ppa, v1.x, acca[2]); accb[2] = fma2(ppb, v1.x, accb[2]);
      acca[3] = fma2(ppa, v1.y, acca[3]); accb[3] = fma2(ppb, v1.y, accb[3]);
      acca[4] = fma2(ppa, v2.x, acca[4]); accb[4] = fma2(ppb, v2.x, accb[4]);
      acca[5] = fma2(ppa, v2.y, acca[5]); accb[5] = fma2(ppb, v2.y, accb[5]);
      acca[6] = fma2(ppa, v3.x, acca[6]); accb[6] = fma2(ppb, v3.x, accb[6]);
      acca[7] = fma2(ppa, v3.y, acca[7]); accb[7] = fma2(ppb, v3.y, accb[7]);
    }
    float inva = 1.f / suma, invb = 1.f / sumb;
    int baseA = na * 100 + grp * 32 + hh * 8;
    int baseB = nb * 100 + grp * 32 + hh * 8;
    uint4 o0, o1;
    {
      float2 u0 = up2(acca[0]), u1 = up2(acca[1]), u2 = up2(acca[2]), u3 = up2(acca[3]);
      float2 u4 = up2(acca[4]), u5 = up2(acca[5]), u6 = up2(acca[6]), u7 = up2(acca[7]);
      o0 = make_uint4(h2pk(u0.x * inva, u0.y * inva), h2pk(u1.x * inva, u1.y * inva),
                      h2pk(u2.x * inva, u2.y * inva), h2pk(u3.x * inva, u3.y * inva));
      o1 = make_uint4(h2pk(u4.x * inva, u4.y * inva), h2pk(u5.x * inva, u5.y * inva),
                      h2pk(u6.x * inva, u6.y * inva), h2pk(u7.x * inva, u7.y * inva));
      *(uint4*)&sgin[baseA] = o0;
      *(uint4*)&sgin[baseA + 4] = o1;
    }
    {
      float2 u0 = up2(accb[0]), u1 = up2(accb[1]), u2 = up2(accb[2]), u3 = up2(accb[3]);
      float2 u4 = up2(accb[4]), u5 = up2(accb[5]), u6 = up2(accb[6]), u7 = up2(accb[7]);
      o0 = make_uint4(h2pk(u0.x * invb, u0.y * invb), h2pk(u1.x * invb, u1.y * invb),
                      h2pk(u2.x * invb, u2.y * invb), h2pk(u3.x * invb, u3.y * invb));
      o1 = make_uint4(h2pk(u4.x * invb, u4.y * invb), h2pk(u5.x * invb, u5.y * invb),
                      h2pk(u6.x * invb, u6.y * invb), h2pk(u7.x * invb, u7.y * invb));
      *(uint4*)&sgin[baseB] = o0;
      *(uint4*)&sgin[baseB + 4] = o1;
    }
  }
  __syncthreads();
  // ---- GEGLU GEMM1: gin(64x192) @ w11 / w12 -> a, g ----
  int rq = lane >> 2, acol = lane & 3;
  float a1[4][4], g1[4][4];
  {
    int o = wa * 8 + 2 * acol;
    float ba0 = b11[e * 64 + o], ba1 = b11[e * 64 + o + 1];
    float bg0 = b12[e * 64 + o], bg1 = b12[e * 64 + o + 1];
#pragma unroll
    for (int mt = 0; mt < 4; mt++) {
      a1[mt][0] = ba0; a1[mt][1] = ba1; a1[mt][2] = ba0; a1[mt][3] = ba1;
      g1[mt][0] = bg0; g1[mt][1] = bg1; g1[mt][2] = bg0; g1[mt][3] = bg1;
    }
  }
  const ull* W11 = g_wp11 + e * 3072 + wa * 12 * 32;
  const ull* W12 = g_wp12 + e * 3072 + wa * 12 * 32;
  for (int kit = 0; kit < 12; kit++) {
    unsigned A[4][4];
#pragma unroll
    for (int mt = 0; mt < 4; mt++) {
      int r = mt * 16 + rq;
      A[mt][0] = sgin[r * 100 + kit * 8 + acol];
      A[mt][1] = sgin[(r + 8) * 100 + kit * 8 + acol];
      A[mt][2] = sgin[r * 100 + kit * 8 + acol + 4];
      A[mt][3] = sgin[(r + 8) * 100 + kit * 8 + acol + 4];
    }
    ull wv1 = W11[kit * 32 + lane];
    ull wv2 = W12[kit * 32 + lane];
#pragma unroll
    for (int mt = 0; mt < 4; mt++) {
      mma_f16(a1[mt], A[mt], (unsigned)wv1, (unsigned)(wv1 >> 32));
      mma_f16(g1[mt], A[mt], (unsigned)wv2, (unsigned)(wv2 >> 32));
    }
  }
#pragma unroll
  for (int mt = 0; mt < 4; mt++) {
    int r0 = mt * 16 + rq;
    stu[r0 * 36 + wa * 4 + acol] = h2pk(gelu_exact(a1[mt][0]) * g1[mt][0],
                                        gelu_exact(a1[mt][1]) * g1[mt][1]);
    stu[(r0 + 8) * 36 + wa * 4 + acol] = h2pk(gelu_exact(a1[mt][2]) * g1[mt][2],
                                              gelu_exact(a1[mt][3]) * g1[mt][3]);
  }
  __syncthreads();
  // ---- GEGLU GEMM2: t(64x64) @ w2 -> y ----
  float y2[4][4];
  {
    int o = wa * 8 + 2 * acol;
    float b0 = b2[e * 64 + o], b1v = b2[e * 64 + o + 1];
#pragma unroll
    for (int mt = 0; mt < 4; mt++) {
      y2[mt][0] = b0; y2[mt][1] = b1v; y2[mt][2] = b0; y2[mt][3] = b1v;
    }
  }
  const ull* W2 = g_wp2 + e * 1024 + wa * 4 * 32;
  for (int kit = 0; kit < 4; kit++) {
    unsigned A[4][4];
#pragma unroll
    for (int mt = 0; mt < 4; mt++) {
      int r = mt * 16 + rq;
      A[mt][0] = stu[r * 36 + kit * 8 + acol];
      A[mt][1] = stu[(r + 8) * 36 + kit * 8 + acol];
      A[mt][2] = stu[r * 36 + kit * 8 + acol + 4];
      A[mt][3] = stu[(r + 8) * 36 + kit * 8 + acol + 4];
    }
    ull wv = W2[kit * 32 + lane];
#pragma unroll
    for (int mt = 0; mt < 4; mt++)
      mma_f16(y2[mt], A[mt], (unsigned)wv, (unsigned)(wv >> 32));
  }
  // stage y (h2) into sgin region (dead after GEMM1 + the sync above)
  unsigned* yst = sgin;
#pragma unroll
  for (int mt = 0; mt < 4; mt++) {
    int r0 = mt * 16 + rq;
    yst[r0 * 36 + wa * 4 + acol] = h2pk(y2[mt][0], y2[mt][1]);
    yst[(r0 + 8) * 36 + wa * 4 + acol] = h2pk(y2[mt][2], y2[mt][3]);
  }
  __syncthreads();
  long ybase = (long)(e * 1024 + w) * 4096;
  for (int idx = t; idx < 2048; idx += 256) {
    int n = idx >> 5, kk = idx & 31;
    *(__half2*)&g_yh[ybase + n * 64 + kk * 2] = *(__half2*)&yst[n * 36 + kk];
  }
}

// ---------------- K4: window reverse + conv1x1 + roll + residual (fp16 MMA) --------
// dyn smem: sa h2 [64*100 uints] @0 ; sres f32 [192*65] @0 (post-MMA)
__global__ void k4_conv11(const float* __restrict__ x) {
  extern __shared__ float sm4[];
  unsigned* sa = (unsigned*)sm4;
  float* sres = sm4;
  int wwin = blockIdx.x;
  int wh = wwin >> 5, ww = wwin & 31;
  int t = threadIdx.x;
  for (int idx = t; idx < 6144; idx += 256) {
    int n = idx / 96, kk = idx - n * 96;
    int c = kk * 2;
    int e = c >> 6, f = c & 63;
    sa[n * 100 + kk] = *(const unsigned*)&g_yh[(long)(e * 1024 + wwin) * 4096 + n * 64 + f];
  }
  __syncthreads();
  int wa = t >> 5, lane = t & 31;
  int rq = lane >> 2, acol = lane & 3, ccol0 = 2 * acol;
  float acc[3][4][4];
#pragma unroll
  for (int j = 0; j < 3; j++)
#pragma unroll
    for (int mt = 0; mt < 4; mt++)
#pragma unroll
      for (int r = 0; r < 4; r++) acc[j][mt][r] = 0.f;
  for (int kit = 0; kit < 12; kit++) {
    unsigned A[4][4];
#pragma unroll
    for (int mt = 0; mt < 4; mt++) {
      int r = mt * 16 + rq;
      A[mt][0] = sa[r * 100 + kit * 8 + acol];
      A[mt][1] = sa[(r + 8) * 100 + kit * 8 + acol];
      A[mt][2] = sa[r * 100 + kit * 8 + acol + 4];
      A[mt][3] = sa[(r + 8) * 100 + kit * 8 + acol + 4];
    }
#pragma unroll
    for (int j = 0; j < 3; j++) {
      ull wv = g_wp192[((wa * 3 + j) * 12 + kit) * 32 + lane];
#pragma unroll
      for (int mt = 0; mt < 4; mt++)
        mma_f16(acc[j][mt], A[mt], (unsigned)wv, (unsigned)(wv >> 32));
    }
  }
  __syncthreads();
#pragma unroll
  for (int j = 0; j < 3; j++) {
    int oc = (wa * 3 + j) * 8 + ccol0;
#pragma unroll
    for (int mt = 0; mt < 4; mt++) {
      int r0 = mt * 16 + rq;
      sres[oc * 65 + r0] = acc[j][mt][0];
      sres[(oc + 1) * 65 + r0] = acc[j][mt][1];
      sres[oc * 65 + r0 + 8] = acc[j][mt][2];
      sres[(oc + 1) * 65 + r0 + 8] = acc[j][mt][3];
    }
  }
  __syncthreads();
  for (int idx = t; idx < 12288; idx += 256) {
    int n = idx & 63, oc = idx >> 6;
    int i = n >> 3, j = n & 7;
    int hp = (wh * 8 + i + 4) & 255;
    int wp = (ww * 8 + j + 4) & 255;
    int gi = oc * 65536 + hp * 256 + wp;
    g_xres[gi] = sres[oc * 65 + n] + x[gi];
  }
}

// ---------------- K5: LN2 + ff_in (192->768) fp16 MMA ------------------------------
// dyn: sxn f32 [64*196] @0 (dies) | sxh h2 [64*100 uints] @50176B | sfl f32 [128*66] @0
__global__ void k5_ln_ffin(const float* __restrict__ ln2w, const float* __restrict__ ln2b) {
  extern __shared__ float sm5[];
  float* sxn = sm5;
  unsigned* sxh = (unsigned*)(sm5 + 12544);
  float* sfl = sm5;
  __shared__ float red[256], red2[256], smean[64], srstd[64];
  int blk = blockIdx.x;
  int h = blk >> 2;
  int w0 = (blk & 3) * 64;
  int pix0 = h * 256 + w0;
  int t = threadIdx.x;
  for (int idx = t; idx < 12288; idx += 256) {
    int c = idx >> 6, p = idx & 63;
    sxn[p * 196 + c] = g_xres[c * 65536 + pix0 + p];
  }
  __syncthreads();
  {
    int p = t & 63, g = t >> 6;
    float s = 0.f, s2v = 0.f;
    for (int c = g; c < 192; c += 4) { float v = sxn[p * 196 + c]; s += v; s2v += v * v; }
    red[t] = s;
    red2[t] = s2v;
  }
  __syncthreads();
  if (t < 64) {
    float s = red[t] + red[64 + t] + red[128 + t] + red[192 + t];
    float s2v = red2[t] + red2[64 + t] + red2[128 + t] + red2[192 + t];
    float m = s * (1.f / 192.f);
    float var = s2v * (1.f / 192.f) - m * m;
    smean[t] = m;
    srstd[t] = rsqrtf(var + 1e-5f);
  }
  __syncthreads();
  for (int idx = t; idx < 6144; idx += 256) {
    int p = idx / 96, kk = idx - p * 96;
    int c = kk * 2;
    float v0 = (sxn[p * 196 + c] - smean[p]) * srstd[p] * ln2w[c] + ln2b[c];
    float v1 = (sxn[p * 196 + c + 1] - smean[p]) * srstd[p] * ln2w[c + 1] + ln2b[c + 1];
    sxh[p * 100 + kk] = h2pk(v0, v1);
  }
  __syncthreads();
  int wa = t >> 5, lane = t & 31;
  int rq = lane >> 2, acol = lane & 3, ccol0 = 2 * acol;
  for (int ch = 0; ch < 6; ch++) {
    float acc[2][4][4];
#pragma unroll
    for (int j = 0; j < 2; j++)
#pragma unroll
      for (int mt = 0; mt < 4; mt++)
#pragma unroll
        for (int r = 0; r < 4; r++) acc[j][mt][r] = 0.f;
    for (int kit = 0; kit < 12; kit++) {
      unsigned A[4][4];
#pragma unroll
      for (int mt = 0; mt < 4; mt++) {
        int r = mt * 16 + rq;
        A[mt][0] = sxh[r * 100 + kit * 8 + acol];
        A[mt][1] = sxh[(r + 8) * 100 + kit * 8 + acol];
        A[mt][2] = sxh[r * 100 + kit * 8 + acol + 4];
        A[mt][3] = sxh[(r + 8) * 100 + kit * 8 + acol + 4];
      }
#pragma unroll
      for (int j = 0; j < 2; j++) {
        int nt = wa * 12 + ch * 2 + j;
        ull wv = g_wp_in[(nt * 12 + kit) * 32 + lane];
#pragma unroll
        for (int mt = 0; mt < 4; mt++)
          mma_f16(acc[j][mt], A[mt], (unsigned)wv, (unsigned)(wv >> 32));
      }
    }
#pragma unroll
    for (int j = 0; j < 2; j++) {
      int lc = (wa * 2 + j) * 8 + ccol0;
#pragma unroll
      for (int mt = 0; mt < 4; mt++) {
        int r0 = mt * 16 + rq;
        sfl[lc * 66 + r0] = acc[j][mt][0];
        sfl[(lc + 1) * 66 + r0] = acc[j][mt][1];
        sfl[lc * 66 + r0 + 8] = acc[j][mt][2];
        sfl[(lc + 1) * 66 + r0 + 8] = acc[j][mt][3];
      }
    }
    __syncthreads();
    for (int idx = t; idx < 4096; idx += 256) {
      int lc = idx >> 5, p2 = (idx & 31) * 2;
      int o = ((lc >> 4) * 12 + ch * 2 + ((lc >> 3) & 1)) * 8 + (lc & 7);
      *(__half2*)&g_hbh[(long)o * 65536 + pix0 + p2] =
          __floats2half2_rn(sfl[lc * 66 + p2], sfl[lc * 66 + p2 + 1]);
    }
    __syncthreads();
  }
}

// ---------------- K6: depthwise 3x3 + gelu(g1)*g2, fp16 I/O ------------------------
__global__ void k6_dw(const float* __restrict__ dw) {
  __shared__ float s0[10][258];
  __shared__ float s1[10][258];
  int h0 = blockIdx.x * 8;
  int c = blockIdx.y;
  int t = threadIdx.x;
  const __half* p0 = g_hbh + (long)c * 65536;
  const __half* p1 = g_hbh + (long)(c + 384) * 65536;
  for (int idx = t; idx < 10 * 258; idx += 256) {
    int r = idx / 258, cc = idx - r * 258;
    int hh = h0 - 1 + r, wp = cc - 1;
    float v0 = 0.f, v1 = 0.f;
    if (hh >= 0 && hh < 256 && wp >= 0 && wp < 256) {
      v0 = __half2float(p0[hh * 256 + wp]);
      v1 = __half2float(p1[hh * 256 + wp]);
    }
    s0[r][cc] = v0;
    s1[r][cc] = v1;
  }
  float f0r[9], f1r[9];
#pragma unroll
  for (int k = 0; k < 9; k++) { f0r[k] = dw[c * 9 + k]; f1r[k] = dw[(c + 384) * 9 + k]; }
  __syncthreads();
  int w = t;
#pragma unroll
  for (int r = 0; r < 8; r++) {
    float a = 0.f, b = 0.f;
#pragma unroll
    for (int dh = 0; dh < 3; dh++) {
#pragma unroll
      for (int dwi = 0; dwi < 3; dwi++) {
        a += s0[r + dh][w + dwi] * f0r[dh * 3 + dwi];
        b += s1[r + dh][w + dwi] * f1r[dh * 3 + dwi];
      }
    }
    g_gbh[(long)c * 65536 + (h0 + r) * 256 + w] = __float2half_rn(gelu_exact(a) * b);
  }
}

// ---------------- K7: ff_out (384->192) + residual, fp16 MMA -----------------------
// dyn: sA h2 [32*196 uints]; static sfl2 f32 [192*34]
__global__ void k7_ffout(float* __restrict__ out) {
  extern __shared__ unsigned sA[];
  __shared__ float sfl2[192 * 34];
  int blk = blockIdx.x;
  int h = blk >> 3;
  int w0 = (blk & 7) * 32;
  int pix0 = h * 256 + w0;
  int t = threadIdx.x;
  for (int idx = t; idx < 6144; idx += 256) {
    int p = idx & 31, kk = idx >> 5;
    int c = kk * 2;
    __half h0 = g_gbh[(long)c * 65536 + pix0 + p];
    __half h1 = g_gbh[(long)(c + 1) * 65536 + pix0 + p];
    __half2 hv = __halves2half2(h0, h1);
    sA[p * 196 + kk] = *(unsigned*)&hv;
  }
  __syncthreads();
  int wa = t >> 5, lane = t & 31;
  int rq = lane >> 2, acol = lane & 3, ccol0 = 2 * acol;
  float acc[3][2][4];
#pragma unroll
  for (int j = 0; j < 3; j++)
#pragma unroll
    for (int mt = 0; mt < 2; mt++)
#pragma unroll
      for (int r = 0; r < 4; r++) acc[j][mt][r] = 0.f;
  for (int kit = 0; kit < 24; kit++) {
    unsigned A[2][4];
#pragma unroll
    for (int mt = 0; mt < 2; mt++) {
      int r = mt * 16 + rq;
      A[mt][0] = sA[r * 196 + kit * 8 + acol];
      A[mt][1] = sA[(r + 8) * 196 + kit * 8 + acol];
      A[mt][2] = sA[r * 196 + kit * 8 + acol + 4];
      A[mt][3] = sA[(r + 8) * 196 + kit * 8 + acol + 4];
    }
#pragma unroll
    for (int j = 0; j < 3; j++) {
      ull wv = g_wp_out[((wa * 3 + j) * 24 + kit) * 32 + lane];
#pragma unroll
      for (int mt = 0; mt < 2; mt++)
        mma_f16(acc[j][mt], A[mt], (unsigned)wv, (unsigned)(wv >> 32));
    }
  }
#pragma unroll
  for (int j = 0; j < 3; j++) {
    int oc = (wa * 3 + j) * 8 + ccol0;
#pragma unroll
    for (int mt = 0; mt < 2; mt++) {
      int r0 = mt * 16 + rq;
      sfl2[oc * 34 + r0] = acc[j][mt][0];
      sfl2[(oc + 1) * 34 + r0] = acc[j][mt][1];
      sfl2[oc * 34 + r0 + 8] = acc[j][mt][2];
      sfl2[(oc + 1) * 34 + r0 + 8] = acc[j][mt][3];
    }
  }
  __syncthreads();
  for (int idx = t; idx < 6144; idx += 256) {
    int oc = idx >> 5, p = idx & 31;
    int gi = oc * 65536 + pix0 + p;
    out[gi] = g_xres[gi] + sfl2[oc * 34 + p];
  }
}

// ---------------- host launcher ----------------------------------------------------
extern "C" void kernel_launch(void* const* d_in, const int* in_sizes, int n_in,
                              void* d_out, int out_size) {
  const float* x    = (const float*)d_in[0];
  const float* ln1w = (const float*)d_in[1];
  const float* ln1b = (const float*)d_in[2];
  const float* ln2w = (const float*)d_in[3];
  const float* ln2b = (const float*)d_in[4];
  const float* wqkv = (const float*)d_in[5];
  const float* w11  = (const float*)d_in[6];
  const float* b11  = (const float*)d_in[7];
  const float* w12  = (const float*)d_in[8];
  const float* b12  = (const float*)d_in[9];
  const float* w2   = (const float*)d_in[10];
  const float* b2   = (const float*)d_in[11];
  const float* c11  = (const float*)d_in[12];
  const float* ffin = (const float*)d_in[13];
  const float* ffdw = (const float*)d_in[14];
  const float* ffou = (const float*)d_in[15];
  float* out = (float*)d_out;

  const int smem1 = 192 * 65 * 4;                 // 49920
  const int smem23 = 65536 + 64 * 100 * 4;        // 91136
  const int smem4 = 192 * 65 * 4;                 // 49920
  const int smem5 = 12544 * 4 + 64 * 100 * 4;     // 75776
  const int smem7 = 32 * 196 * 4;                 // 25088
  cudaFuncSetAttribute(k1_qkv, cudaFuncAttributeMaxDynamicSharedMemorySize, smem1);
  cudaFuncSetAttribute(k23_attn_geglu, cudaFuncAttributeMaxDynamicSharedMemorySize, smem23);
  cudaFuncSetAttribute(k4_conv11, cudaFuncAttributeMaxDynamicSharedMemorySize, smem4);
  cudaFuncSetAttribute(k5_ln_ffin, cudaFuncAttributeMaxDynamicSharedMemorySize, smem5);
  cudaFuncSetAttribute(k7_ffout, cudaFuncAttributeMaxDynamicSharedMemorySize, smem7);

  kpos<<<1, 64>>>();
  kpack<<<144, 256>>>(c11, ffin, ffou, w11, w12, w2, wqkv);
  k1_qkv<<<3072, 256, smem1>>>(x, ln1w, ln1b);
  {
    dim3 g23(1024, 3);
    k23_attn_geglu<<<g23, 256, smem23>>>(b11, b12, b2);
  }
  k4_conv11<<<1024, 256, smem4>>>(x);
  k5_ln_ffin<<<1024, 256, smem5>>>(ln2w, ln2b);
  {
    dim3 g6(32, 384);
    k6_dw<<<g6, 256>>>(ffdw);
  }
  k7_ffout<<<2048, 256, smem7>>>(out);
}

// round 7
// speedup vs baseline: 6.3994x; 1.0837x over previous
#include <cuda_runtime.h>
#include <cuda_fp16.h>
#include <math.h>

typedef unsigned long long ull;

// ---------------- fp16 MMA helpers -------------------------------------------------
__device__ __forceinline__ unsigned h2pk(float a, float b) {
  __half2 h = __floats2half2_rn(a, b);
  return *(unsigned*)&h;
}
__device__ __forceinline__ void mma_f16(float* c, const unsigned* a, unsigned b0, unsigned b1) {
  asm volatile(
      "mma.sync.aligned.m16n8k16.row.col.f32.f16.f16.f32 "
      "{%0,%1,%2,%3},{%4,%5,%6,%7},{%8,%9},{%0,%1,%2,%3};"
      : "+f"(c[0]), "+f"(c[1]), "+f"(c[2]), "+f"(c[3])
      : "r"(a[0]), "r"(a[1]), "r"(a[2]), "r"(a[3]), "r"(b0), "r"(b1));
}
__device__ __forceinline__ float gelu_exact(float a) {
  return 0.5f * a * (1.f + erff(a * 0.70710678118654752f));
}
// hi/lo fp16 split: hi = rn(x), lo = rn(x - float(hi))
__device__ __forceinline__ void hilo2(float x, float y, unsigned& hi, unsigned& lo) {
  __half hx = __float2half_rn(x), hy = __float2half_rn(y);
  __half2 h = __halves2half2(hx, hy);
  hi = *(unsigned*)&h;
  lo = h2pk(x - __half2float(hx), y - __half2float(hy));
}

// ---------------- static device scratch --------------------------------------------
__device__ float g_pos[64 * 64];
__device__ float g_q[3 * 1024 * 4 * 64 * 16];
__device__ float g_k[3 * 1024 * 4 * 64 * 16];
__device__ float g_v[3 * 1024 * 4 * 64 * 16];
__device__ __half g_yh[3 * 1024 * 4096];
__device__ float g_xres[192 * 65536];
__device__ __half g_hbh[768 * 65536];
__device__ __half g_gbh[384 * 65536];
// packed fp16 weight fragments: [ntile][kit16][lane] -> (b0 | b1<<32)
__device__ ull g_wp_in[96 * 12 * 32];     // ff_in  (K=192, N=768)
__device__ ull g_wp_out[24 * 24 * 32];    // ff_out (K=384, N=192)
__device__ ull g_wp11[3 * 8 * 12 * 32];   // me_w11 (K=192, N=64)
__device__ ull g_wp12[3 * 8 * 12 * 32];   // me_w12
__device__ ull g_wp2[3 * 8 * 4 * 32];     // me_w2  (K=64,  N=64)
__device__ ull g_wpqkv[24 * 4 * 32];      // w_qkv  (K=64,  N=192)
__device__ ull g_wp192[24 * 12 * 32];     // conv11 (K=192, N=192)

// ---------------- K0a: sine positional encoding ------------------------------------
__global__ void kpos() {
  int n = threadIdx.x;
  int i = n >> 3, j = n & 7;
  double scale = 6.283185307179586476925286766559;
  double yv = (double)(i + 1) / (8.0 + 1e-6) * scale;
  double xv = (double)(j + 1) / (8.0 + 1e-6) * scale;
  for (int c = 0; c < 64; c++) {
    double base = (c < 32) ? yv : xv;
    int k = (c < 32) ? c : (c - 32);
    double dt = pow(10000.0, (double)(k >> 1) / 16.0);
    double v = base / dt;
    g_pos[n * 64 + c] = (float)(((k & 1) == 0) ? sin(v) : cos(v));
  }
}

// ---------------- K0b: fp16 fragment packing ---------------------------------------
__global__ void kpack(const float* __restrict__ c11, const float* __restrict__ ffin,
                      const float* __restrict__ ffout, const float* __restrict__ w11,
                      const float* __restrict__ w12, const float* __restrict__ w2,
                      const float* __restrict__ wqkv) {
  int idx = blockIdx.x * 256 + threadIdx.x;
  int lane = idx & 31;
  if (idx < 36864) {  // wp_in [96][12][32], src [o=768][k=192]
    int kit = (idx >> 5) % 12, nt = idx / 384;
    int o = nt * 8 + (lane >> 2), k0 = kit * 16 + (lane & 3) * 2;
    unsigned b0 = h2pk(ffin[o * 192 + k0], ffin[o * 192 + k0 + 1]);
    unsigned b1 = h2pk(ffin[o * 192 + k0 + 8], ffin[o * 192 + k0 + 9]);
    g_wp_in[idx] = (ull)b0 | ((ull)b1 << 32);
  }
  if (idx < 18432) {  // wp_out [24][24][32], src [o=192][k=384]
    int kit = (idx >> 5) % 24, nt = idx / 768;
    int o = nt * 8 + (lane >> 2), k0 = kit * 16 + (lane & 3) * 2;
    unsigned b0 = h2pk(ffout[o * 384 + k0], ffout[o * 384 + k0 + 1]);
    unsigned b1 = h2pk(ffout[o * 384 + k0 + 8], ffout[o * 384 + k0 + 9]);
    g_wp_out[idx] = (ull)b0 | ((ull)b1 << 32);
  }
  if (idx < 9216) {  // wp11/wp12 [3][8][12][32], src [e][k=192][f=64]
    int e = idx / 3072, r = idx % 3072;
    int kit = (r >> 5) % 12, nt = r / 384;
    int f = nt * 8 + (lane >> 2), k0 = kit * 16 + (lane & 3) * 2;
    const float* Wa = w11 + e * 12288;
    const float* Wb = w12 + e * 12288;
    unsigned a0 = h2pk(Wa[k0 * 64 + f], Wa[(k0 + 1) * 64 + f]);
    unsigned a1 = h2pk(Wa[(k0 + 8) * 64 + f], Wa[(k0 + 9) * 64 + f]);
    g_wp11[idx] = (ull)a0 | ((ull)a1 << 32);
    unsigned c0 = h2pk(Wb[k0 * 64 + f], Wb[(k0 + 1) * 64 + f]);
    unsigned c1 = h2pk(Wb[(k0 + 8) * 64 + f], Wb[(k0 + 9) * 64 + f]);
    g_wp12[idx] = (ull)c0 | ((ull)c1 << 32);
  }
  if (idx < 3072) {  // wp2 [3][8][4][32], src [e][k=64][f=64]
    int e = idx / 1024, r = idx % 1024;
    int kit = (r >> 5) % 4, nt = r / 128;
    int f = nt * 8 + (lane >> 2), k0 = kit * 16 + (lane & 3) * 2;
    const float* Wa = w2 + e * 4096;
    unsigned b0 = h2pk(Wa[k0 * 64 + f], Wa[(k0 + 1) * 64 + f]);
    unsigned b1 = h2pk(Wa[(k0 + 8) * 64 + f], Wa[(k0 + 9) * 64 + f]);
    g_wp2[idx] = (ull)b0 | ((ull)b1 << 32);
  }
  if (idx < 3072) {  // wpqkv [24][4][32], src [k=64][n=192]
    int kit = (idx >> 5) % 4, nt = idx / 128;
    int n = nt * 8 + (lane >> 2), k0 = kit * 16 + (lane & 3) * 2;
    unsigned b0 = h2pk(wqkv[k0 * 192 + n], wqkv[(k0 + 1) * 192 + n]);
    unsigned b1 = h2pk(wqkv[(k0 + 8) * 192 + n], wqkv[(k0 + 9) * 192 + n]);
    g_wpqkv[idx] = (ull)b0 | ((ull)b1 << 32);
  }
  if (idx < 9216) {  // wp192 [24][12][32], src [o=192][k=192]
    int kit = (idx >> 5) % 12, nt = idx / 384;
    int o = nt * 8 + (lane >> 2), k0 = kit * 16 + (lane & 3) * 2;
    unsigned b0 = h2pk(c11[o * 192 + k0], c11[o * 192 + k0 + 1]);
    unsigned b1 = h2pk(c11[o * 192 + k0 + 8], c11[o * 192 + k0 + 9]);
    g_wp192[idx] = (ull)b0 | ((ull)b1 << 32);
  }
}

// ---------------- K1: shift+window + LN1 + pos + QKV GEMM (fp16 MMA) ---------------
__global__ void k1_qkv(const float* __restrict__ x, const float* __restrict__ ln1w,
                       const float* __restrict__ ln1b) {
  extern __shared__ float sm1[];
  float* sx = sm1;
  unsigned* snT = (unsigned*)(sm1 + 4160);
  float* sout = sm1;
  __shared__ float smean[64], srstd[64];
  int blk = blockIdx.x;
  int e = blk >> 10, wwin = blk & 1023;
  int wh = wwin >> 5, ww = wwin & 31;
  int t = threadIdx.x;
  for (int idx = t; idx < 4096; idx += 256) {
    int c = idx >> 6, n = idx & 63;
    int i = n >> 3, j = n & 7;
    int h0 = (wh * 8 + i + 4) & 255;
    int w0 = (ww * 8 + j + 4) & 255;
    sx[n * 65 + c] = x[((e * 64 + c) * 256 + h0) * 256 + w0];
  }
  __syncthreads();
  if (t < 64) {
    int n = t;
    float m = 0.f;
#pragma unroll
    for (int c = 0; c < 64; c++) m += sx[n * 65 + c];
    m *= (1.f / 64.f);
    float v = 0.f;
#pragma unroll
    for (int c = 0; c < 64; c++) { float d = sx[n * 65 + c] - m; v += d * d; }
    v *= (1.f / 64.f);
    smean[n] = m;
    srstd[n] = rsqrtf(v + 1e-5f);
  }
  __syncthreads();
  for (int idx = t; idx < 2048; idx += 256) {
    int n = idx >> 5, kk = idx & 31;
    int c = kk * 2;
    float v0 = (sx[n * 65 + c] - smean[n]) * srstd[n] * ln1w[c] + ln1b[c] + g_pos[n * 64 + c];
    float v1 = (sx[n * 65 + c + 1] - smean[n]) * srstd[n] * ln1w[c + 1] + ln1b[c + 1] + g_pos[n * 64 + c + 1];
    snT[n * 36 + kk] = h2pk(v0, v1);
  }
  __syncthreads();
  int wa = t >> 5, lane = t & 31;
  int rq = lane >> 2, acol = lane & 3, ccol0 = 2 * acol;
  float acc[3][4][4];
#pragma unroll
  for (int j = 0; j < 3; j++)
#pragma unroll
    for (int mt = 0; mt < 4; mt++)
#pragma unroll
      for (int r = 0; r < 4; r++) acc[j][mt][r] = 0.f;
  for (int kit = 0; kit < 4; kit++) {
    unsigned A[4][4];
#pragma unroll
    for (int mt = 0; mt < 4; mt++) {
      int r = mt * 16 + rq;
      A[mt][0] = snT[r * 36 + kit * 8 + acol];
      A[mt][1] = snT[(r + 8) * 36 + kit * 8 + acol];
      A[mt][2] = snT[r * 36 + kit * 8 + acol + 4];
      A[mt][3] = snT[(r + 8) * 36 + kit * 8 + acol + 4];
    }
#pragma unroll
    for (int j = 0; j < 3; j++) {
      ull wv = g_wpqkv[((wa * 3 + j) * 4 + kit) * 32 + lane];
#pragma unroll
      for (int mt = 0; mt < 4; mt++)
        mma_f16(acc[j][mt], A[mt], (unsigned)wv, (unsigned)(wv >> 32));
    }
  }
  __syncthreads();
#pragma unroll
  for (int j = 0; j < 3; j++) {
    int jc = (wa * 3 + j) * 8 + ccol0;
#pragma unroll
    for (int mt = 0; mt < 4; mt++) {
      int r0 = mt * 16 + rq;
      sout[jc * 65 + r0] = acc[j][mt][0];
      sout[(jc + 1) * 65 + r0] = acc[j][mt][1];
      sout[jc * 65 + r0 + 8] = acc[j][mt][2];
      sout[(jc + 1) * 65 + r0 + 8] = acc[j][mt][3];
    }
  }
  __syncthreads();
  long wb = (long)(e * 1024 + wwin);
  for (int idx = t; idx < 12288; idx += 256) {
    int ch = idx & 15, n = (idx >> 4) & 63, hh = (idx >> 10) & 3, p = idx >> 12;
    int jc = p * 64 + ch * 4 + hh;
    float vv = sout[jc * 65 + n];
    long qi = (wb * 4 + hh) * 1024 + n * 16 + ch;
    if (p == 0) g_q[qi] = vv;
    else if (p == 1) g_k[qi] = vv;
    else g_v[qi] = vv;
  }
}

// ---------------- K23: fused attention (fp16 MMA, hi/lo QK) + GEGLU ----------------
// dyn smem (uints): Vt [8 arrays][16 ch][36] @0 (4608) | sgin [64][100] @4608 (6400)
__device__ __forceinline__ ull maskw(int row, int wh, int ww) {
  ull m = 0ULL;
  if (wh == 31) m |= ((row >> 3) < 4) ? 0xFFFFFFFF00000000ULL : 0x00000000FFFFFFFFULL;
  if (ww == 31) m |= ((row & 7) < 4) ? 0xF0F0F0F0F0F0F0F0ULL : 0x0F0F0F0F0F0F0F0FULL;
  return m;
}

__global__ void __launch_bounds__(256, 2)
k23_attn_geglu(const float* __restrict__ b11, const float* __restrict__ b12,
               const float* __restrict__ b2) {
  extern __shared__ unsigned smu[];
  unsigned* Vt = smu;            // 4608 uints
  unsigned* sgin = smu + 4608;   // 6400 uints
  __shared__ unsigned stu[64 * 36];
  int w = blockIdx.x, e = blockIdx.y;
  const int ekvA_of[3] = {1, 0, 1};
  const int ekvB_of[3] = {2, 2, 0};
  long kbA = (long)(ekvA_of[e] * 1024 + w) * 4096;
  long kbB = (long)(ekvB_of[e] * 1024 + w) * 4096;
  long qb = (long)(e * 1024 + w) * 4096;
  int t = threadIdx.x;
  int wa = t >> 5, lane = t & 31;
  int rq = lane >> 2, acol = lane & 3;
  // --- cooperative: build Vt (fp16, [ch][key] transposed) ---
  for (int idx = t; idx < 2048; idx += 256) {
    int sh = idx >> 8;
    int n = (idx >> 2) & 63;
    int cq = idx & 3;
    long kb = ((sh >> 2) ? kbB : kbA) + (sh & 3) * 1024;
    float4 v = *(const float4*)&g_v[kb + n * 16 + cq * 4];
    __half* vt = (__half*)(Vt + sh * 576);
    vt[(cq * 4 + 0) * 72 + n] = __float2half_rn(v.x);
    vt[(cq * 4 + 1) * 72 + n] = __float2half_rn(v.y);
    vt[(cq * 4 + 2) * 72 + n] = __float2half_rn(v.z);
    vt[(cq * 4 + 3) * 72 + n] = __float2half_rn(v.w);
  }
  // --- cooperative: merged-q into sgin features [128,192) ---
  for (int idx = t; idx < 1024; idx += 256) {
    int n = idx >> 4, pr = idx & 15;
    int hh = pr >> 2, ch = (pr & 3) * 4;
    float4 qv = *(const float4*)&g_q[qb + hh * 1024 + n * 16 + ch];
    sgin[n * 100 + 64 + pr * 2] = h2pk(qv.x, qv.y);
    sgin[n * 100 + 64 + pr * 2 + 1] = h2pk(qv.z, qv.w);
  }
  __syncthreads();
  // --- attention: warp = (slot, head) ---
  {
    int slot = wa >> 2, hh = wa & 3;
    long kb = (slot ? kbB : kbA) + hh * 1024;
    long qhb = qb + hh * 1024;
    int wh = w >> 5, ww = w & 31;
    // K fragments hi/lo in registers (each warp: full 64x16 K of its head)
    unsigned Kfh[8][2], Kfl[8][2];
#pragma unroll
    for (int nt = 0; nt < 8; nt++) {
      int row = nt * 8 + rq;
      float2 k0 = *(const float2*)&g_k[kb + row * 16 + 2 * acol];
      float2 k1 = *(const float2*)&g_k[kb + row * 16 + 8 + 2 * acol];
      hilo2(k0.x, k0.y, Kfh[nt][0], Kfl[nt][0]);
      hilo2(k1.x, k1.y, Kfh[nt][1], Kfl[nt][1]);
    }
    const unsigned* vtw = Vt + (slot * 4 + hh) * 576;
#pragma unroll
    for (int mt = 0; mt < 4; mt++) {
      int r0 = mt * 16 + rq;
      // Q fragments hi/lo
      unsigned Ah[4], Al[4];
      {
        float2 q0 = *(const float2*)&g_q[qhb + r0 * 16 + 2 * acol];
        float2 q1 = *(const float2*)&g_q[qhb + (r0 + 8) * 16 + 2 * acol];
        float2 q2 = *(const float2*)&g_q[qhb + r0 * 16 + 8 + 2 * acol];
        float2 q3 = *(const float2*)&g_q[qhb + (r0 + 8) * 16 + 8 + 2 * acol];
        hilo2(q0.x, q0.y, Ah[0], Al[0]);
        hilo2(q1.x, q1.y, Ah[1], Al[1]);
        hilo2(q2.x, q2.y, Ah[2], Al[2]);
        hilo2(q3.x, q3.y, Ah[3], Al[3]);
      }
      // S = (qh+ql)(kh+kl) ~ qh kh + qh kl + ql kh
      float sc[8][4];
#pragma unroll
      for (int nt = 0; nt < 8; nt++) {
#pragma unroll
        for (int r = 0; r < 4; r++) sc[nt][r] = 0.f;
        mma_f16(sc[nt], Ah, Kfh[nt][0], Kfh[nt][1]);
        mma_f16(sc[nt], Ah, Kfl[nt][0], Kfl[nt][1]);
        mma_f16(sc[nt], Al, Kfh[nt][0], Kfh[nt][1]);
      }
      // softmax (single pass, no max; masked -> exactly 0)
      ull m0 = maskw(r0, wh, ww);
      ull m1 = maskw(r0 + 8, wh, ww);
      float sum0 = 0.f, sum1 = 0.f;
      unsigned Pf[4][4];
#pragma unroll
      for (int nt = 0; nt < 8; nt++) {
        int c0 = nt * 8 + 2 * acol;
        float p0 = ((m0 >> c0) & 1) ? 0.f : __expf(sc[nt][0] * 0.125f);
        float p1 = ((m0 >> (c0 + 1)) & 1) ? 0.f : __expf(sc[nt][1] * 0.125f);
        float p2 = ((m1 >> c0) & 1) ? 0.f : __expf(sc[nt][2] * 0.125f);
        float p3 = ((m1 >> (c0 + 1)) & 1) ? 0.f : __expf(sc[nt][3] * 0.125f);
        sum0 += p0 + p1;
        sum1 += p2 + p3;
        Pf[nt >> 1][(nt & 1) ? 2 : 0] = h2pk(p0, p1);
        Pf[nt >> 1][(nt & 1) ? 3 : 1] = h2pk(p2, p3);
      }
      sum0 += __shfl_xor_sync(0xFFFFFFFFu, sum0, 1);
      sum0 += __shfl_xor_sync(0xFFFFFFFFu, sum0, 2);
      sum1 += __shfl_xor_sync(0xFFFFFFFFu, sum1, 1);
      sum1 += __shfl_xor_sync(0xFFFFFFFFu, sum1, 2);
      float inv0 = 1.f / sum0, inv1 = 1.f / sum1;
      // O = P V
      float oc[2][4];
#pragma unroll
      for (int n2 = 0; n2 < 2; n2++)
#pragma unroll
        for (int r = 0; r < 4; r++) oc[n2][r] = 0.f;
#pragma unroll
      for (int kit = 0; kit < 4; kit++) {
#pragma unroll
        for (int n2 = 0; n2 < 2; n2++) {
          unsigned b0 = vtw[(n2 * 8 + rq) * 36 + kit * 8 + acol];
          unsigned b1 = vtw[(n2 * 8 + rq) * 36 + kit * 8 + 4 + acol];
          mma_f16(oc[n2], Pf[kit], b0, b1);
        }
      }
      // write normalized O (fp16) into sgin
#pragma unroll
      for (int n2 = 0; n2 < 2; n2++) {
        int fb = slot * 32 + hh * 8 + n2 * 4 + acol;
        sgin[r0 * 100 + fb] = h2pk(oc[n2][0] * inv0, oc[n2][1] * inv0);
        sgin[(r0 + 8) * 100 + fb] = h2pk(oc[n2][2] * inv1, oc[n2][3] * inv1);
      }
    }
  }
  __syncthreads();
  // ---- GEGLU GEMM1 ----
  float a1[4][4], g1[4][4];
  {
    int o = wa * 8 + 2 * acol;
    float ba0 = b11[e * 64 + o], ba1 = b11[e * 64 + o + 1];
    float bg0 = b12[e * 64 + o], bg1 = b12[e * 64 + o + 1];
#pragma unroll
    for (int mt = 0; mt < 4; mt++) {
      a1[mt][0] = ba0; a1[mt][1] = ba1; a1[mt][2] = ba0; a1[mt][3] = ba1;
      g1[mt][0] = bg0; g1[mt][1] = bg1; g1[mt][2] = bg0; g1[mt][3] = bg1;
    }
  }
  const ull* W11 = g_wp11 + e * 3072 + wa * 12 * 32;
  const ull* W12 = g_wp12 + e * 3072 + wa * 12 * 32;
  for (int kit = 0; kit < 12; kit++) {
    unsigned A[4][4];
#pragma unroll
    for (int mt = 0; mt < 4; mt++) {
      int r = mt * 16 + rq;
      A[mt][0] = sgin[r * 100 + kit * 8 + acol];
      A[mt][1] = sgin[(r + 8) * 100 + kit * 8 + acol];
      A[mt][2] = sgin[r * 100 + kit * 8 + acol + 4];
      A[mt][3] = sgin[(r + 8) * 100 + kit * 8 + acol + 4];
    }
    ull wv1 = W11[kit * 32 + lane];
    ull wv2 = W12[kit * 32 + lane];
#pragma unroll
    for (int mt = 0; mt < 4; mt++) {
      mma_f16(a1[mt], A[mt], (unsigned)wv1, (unsigned)(wv1 >> 32));
      mma_f16(g1[mt], A[mt], (unsigned)wv2, (unsigned)(wv2 >> 32));
    }
  }
#pragma unroll
  for (int mt = 0; mt < 4; mt++) {
    int r0 = mt * 16 + rq;
    stu[r0 * 36 + wa * 4 + acol] = h2pk(gelu_exact(a1[mt][0]) * g1[mt][0],
                                        gelu_exact(a1[mt][1]) * g1[mt][1]);
    stu[(r0 + 8) * 36 + wa * 4 + acol] = h2pk(gelu_exact(a1[mt][2]) * g1[mt][2],
                                              gelu_exact(a1[mt][3]) * g1[mt][3]);
  }
  __syncthreads();
  // ---- GEGLU GEMM2 ----
  float y2[4][4];
  {
    int o = wa * 8 + 2 * acol;
    float b0 = b2[e * 64 + o], b1v = b2[e * 64 + o + 1];
#pragma unroll
    for (int mt = 0; mt < 4; mt++) {
      y2[mt][0] = b0; y2[mt][1] = b1v; y2[mt][2] = b0; y2[mt][3] = b1v;
    }
  }
  const ull* W2 = g_wp2 + e * 1024 + wa * 4 * 32;
  for (int kit = 0; kit < 4; kit++) {
    unsigned A[4][4];
#pragma unroll
    for (int mt = 0; mt < 4; mt++) {
      int r = mt * 16 + rq;
      A[mt][0] = stu[r * 36 + kit * 8 + acol];
      A[mt][1] = stu[(r + 8) * 36 + kit * 8 + acol];
      A[mt][2] = stu[r * 36 + kit * 8 + acol + 4];
      A[mt][3] = stu[(r + 8) * 36 + kit * 8 + acol + 4];
    }
    ull wv = W2[kit * 32 + lane];
#pragma unroll
    for (int mt = 0; mt < 4; mt++)
      mma_f16(y2[mt], A[mt], (unsigned)wv, (unsigned)(wv >> 32));
  }
  // stage y (h2) into sgin region (dead now)
  unsigned* yst = sgin;
#pragma unroll
  for (int mt = 0; mt < 4; mt++) {
    int r0 = mt * 16 + rq;
    yst[r0 * 36 + wa * 4 + acol] = h2pk(y2[mt][0], y2[mt][1]);
    yst[(r0 + 8) * 36 + wa * 4 + acol] = h2pk(y2[mt][2], y2[mt][3]);
  }
  __syncthreads();
  long ybase = (long)(e * 1024 + w) * 4096;
  for (int idx = t; idx < 2048; idx += 256) {
    int n = idx >> 5, kk = idx & 31;
    *(__half2*)&g_yh[ybase + n * 64 + kk * 2] = *(__half2*)&yst[n * 36 + kk];
  }
}

// ---------------- K4: window reverse + conv1x1 + roll + residual (fp16 MMA) --------
__global__ void k4_conv11(const float* __restrict__ x) {
  extern __shared__ float sm4[];
  unsigned* sa = (unsigned*)sm4;
  float* sres = sm4;
  int wwin = blockIdx.x;
  int wh = wwin >> 5, ww = wwin & 31;
  int t = threadIdx.x;
  for (int idx = t; idx < 6144; idx += 256) {
    int n = idx / 96, kk = idx - n * 96;
    int c = kk * 2;
    int e = c >> 6, f = c & 63;
    sa[n * 100 + kk] = *(const unsigned*)&g_yh[(long)(e * 1024 + wwin) * 4096 + n * 64 + f];
  }
  __syncthreads();
  int wa = t >> 5, lane = t & 31;
  int rq = lane >> 2, acol = lane & 3, ccol0 = 2 * acol;
  float acc[3][4][4];
#pragma unroll
  for (int j = 0; j < 3; j++)
#pragma unroll
    for (int mt = 0; mt < 4; mt++)
#pragma unroll
      for (int r = 0; r < 4; r++) acc[j][mt][r] = 0.f;
  for (int kit = 0; kit < 12; kit++) {
    unsigned A[4][4];
#pragma unroll
    for (int mt = 0; mt < 4; mt++) {
      int r = mt * 16 + rq;
      A[mt][0] = sa[r * 100 + kit * 8 + acol];
      A[mt][1] = sa[(r + 8) * 100 + kit * 8 + acol];
      A[mt][2] = sa[r * 100 + kit * 8 + acol + 4];
      A[mt][3] = sa[(r + 8) * 100 + kit * 8 + acol + 4];
    }
#pragma unroll
    for (int j = 0; j < 3; j++) {
      ull wv = g_wp192[((wa * 3 + j) * 12 + kit) * 32 + lane];
#pragma unroll
      for (int mt = 0; mt < 4; mt++)
        mma_f16(acc[j][mt], A[mt], (unsigned)wv, (unsigned)(wv >> 32));
    }
  }
  __syncthreads();
#pragma unroll
  for (int j = 0; j < 3; j++) {
    int oc = (wa * 3 + j) * 8 + ccol0;
#pragma unroll
    for (int mt = 0; mt < 4; mt++) {
      int r0 = mt * 16 + rq;
      sres[oc * 65 + r0] = acc[j][mt][0];
      sres[(oc + 1) * 65 + r0] = acc[j][mt][1];
      sres[oc * 65 + r0 + 8] = acc[j][mt][2];
      sres[(oc + 1) * 65 + r0 + 8] = acc[j][mt][3];
    }
  }
  __syncthreads();
  for (int idx = t; idx < 12288; idx += 256) {
    int n = idx & 63, oc = idx >> 6;
    int i = n >> 3, j = n & 7;
    int hp = (wh * 8 + i + 4) & 255;
    int wp = (ww * 8 + j + 4) & 255;
    int gi = oc * 65536 + hp * 256 + wp;
    g_xres[gi] = sres[oc * 65 + n] + x[gi];
  }
}

// ---------------- K5: LN2 + ff_in (192->768) fp16 MMA ------------------------------
__global__ void k5_ln_ffin(const float* __restrict__ ln2w, const float* __restrict__ ln2b) {
  extern __shared__ float sm5[];
  float* sxn = sm5;
  unsigned* sxh = (unsigned*)(sm5 + 12544);
  float* sfl = sm5;
  __shared__ float red[256], red2[256], smean[64], srstd[64];
  int blk = blockIdx.x;
  int h = blk >> 2;
  int w0 = (blk & 3) * 64;
  int pix0 = h * 256 + w0;
  int t = threadIdx.x;
  for (int idx = t; idx < 12288; idx += 256) {
    int c = idx >> 6, p = idx & 63;
    sxn[p * 196 + c] = g_xres[c * 65536 + pix0 + p];
  }
  __syncthreads();
  {
    int p = t & 63, g = t >> 6;
    float s = 0.f, s2v = 0.f;
    for (int c = g; c < 192; c += 4) { float v = sxn[p * 196 + c]; s += v; s2v += v * v; }
    red[t] = s;
    red2[t] = s2v;
  }
  __syncthreads();
  if (t < 64) {
    float s = red[t] + red[64 + t] + red[128 + t] + red[192 + t];
    float s2v = red2[t] + red2[64 + t] + red2[128 + t] + red2[192 + t];
    float m = s * (1.f / 192.f);
    float var = s2v * (1.f / 192.f) - m * m;
    smean[t] = m;
    srstd[t] = rsqrtf(var + 1e-5f);
  }
  __syncthreads();
  for (int idx = t; idx < 6144; idx += 256) {
    int p = idx / 96, kk = idx - p * 96;
    int c = kk * 2;
    float v0 = (sxn[p * 196 + c] - smean[p]) * srstd[p] * ln2w[c] + ln2b[c];
    float v1 = (sxn[p * 196 + c + 1] - smean[p]) * srstd[p] * ln2w[c + 1] + ln2b[c + 1];
    sxh[p * 100 + kk] = h2pk(v0, v1);
  }
  __syncthreads();
  int wa = t >> 5, lane = t & 31;
  int rq = lane >> 2, acol = lane & 3, ccol0 = 2 * acol;
  for (int ch = 0; ch < 6; ch++) {
    float acc[2][4][4];
#pragma unroll
    for (int j = 0; j < 2; j++)
#pragma unroll
      for (int mt = 0; mt < 4; mt++)
#pragma unroll
        for (int r = 0; r < 4; r++) acc[j][mt][r] = 0.f;
    for (int kit = 0; kit < 12; kit++) {
      unsigned A[4][4];
#pragma unroll
      for (int mt = 0; mt < 4; mt++) {
        int r = mt * 16 + rq;
        A[mt][0] = sxh[r * 100 + kit * 8 + acol];
        A[mt][1] = sxh[(r + 8) * 100 + kit * 8 + acol];
        A[mt][2] = sxh[r * 100 + kit * 8 + acol + 4];
        A[mt][3] = sxh[(r + 8) * 100 + kit * 8 + acol + 4];
      }
#pragma unroll
      for (int j = 0; j < 2; j++) {
        int nt = wa * 12 + ch * 2 + j;
        ull wv = g_wp_in[(nt * 12 + kit) * 32 + lane];
#pragma unroll
        for (int mt = 0; mt < 4; mt++)
          mma_f16(acc[j][mt], A[mt], (unsigned)wv, (unsigned)(wv >> 32));
      }
    }
#pragma unroll
    for (int j = 0; j < 2; j++) {
      int lc = (wa * 2 + j) * 8 + ccol0;
#pragma unroll
      for (int mt = 0; mt < 4; mt++) {
        int r0 = mt * 16 + rq;
        sfl[lc * 66 + r0] = acc[j][mt][0];
        sfl[(lc + 1) * 66 + r0] = acc[j][mt][1];
        sfl[lc * 66 + r0 + 8] = acc[j][mt][2];
        sfl[(lc + 1) * 66 + r0 + 8] = acc[j][mt][3];
      }
    }
    __syncthreads();
    for (int idx = t; idx < 4096; idx += 256) {
      int lc = idx >> 5, p2 = (idx & 31) * 2;
      int o = ((lc >> 4) * 12 + ch * 2 + ((lc >> 3) & 1)) * 8 + (lc & 7);
      *(__half2*)&g_hbh[(long)o * 65536 + pix0 + p2] =
          __floats2half2_rn(sfl[lc * 66 + p2], sfl[lc * 66 + p2 + 1]);
    }
    __syncthreads();
  }
}

// ---------------- K6: depthwise 3x3 + gelu(g1)*g2, 16 rows/block, half2 ------------
__global__ void k6_dw(const float* __restrict__ dw) {
  __shared__ float s0[18][264];
  __shared__ float s1[18][264];
  int h0 = blockIdx.x * 16;
  int c = blockIdx.y;
  int t = threadIdx.x;
  const __half* p0 = g_hbh + (long)c * 65536;
  const __half* p1 = g_hbh + (long)(c + 384) * 65536;
  for (int idx = t; idx < 18 * 128; idx += 256) {
    int r = idx >> 7, cc = idx & 127;
    int hh = h0 - 1 + r;
    float2 v0 = make_float2(0.f, 0.f), v1 = make_float2(0.f, 0.f);
    if (hh >= 0 && hh < 256) {
      v0 = __half22float2(*(const __half2*)&p0[hh * 256 + cc * 2]);
      v1 = __half22float2(*(const __half2*)&p1[hh * 256 + cc * 2]);
    }
    s0[r][1 + 2 * cc] = v0.x;
    s0[r][2 + 2 * cc] = v0.y;
    s1[r][1 + 2 * cc] = v1.x;
    s1[r][2 + 2 * cc] = v1.y;
  }
  if (t < 18) { s0[t][0] = 0.f; s0[t][257] = 0.f; s1[t][0] = 0.f; s1[t][257] = 0.f; }
  float f0r[9], f1r[9];
#pragma unroll
  for (int k = 0; k < 9; k++) { f0r[k] = dw[c * 9 + k]; f1r[k] = dw[(c + 384) * 9 + k]; }
  __syncthreads();
  int cp = (t & 127) * 2;      // column pair
  int rg = t >> 7;             // row group 0/1 -> rows rg*8 .. rg*8+8
#pragma unroll
  for (int r = 0; r < 8; r++) {
    int row = rg * 8 + r;
    float a0 = 0.f, b0 = 0.f, a1 = 0.f, b1 = 0.f;
#pragma unroll
    for (int dh = 0; dh < 3; dh++) {
#pragma unroll
      for (int dwi = 0; dwi < 3; dwi++) {
        float w = f0r[dh * 3 + dwi];
        float wv = f1r[dh * 3 + dwi];
        a0 += s0[row + dh][cp + dwi] * w;
        a1 += s0[row + dh][cp + 1 + dwi] * w;
        b0 += s1[row + dh][cp + dwi] * wv;
        b1 += s1[row + dh][cp + 1 + dwi] * wv;
      }
    }
    float o0 = gelu_exact(a0) * b0;
    float o1 = gelu_exact(a1) * b1;
    *(__half2*)&g_gbh[(long)c * 65536 + (h0 + row) * 256 + cp] = __floats2half2_rn(o0, o1);
  }
}

// ---------------- K7: ff_out (384->192) + residual, fp16 MMA -----------------------
__global__ void k7_ffout(float* __restrict__ out) {
  extern __shared__ unsigned sA[];
  __shared__ float sfl2[192 * 34];
  int blk = blockIdx.x;
  int h = blk >> 3;
  int w0 = (blk & 7) * 32;
  int pix0 = h * 256 + w0;
  int t = threadIdx.x;
  for (int idx = t; idx < 6144; idx += 256) {
    int p = idx & 31, kk = idx >> 5;
    int c = kk * 2;
    __half h0 = g_gbh[(long)c * 65536 + pix0 + p];
    __half h1 = g_gbh[(long)(c + 1) * 65536 + pix0 + p];
    __half2 hv = __halves2half2(h0, h1);
    sA[p * 196 + kk] = *(unsigned*)&hv;
  }
  __syncthreads();
  int wa = t >> 5, lane = t & 31;
  int rq = lane >> 2, acol = lane & 3, ccol0 = 2 * acol;
  float acc[3][2][4];
#pragma unroll
  for (int j = 0; j < 3; j++)
#pragma unroll
    for (int mt = 0; mt < 2; mt++)
#pragma unroll
      for (int r = 0; r < 4; r++) acc[j][mt][r] = 0.f;
  for (int kit = 0; kit < 24; kit++) {
    unsigned A[2][4];
#pragma unroll
    for (int mt = 0; mt < 2; mt++) {
      int r = mt * 16 + rq;
      A[mt][0] = sA[r * 196 + kit * 8 + acol];
      A[mt][1] = sA[(r + 8) * 196 + kit * 8 + acol];
      A[mt][2] = sA[r * 196 + kit * 8 + acol + 4];
      A[mt][3] = sA[(r + 8) * 196 + kit * 8 + acol + 4];
    }
#pragma unroll
    for (int j = 0; j < 3; j++) {
      ull wv = g_wp_out[((wa * 3 + j) * 24 + kit) * 32 + lane];
#pragma unroll
      for (int mt = 0; mt < 2; mt++)
        mma_f16(acc[j][mt], A[mt], (unsigned)wv, (unsigned)(wv >> 32));
    }
  }
#pragma unroll
  for (int j = 0; j < 3; j++) {
    int oc = (wa * 3 + j) * 8 + ccol0;
#pragma unroll
    for (int mt = 0; mt < 2; mt++) {
      int r0 = mt * 16 + rq;
      sfl2[oc * 34 + r0] = acc[j][mt][0];
      sfl2[(oc + 1) * 34 + r0] = acc[j][mt][1];
      sfl2[oc * 34 + r0 + 8] = acc[j][mt][2];
      sfl2[(oc + 1) * 34 + r0 + 8] = acc[j][mt][3];
    }
  }
  __syncthreads();
  for (int idx = t; idx < 6144; idx += 256) {
    int oc = idx >> 5, p = idx & 31;
    int gi = oc * 65536 + pix0 + p;
    out[gi] = g_xres[gi] + sfl2[oc * 34 + p];
  }
}

// ---------------- host launcher ----------------------------------------------------
extern "C" void kernel_launch(void* const* d_in, const int* in_sizes, int n_in,
                              void* d_out, int out_size) {
  const float* x    = (const float*)d_in[0];
  const float* ln1w = (const float*)d_in[1];
  const float* ln1b = (const float*)d_in[2];
  const float* ln2w = (const float*)d_in[3];
  const float* ln2b = (const float*)d_in[4];
  const float* wqkv = (const float*)d_in[5];
  const float* w11  = (const float*)d_in[6];
  const float* b11  = (const float*)d_in[7];
  const float* w12  = (const float*)d_in[8];
  const float* b12  = (const float*)d_in[9];
  const float* w2   = (const float*)d_in[10];
  const float* b2   = (const float*)d_in[11];
  const float* c11  = (const float*)d_in[12];
  const float* ffin = (const float*)d_in[13];
  const float* ffdw = (const float*)d_in[14];
  const float* ffou = (const float*)d_in[15];
  float* out = (float*)d_out;

  const int smem1 = 192 * 65 * 4;                 // 49920
  const int smem23 = (4608 + 6400) * 4;           // 44032
  const int smem4 = 192 * 65 * 4;                 // 49920
  const int smem5 = 12544 * 4 + 64 * 100 * 4;     // 75776
  const int smem7 = 32 * 196 * 4;                 // 25088
  cudaFuncSetAttribute(k1_qkv, cudaFuncAttributeMaxDynamicSharedMemorySize, smem1);
  cudaFuncSetAttribute(k23_attn_geglu, cudaFuncAttributeMaxDynamicSharedMemorySize, smem23);
  cudaFuncSetAttribute(k4_conv11, cudaFuncAttributeMaxDynamicSharedMemorySize, smem4);
  cudaFuncSetAttribute(k5_ln_ffin, cudaFuncAttributeMaxDynamicSharedMemorySize, smem5);
  cudaFuncSetAttribute(k7_ffout, cudaFuncAttributeMaxDynamicSharedMemorySize, smem7);

  kpos<<<1, 64>>>();
  kpack<<<144, 256>>>(c11, ffin, ffou, w11, w12, w2, wqkv);
  k1_qkv<<<3072, 256, smem1>>>(x, ln1w, ln1b);
  {
    dim3 g23(1024, 3);
    k23_attn_geglu<<<g23, 256, smem23>>>(b11, b12, b2);
  }
  k4_conv11<<<1024, 256, smem4>>>(x);
  k5_ln_ffin<<<1024, 256, smem5>>>(ln2w, ln2b);
  {
    dim3 g6(16, 384);
    k6_dw<<<g6, 256>>>(ffdw);
  }
  k7_ffout<<<2048, 256, smem7>>>(out);
}

// round 8
// speedup vs baseline: 6.5596x; 1.0250x over previous
#include <cuda_runtime.h>
#include <cuda_fp16.h>
#include <math.h>

typedef unsigned long long ull;

// ---------------- fp16 MMA helpers -------------------------------------------------
__device__ __forceinline__ unsigned h2pk(float a, float b) {
  __half2 h = __floats2half2_rn(a, b);
  return *(unsigned*)&h;
}
__device__ __forceinline__ void mma_f16(float* c, const unsigned* a, unsigned b0, unsigned b1) {
  asm volatile(
      "mma.sync.aligned.m16n8k16.row.col.f32.f16.f16.f32 "
      "{%0,%1,%2,%3},{%4,%5,%6,%7},{%8,%9},{%0,%1,%2,%3};"
      : "+f"(c[0]), "+f"(c[1]), "+f"(c[2]), "+f"(c[3])
      : "r"(a[0]), "r"(a[1]), "r"(a[2]), "r"(a[3]), "r"(b0), "r"(b1));
}
__device__ __forceinline__ float gelu_exact(float a) {
  return 0.5f * a * (1.f + erff(a * 0.70710678118654752f));
}

// ---------------- static device scratch --------------------------------------------
__device__ float g_pos[64 * 64];
// q/k stored as fp16 hi/lo split; v stored fp16 transposed [head][ch][key]
__device__ __half g_qh[3 * 1024 * 4096];
__device__ __half g_ql[3 * 1024 * 4096];
__device__ __half g_kh[3 * 1024 * 4096];
__device__ __half g_kl[3 * 1024 * 4096];
__device__ __half g_vt[3 * 1024 * 4096];
__device__ __half g_yh[3 * 1024 * 4096];
__device__ float g_xres[192 * 65536];
__device__ __half g_hbh[768 * 65536];
__device__ __half g_gbh[384 * 65536];
// packed fp16 weight fragments: [ntile][kit16][lane] -> (b0 | b1<<32)
__device__ ull g_wp_in[96 * 12 * 32];     // ff_in  (K=192, N=768)
__device__ ull g_wp_out[24 * 24 * 32];    // ff_out (K=384, N=192)
__device__ ull g_wp11[3 * 8 * 12 * 32];   // me_w11 (K=192, N=64)
__device__ ull g_wp12[3 * 8 * 12 * 32];   // me_w12
__device__ ull g_wp2[3 * 8 * 4 * 32];     // me_w2  (K=64,  N=64)
__device__ ull g_wpqkv[24 * 4 * 32];      // w_qkv  (K=64,  N=192)
__device__ ull g_wp192[24 * 12 * 32];     // conv11 (K=192, N=192)

// ---------------- K0a: sine positional encoding ------------------------------------
__global__ void kpos() {
  int n = threadIdx.x;
  int i = n >> 3, j = n & 7;
  double scale = 6.283185307179586476925286766559;
  double yv = (double)(i + 1) / (8.0 + 1e-6) * scale;
  double xv = (double)(j + 1) / (8.0 + 1e-6) * scale;
  for (int c = 0; c < 64; c++) {
    double base = (c < 32) ? yv : xv;
    int k = (c < 32) ? c : (c - 32);
    double dt = pow(10000.0, (double)(k >> 1) / 16.0);
    double v = base / dt;
    g_pos[n * 64 + c] = (float)(((k & 1) == 0) ? sin(v) : cos(v));
  }
}

// ---------------- K0b: fp16 fragment packing ---------------------------------------
__global__ void kpack(const float* __restrict__ c11, const float* __restrict__ ffin,
                      const float* __restrict__ ffout, const float* __restrict__ w11,
                      const float* __restrict__ w12, const float* __restrict__ w2,
                      const float* __restrict__ wqkv) {
  int idx = blockIdx.x * 256 + threadIdx.x;
  int lane = idx & 31;
  if (idx < 36864) {  // wp_in [96][12][32], src [o=768][k=192]
    int kit = (idx >> 5) % 12, nt = idx / 384;
    int o = nt * 8 + (lane >> 2), k0 = kit * 16 + (lane & 3) * 2;
    unsigned b0 = h2pk(ffin[o * 192 + k0], ffin[o * 192 + k0 + 1]);
    unsigned b1 = h2pk(ffin[o * 192 + k0 + 8], ffin[o * 192 + k0 + 9]);
    g_wp_in[idx] = (ull)b0 | ((ull)b1 << 32);
  }
  if (idx < 18432) {  // wp_out [24][24][32], src [o=192][k=384]
    int kit = (idx >> 5) % 24, nt = idx / 768;
    int o = nt * 8 + (lane >> 2), k0 = kit * 16 + (lane & 3) * 2;
    unsigned b0 = h2pk(ffout[o * 384 + k0], ffout[o * 384 + k0 + 1]);
    unsigned b1 = h2pk(ffout[o * 384 + k0 + 8], ffout[o * 384 + k0 + 9]);
    g_wp_out[idx] = (ull)b0 | ((ull)b1 << 32);
  }
  if (idx < 9216) {  // wp11/wp12 [3][8][12][32], src [e][k=192][f=64]
    int e = idx / 3072, r = idx % 3072;
    int kit = (r >> 5) % 12, nt = r / 384;
    int f = nt * 8 + (lane >> 2), k0 = kit * 16 + (lane & 3) * 2;
    const float* Wa = w11 + e * 12288;
    const float* Wb = w12 + e * 12288;
    unsigned a0 = h2pk(Wa[k0 * 64 + f], Wa[(k0 + 1) * 64 + f]);
    unsigned a1 = h2pk(Wa[(k0 + 8) * 64 + f], Wa[(k0 + 9) * 64 + f]);
    g_wp11[idx] = (ull)a0 | ((ull)a1 << 32);
    unsigned c0 = h2pk(Wb[k0 * 64 + f], Wb[(k0 + 1) * 64 + f]);
    unsigned c1 = h2pk(Wb[(k0 + 8) * 64 + f], Wb[(k0 + 9) * 64 + f]);
    g_wp12[idx] = (ull)c0 | ((ull)c1 << 32);
  }
  if (idx < 3072) {  // wp2 [3][8][4][32], src [e][k=64][f=64]
    int e = idx / 1024, r = idx % 1024;
    int kit = (r >> 5) % 4, nt = r / 128;
    int f = nt * 8 + (lane >> 2), k0 = kit * 16 + (lane & 3) * 2;
    const float* Wa = w2 + e * 4096;
    unsigned b0 = h2pk(Wa[k0 * 64 + f], Wa[(k0 + 1) * 64 + f]);
    unsigned b1 = h2pk(Wa[(k0 + 8) * 64 + f], Wa[(k0 + 9) * 64 + f]);
    g_wp2[idx] = (ull)b0 | ((ull)b1 << 32);
  }
  if (idx < 3072) {  // wpqkv [24][4][32], src [k=64][n=192]
    int kit = (idx >> 5) % 4, nt = idx / 128;
    int n = nt * 8 + (lane >> 2), k0 = kit * 16 + (lane & 3) * 2;
    unsigned b0 = h2pk(wqkv[k0 * 192 + n], wqkv[(k0 + 1) * 192 + n]);
    unsigned b1 = h2pk(wqkv[(k0 + 8) * 192 + n], wqkv[(k0 + 9) * 192 + n]);
    g_wpqkv[idx] = (ull)b0 | ((ull)b1 << 32);
  }
  if (idx < 9216) {  // wp192 [24][12][32], src [o=192][k=192]
    int kit = (idx >> 5) % 12, nt = idx / 384;
    int o = nt * 8 + (lane >> 2), k0 = kit * 16 + (lane & 3) * 2;
    unsigned b0 = h2pk(c11[o * 192 + k0], c11[o * 192 + k0 + 1]);
    unsigned b1 = h2pk(c11[o * 192 + k0 + 8], c11[o * 192 + k0 + 9]);
    g_wp192[idx] = (ull)b0 | ((ull)b1 << 32);
  }
}

// ---------------- K1: shift+window + LN1 + pos + QKV GEMM (fp16 MMA) ---------------
// epilogue writes q/k as hi/lo fp16 and V transposed fp16.
__global__ void k1_qkv(const float* __restrict__ x, const float* __restrict__ ln1w,
                       const float* __restrict__ ln1b) {
  extern __shared__ float sm1[];
  float* sx = sm1;
  unsigned* snT = (unsigned*)(sm1 + 4160);
  float* sout = sm1;
  __shared__ float smean[64], srstd[64];
  int blk = blockIdx.x;
  int e = blk >> 10, wwin = blk & 1023;
  int wh = wwin >> 5, ww = wwin & 31;
  int t = threadIdx.x;
  for (int idx = t; idx < 4096; idx += 256) {
    int c = idx >> 6, n = idx & 63;
    int i = n >> 3, j = n & 7;
    int h0 = (wh * 8 + i + 4) & 255;
    int w0 = (ww * 8 + j + 4) & 255;
    sx[n * 65 + c] = x[((e * 64 + c) * 256 + h0) * 256 + w0];
  }
  __syncthreads();
  if (t < 64) {
    int n = t;
    float m = 0.f;
#pragma unroll
    for (int c = 0; c < 64; c++) m += sx[n * 65 + c];
    m *= (1.f / 64.f);
    float v = 0.f;
#pragma unroll
    for (int c = 0; c < 64; c++) { float d = sx[n * 65 + c] - m; v += d * d; }
    v *= (1.f / 64.f);
    smean[n] = m;
    srstd[n] = rsqrtf(v + 1e-5f);
  }
  __syncthreads();
  for (int idx = t; idx < 2048; idx += 256) {
    int n = idx >> 5, kk = idx & 31;
    int c = kk * 2;
    float v0 = (sx[n * 65 + c] - smean[n]) * srstd[n] * ln1w[c] + ln1b[c] + g_pos[n * 64 + c];
    float v1 = (sx[n * 65 + c + 1] - smean[n]) * srstd[n] * ln1w[c + 1] + ln1b[c + 1] + g_pos[n * 64 + c + 1];
    snT[n * 36 + kk] = h2pk(v0, v1);
  }
  __syncthreads();
  int wa = t >> 5, lane = t & 31;
  int rq = lane >> 2, acol = lane & 3, ccol0 = 2 * acol;
  float acc[3][4][4];
#pragma unroll
  for (int j = 0; j < 3; j++)
#pragma unroll
    for (int mt = 0; mt < 4; mt++)
#pragma unroll
      for (int r = 0; r < 4; r++) acc[j][mt][r] = 0.f;
  for (int kit = 0; kit < 4; kit++) {
    unsigned A[4][4];
#pragma unroll
    for (int mt = 0; mt < 4; mt++) {
      int r = mt * 16 + rq;
      A[mt][0] = snT[r * 36 + kit * 8 + acol];
      A[mt][1] = snT[(r + 8) * 36 + kit * 8 + acol];
      A[mt][2] = snT[r * 36 + kit * 8 + acol + 4];
      A[mt][3] = snT[(r + 8) * 36 + kit * 8 + acol + 4];
    }
#pragma unroll
    for (int j = 0; j < 3; j++) {
      ull wv = g_wpqkv[((wa * 3 + j) * 4 + kit) * 32 + lane];
#pragma unroll
      for (int mt = 0; mt < 4; mt++)
        mma_f16(acc[j][mt], A[mt], (unsigned)wv, (unsigned)(wv >> 32));
    }
  }
  __syncthreads();
#pragma unroll
  for (int j = 0; j < 3; j++) {
    int jc = (wa * 3 + j) * 8 + ccol0;
#pragma unroll
    for (int mt = 0; mt < 4; mt++) {
      int r0 = mt * 16 + rq;
      sout[jc * 65 + r0] = acc[j][mt][0];
      sout[(jc + 1) * 65 + r0] = acc[j][mt][1];
      sout[jc * 65 + r0 + 8] = acc[j][mt][2];
      sout[(jc + 1) * 65 + r0 + 8] = acc[j][mt][3];
    }
  }
  __syncthreads();
  long wb = (long)(e * 1024 + wwin);
  // q/k: hi/lo fp16 split, layout [hh][n][16]
  for (int idx = t; idx < 8192; idx += 256) {
    int ch = idx & 15, n = (idx >> 4) & 63, hh = (idx >> 10) & 3, p = idx >> 12;
    int jc = p * 64 + ch * 4 + hh;
    float vv = sout[jc * 65 + n];
    __half hi = __float2half_rn(vv);
    __half lo = __float2half_rn(vv - __half2float(hi));
    long qi = (wb * 4 + hh) * 1024 + n * 16 + ch;
    if (p == 0) { g_qh[qi] = hi; g_ql[qi] = lo; }
    else { g_kh[qi] = hi; g_kl[qi] = lo; }
  }
  // v: fp16 transposed [hh][ch][n]
  for (int idx = t; idx < 4096; idx += 256) {
    int n = idx & 63, co = idx >> 6;
    int hh = co & 3, ch = co >> 2;
    float vv = sout[(128 + co) * 65 + n];
    g_vt[(wb * 4 + hh) * 1024 + ch * 64 + n] = __float2half_rn(vv);
  }
}

// ---------------- K23: fused attention (fp16 MMA, preloaded hi/lo) + GEGLU ---------
// dyn smem (uints): sgin [64][100]
__device__ __forceinline__ ull maskw(int row, int wh, int ww) {
  ull m = 0ULL;
  if (wh == 31) m |= ((row >> 3) < 4) ? 0xFFFFFFFF00000000ULL : 0x00000000FFFFFFFFULL;
  if (ww == 31) m |= ((row & 7) < 4) ? 0xF0F0F0F0F0F0F0F0ULL : 0x0F0F0F0F0F0F0F0FULL;
  return m;
}

__global__ void __launch_bounds__(256, 2)
k23_attn_geglu(const float* __restrict__ b11, const float* __restrict__ b12,
               const float* __restrict__ b2) {
  extern __shared__ unsigned smu[];
  unsigned* sgin = smu;          // 6400 uints
  __shared__ unsigned stu[64 * 36];
  int w = blockIdx.x, e = blockIdx.y;
  const int ekvA_of[3] = {1, 0, 1};
  const int ekvB_of[3] = {2, 2, 0};
  int eA = ekvA_of[e], eB = ekvB_of[e];
  int t = threadIdx.x;
  int wa = t >> 5, lane = t & 31;
  int rq = lane >> 2, acol = lane & 3;
  // --- cooperative: merged-q (qhi) into sgin features [128,192) ---
  for (int idx = t; idx < 1024; idx += 256) {
    int n = idx >> 4, pr = idx & 15;
    int hh2 = pr >> 2, c2 = (pr & 3) * 4;
    uint2 qv = *(const uint2*)&g_qh[((long)(e * 1024 + w) * 4 + hh2) * 1024 + n * 16 + c2];
    sgin[n * 100 + 64 + pr * 2] = qv.x;
    sgin[n * 100 + 64 + pr * 2 + 1] = qv.y;
  }
  // --- attention: warp = (slot, head) ---
  {
    int slot = wa >> 2, hh = wa & 3;
    int ekv = slot ? eB : eA;
    long kb = ((long)(ekv * 1024 + w) * 4 + hh) * 1024;
    long qhb = ((long)(e * 1024 + w) * 4 + hh) * 1024;
    int wh = w >> 5, ww = w & 31;
    // K fragments hi/lo (full 64x16 K of this head)
    unsigned Kfh[8][2], Kfl[8][2];
#pragma unroll
    for (int nt = 0; nt < 8; nt++) {
      int row = nt * 8 + rq;
      Kfh[nt][0] = *(const unsigned*)&g_kh[kb + row * 16 + 2 * acol];
      Kfh[nt][1] = *(const unsigned*)&g_kh[kb + row * 16 + 8 + 2 * acol];
      Kfl[nt][0] = *(const unsigned*)&g_kl[kb + row * 16 + 2 * acol];
      Kfl[nt][1] = *(const unsigned*)&g_kl[kb + row * 16 + 8 + 2 * acol];
    }
    // V B-fragments, preloaded once, reused across all 4 mt tiles
    unsigned Vf[4][2][2];
#pragma unroll
    for (int kit = 0; kit < 4; kit++)
#pragma unroll
      for (int n2 = 0; n2 < 2; n2++) {
        Vf[kit][n2][0] = *(const unsigned*)&g_vt[kb + (n2 * 8 + rq) * 64 + (kit * 8 + acol) * 2];
        Vf[kit][n2][1] = *(const unsigned*)&g_vt[kb + (n2 * 8 + rq) * 64 + (kit * 8 + 4 + acol) * 2];
      }
#pragma unroll
    for (int mt = 0; mt < 4; mt++) {
      int r0 = mt * 16 + rq;
      unsigned Ah[4], Al[4];
      Ah[0] = *(const unsigned*)&g_qh[qhb + r0 * 16 + 2 * acol];
      Ah[1] = *(const unsigned*)&g_qh[qhb + (r0 + 8) * 16 + 2 * acol];
      Ah[2] = *(const unsigned*)&g_qh[qhb + r0 * 16 + 8 + 2 * acol];
      Ah[3] = *(const unsigned*)&g_qh[qhb + (r0 + 8) * 16 + 8 + 2 * acol];
      Al[0] = *(const unsigned*)&g_ql[qhb + r0 * 16 + 2 * acol];
      Al[1] = *(const unsigned*)&g_ql[qhb + (r0 + 8) * 16 + 2 * acol];
      Al[2] = *(const unsigned*)&g_ql[qhb + r0 * 16 + 8 + 2 * acol];
      Al[3] = *(const unsigned*)&g_ql[qhb + (r0 + 8) * 16 + 8 + 2 * acol];
      // S ~ qh kh + qh kl + ql kh
      float sc[8][4];
#pragma unroll
      for (int nt = 0; nt < 8; nt++) {
#pragma unroll
        for (int r = 0; r < 4; r++) sc[nt][r] = 0.f;
        mma_f16(sc[nt], Ah, Kfh[nt][0], Kfh[nt][1]);
        mma_f16(sc[nt], Ah, Kfl[nt][0], Kfl[nt][1]);
        mma_f16(sc[nt], Al, Kfh[nt][0], Kfh[nt][1]);
      }
      // softmax (single pass, no max; masked -> exactly 0)
      ull m0 = maskw(r0, wh, ww);
      ull m1 = maskw(r0 + 8, wh, ww);
      float sum0 = 0.f, sum1 = 0.f;
      unsigned Pf[4][4];
#pragma unroll
      for (int nt = 0; nt < 8; nt++) {
        int c0 = nt * 8 + 2 * acol;
        float p0 = ((m0 >> c0) & 1) ? 0.f : __expf(sc[nt][0] * 0.125f);
        float p1 = ((m0 >> (c0 + 1)) & 1) ? 0.f : __expf(sc[nt][1] * 0.125f);
        float p2 = ((m1 >> c0) & 1) ? 0.f : __expf(sc[nt][2] * 0.125f);
        float p3 = ((m1 >> (c0 + 1)) & 1) ? 0.f : __expf(sc[nt][3] * 0.125f);
        sum0 += p0 + p1;
        sum1 += p2 + p3;
        Pf[nt >> 1][(nt & 1) ? 2 : 0] = h2pk(p0, p1);
        Pf[nt >> 1][(nt & 1) ? 3 : 1] = h2pk(p2, p3);
      }
      sum0 += __shfl_xor_sync(0xFFFFFFFFu, sum0, 1);
      sum0 += __shfl_xor_sync(0xFFFFFFFFu, sum0, 2);
      sum1 += __shfl_xor_sync(0xFFFFFFFFu, sum1, 1);
      sum1 += __shfl_xor_sync(0xFFFFFFFFu, sum1, 2);
      float inv0 = 1.f / sum0, inv1 = 1.f / sum1;
      // O = P V
      float oc[2][4];
#pragma unroll
      for (int n2 = 0; n2 < 2; n2++)
#pragma unroll
        for (int r = 0; r < 4; r++) oc[n2][r] = 0.f;
#pragma unroll
      for (int kit = 0; kit < 4; kit++)
#pragma unroll
        for (int n2 = 0; n2 < 2; n2++)
          mma_f16(oc[n2], Pf[kit], Vf[kit][n2][0], Vf[kit][n2][1]);
      // write normalized O (fp16) into sgin
#pragma unroll
      for (int n2 = 0; n2 < 2; n2++) {
        int fb = slot * 32 + hh * 8 + n2 * 4 + acol;
        sgin[r0 * 100 + fb] = h2pk(oc[n2][0] * inv0, oc[n2][1] * inv0);
        sgin[(r0 + 8) * 100 + fb] = h2pk(oc[n2][2] * inv1, oc[n2][3] * inv1);
      }
    }
  }
  __syncthreads();
  // ---- GEGLU GEMM1 ----
  float a1[4][4], g1[4][4];
  {
    int o = wa * 8 + 2 * acol;
    float ba0 = b11[e * 64 + o], ba1 = b11[e * 64 + o + 1];
    float bg0 = b12[e * 64 + o], bg1 = b12[e * 64 + o + 1];
#pragma unroll
    for (int mt = 0; mt < 4; mt++) {
      a1[mt][0] = ba0; a1[mt][1] = ba1; a1[mt][2] = ba0; a1[mt][3] = ba1;
      g1[mt][0] = bg0; g1[mt][1] = bg1; g1[mt][2] = bg0; g1[mt][3] = bg1;
    }
  }
  const ull* W11 = g_wp11 + e * 3072 + wa * 12 * 32;
  const ull* W12 = g_wp12 + e * 3072 + wa * 12 * 32;
  for (int kit = 0; kit < 12; kit++) {
    unsigned A[4][4];
#pragma unroll
    for (int mt = 0; mt < 4; mt++) {
      int r = mt * 16 + rq;
      A[mt][0] = sgin[r * 100 + kit * 8 + acol];
      A[mt][1] = sgin[(r + 8) * 100 + kit * 8 + acol];
      A[mt][2] = sgin[r * 100 + kit * 8 + acol + 4];
      A[mt][3] = sgin[(r + 8) * 100 + kit * 8 + acol + 4];
    }
    ull wv1 = W11[kit * 32 + lane];
    ull wv2 = W12[kit * 32 + lane];
#pragma unroll
    for (int mt = 0; mt < 4; mt++) {
      mma_f16(a1[mt], A[mt], (unsigned)wv1, (unsigned)(wv1 >> 32));
      mma_f16(g1[mt], A[mt], (unsigned)wv2, (unsigned)(wv2 >> 32));
    }
  }
#pragma unroll
  for (int mt = 0; mt < 4; mt++) {
    int r0 = mt * 16 + rq;
    stu[r0 * 36 + wa * 4 + acol] = h2pk(gelu_exact(a1[mt][0]) * g1[mt][0],
                                        gelu_exact(a1[mt][1]) * g1[mt][1]);
    stu[(r0 + 8) * 36 + wa * 4 + acol] = h2pk(gelu_exact(a1[mt][2]) * g1[mt][2],
                                              gelu_exact(a1[mt][3]) * g1[mt][3]);
  }
  __syncthreads();
  // ---- GEGLU GEMM2 ----
  float y2[4][4];
  {
    int o = wa * 8 + 2 * acol;
    float b0 = b2[e * 64 + o], b1v = b2[e * 64 + o + 1];
#pragma unroll
    for (int mt = 0; mt < 4; mt++) {
      y2[mt][0] = b0; y2[mt][1] = b1v; y2[mt][2] = b0; y2[mt][3] = b1v;
    }
  }
  const ull* W2 = g_wp2 + e * 1024 + wa * 4 * 32;
  for (int kit = 0; kit < 4; kit++) {
    unsigned A[4][4];
#pragma unroll
    for (int mt = 0; mt < 4; mt++) {
      int r = mt * 16 + rq;
      A[mt][0] = stu[r * 36 + kit * 8 + acol];
      A[mt][1] = stu[(r + 8) * 36 + kit * 8 + acol];
      A[mt][2] = stu[r * 36 + kit * 8 + acol + 4];
      A[mt][3] = stu[(r + 8) * 36 + kit * 8 + acol + 4];
    }
    ull wv = W2[kit * 32 + lane];
#pragma unroll
    for (int mt = 0; mt < 4; mt++)
      mma_f16(y2[mt], A[mt], (unsigned)wv, (unsigned)(wv >> 32));
  }
  // stage y (h2) into sgin region (dead now)
  unsigned* yst = sgin;
#pragma unroll
  for (int mt = 0; mt < 4; mt++) {
    int r0 = mt * 16 + rq;
    yst[r0 * 36 + wa * 4 + acol] = h2pk(y2[mt][0], y2[mt][1]);
    yst[(r0 + 8) * 36 + wa * 4 + acol] = h2pk(y2[mt][2], y2[mt][3]);
  }
  __syncthreads();
  long ybase = (long)(e * 1024 + w) * 4096;
  for (int idx = t; idx < 2048; idx += 256) {
    int n = idx >> 5, kk = idx & 31;
    *(__half2*)&g_yh[ybase + n * 64 + kk * 2] = *(__half2*)&yst[n * 36 + kk];
  }
}

// ---------------- K4: window reverse + conv1x1 + roll + residual (fp16 MMA) --------
__global__ void k4_conv11(const float* __restrict__ x) {
  extern __shared__ float sm4[];
  unsigned* sa = (unsigned*)sm4;
  float* sres = sm4;
  int wwin = blockIdx.x;
  int wh = wwin >> 5, ww = wwin & 31;
  int t = threadIdx.x;
  for (int idx = t; idx < 6144; idx += 256) {
    int n = idx / 96, kk = idx - n * 96;
    int c = kk * 2;
    int e = c >> 6, f = c & 63;
    sa[n * 100 + kk] = *(const unsigned*)&g_yh[(long)(e * 1024 + wwin) * 4096 + n * 64 + f];
  }
  __syncthreads();
  int wa = t >> 5, lane = t & 31;
  int rq = lane >> 2, acol = lane & 3, ccol0 = 2 * acol;
  float acc[3][4][4];
#pragma unroll
  for (int j = 0; j < 3; j++)
#pragma unroll
    for (int mt = 0; mt < 4; mt++)
#pragma unroll
      for (int r = 0; r < 4; r++) acc[j][mt][r] = 0.f;
  for (int kit = 0; kit < 12; kit++) {
    unsigned A[4][4];
#pragma unroll
    for (int mt = 0; mt < 4; mt++) {
      int r = mt * 16 + rq;
      A[mt][0] = sa[r * 100 + kit * 8 + acol];
      A[mt][1] = sa[(r + 8) * 100 + kit * 8 + acol];
      A[mt][2] = sa[r * 100 + kit * 8 + acol + 4];
      A[mt][3] = sa[(r + 8) * 100 + kit * 8 + acol + 4];
    }
#pragma unroll
    for (int j = 0; j < 3; j++) {
      ull wv = g_wp192[((wa * 3 + j) * 12 + kit) * 32 + lane];
#pragma unroll
      for (int mt = 0; mt < 4; mt++)
        mma_f16(acc[j][mt], A[mt], (unsigned)wv, (unsigned)(wv >> 32));
    }
  }
  __syncthreads();
#pragma unroll
  for (int j = 0; j < 3; j++) {
    int oc = (wa * 3 + j) * 8 + ccol0;
#pragma unroll
    for (int mt = 0; mt < 4; mt++) {
      int r0 = mt * 16 + rq;
      sres[oc * 65 + r0] = acc[j][mt][0];
      sres[(oc + 1) * 65 + r0] = acc[j][mt][1];
      sres[oc * 65 + r0 + 8] = acc[j][mt][2];
      sres[(oc + 1) * 65 + r0 + 8] = acc[j][mt][3];
    }
  }
  __syncthreads();
  for (int idx = t; idx < 12288; idx += 256) {
    int n = idx & 63, oc = idx >> 6;
    int i = n >> 3, j = n & 7;
    int hp = (wh * 8 + i + 4) & 255;
    int wp = (ww * 8 + j + 4) & 255;
    int gi = oc * 65536 + hp * 256 + wp;
    g_xres[gi] = sres[oc * 65 + n] + x[gi];
  }
}

// ---------------- K5: LN2 + ff_in (192->768) fp16 MMA ------------------------------
__global__ void k5_ln_ffin(const float* __restrict__ ln2w, const float* __restrict__ ln2b) {
  extern __shared__ float sm5[];
  float* sxn = sm5;
  unsigned* sxh = (unsigned*)(sm5 + 12544);
  float* sfl = sm5;
  __shared__ float red[256], red2[256], smean[64], srstd[64];
  int blk = blockIdx.x;
  int h = blk >> 2;
  int w0 = (blk & 3) * 64;
  int pix0 = h * 256 + w0;
  int t = threadIdx.x;
  for (int idx = t; idx < 12288; idx += 256) {
    int c = idx >> 6, p = idx & 63;
    sxn[p * 196 + c] = g_xres[c * 65536 + pix0 + p];
  }
  __syncthreads();
  {
    int p = t & 63, g = t >> 6;
    float s = 0.f, s2v = 0.f;
    for (int c = g; c < 192; c += 4) { float v = sxn[p * 196 + c]; s += v; s2v += v * v; }
    red[t] = s;
    red2[t] = s2v;
  }
  __syncthreads();
  if (t < 64) {
    float s = red[t] + red[64 + t] + red[128 + t] + red[192 + t];
    float s2v = red2[t] + red2[64 + t] + red2[128 + t] + red2[192 + t];
    float m = s * (1.f / 192.f);
    float var = s2v * (1.f / 192.f) - m * m;
    smean[t] = m;
    srstd[t] = rsqrtf(var + 1e-5f);
  }
  __syncthreads();
  for (int idx = t; idx < 6144; idx += 256) {
    int p = idx / 96, kk = idx - p * 96;
    int c = kk * 2;
    float v0 = (sxn[p * 196 + c] - smean[p]) * srstd[p] * ln2w[c] + ln2b[c];
    float v1 = (sxn[p * 196 + c + 1] - smean[p]) * srstd[p] * ln2w[c + 1] + ln2b[c + 1];
    sxh[p * 100 + kk] = h2pk(v0, v1);
  }
  __syncthreads();
  int wa = t >> 5, lane = t & 31;
  int rq = lane >> 2, acol = lane & 3, ccol0 = 2 * acol;
  for (int ch = 0; ch < 6; ch++) {
    float acc[2][4][4];
#pragma unroll
    for (int j = 0; j < 2; j++)
#pragma unroll
      for (int mt = 0; mt < 4; mt++)
#pragma unroll
        for (int r = 0; r < 4; r++) acc[j][mt][r] = 0.f;
    for (int kit = 0; kit < 12; kit++) {
      unsigned A[4][4];
#pragma unroll
      for (int mt = 0; mt < 4; mt++) {
        int r = mt * 16 + rq;
        A[mt][0] = sxh[r * 100 + kit * 8 + acol];
        A[mt][1] = sxh[(r + 8) * 100 + kit * 8 + acol];
        A[mt][2] = sxh[r * 100 + kit * 8 + acol + 4];
        A[mt][3] = sxh[(r + 8) * 100 + kit * 8 + acol + 4];
      }
#pragma unroll
      for (int j = 0; j < 2; j++) {
        int nt = wa * 12 + ch * 2 + j;
        ull wv = g_wp_in[(nt * 12 + kit) * 32 + lane];
#pragma unroll
        for (int mt = 0; mt < 4; mt++)
          mma_f16(acc[j][mt], A[mt], (unsigned)wv, (unsigned)(wv >> 32));
      }
    }
#pragma unroll
    for (int j = 0; j < 2; j++) {
      int lc = (wa * 2 + j) * 8 + ccol0;
#pragma unroll
      for (int mt = 0; mt < 4; mt++) {
        int r0 = mt * 16 + rq;
        sfl[lc * 66 + r0] = acc[j][mt][0];
        sfl[(lc + 1) * 66 + r0] = acc[j][mt][1];
        sfl[lc * 66 + r0 + 8] = acc[j][mt][2];
        sfl[(lc + 1) * 66 + r0 + 8] = acc[j][mt][3];
      }
    }
    __syncthreads();
    for (int idx = t; idx < 4096; idx += 256) {
      int lc = idx >> 5, p2 = (idx & 31) * 2;
      int o = ((lc >> 4) * 12 + ch * 2 + ((lc >> 3) & 1)) * 8 + (lc & 7);
      *(__half2*)&g_hbh[(long)o * 65536 + pix0 + p2] =
          __floats2half2_rn(sfl[lc * 66 + p2], sfl[lc * 66 + p2 + 1]);
    }
    __syncthreads();
  }
}

// ---------------- K6: depthwise 3x3 + gelu(g1)*g2, 16 rows/block, half2 ------------
__global__ void k6_dw(const float* __restrict__ dw) {
  __shared__ float s0[18][264];
  __shared__ float s1[18][264];
  int h0 = blockIdx.x * 16;
  int c = blockIdx.y;
  int t = threadIdx.x;
  const __half* p0 = g_hbh + (long)c * 65536;
  const __half* p1 = g_hbh + (long)(c + 384) * 65536;
  for (int idx = t; idx < 18 * 128; idx += 256) {
    int r = idx >> 7, cc = idx & 127;
    int hh = h0 - 1 + r;
    float2 v0 = make_float2(0.f, 0.f), v1 = make_float2(0.f, 0.f);
    if (hh >= 0 && hh < 256) {
      v0 = __half22float2(*(const __half2*)&p0[hh * 256 + cc * 2]);
      v1 = __half22float2(*(const __half2*)&p1[hh * 256 + cc * 2]);
    }
    s0[r][1 + 2 * cc] = v0.x;
    s0[r][2 + 2 * cc] = v0.y;
    s1[r][1 + 2 * cc] = v1.x;
    s1[r][2 + 2 * cc] = v1.y;
  }
  if (t < 18) { s0[t][0] = 0.f; s0[t][257] = 0.f; s1[t][0] = 0.f; s1[t][257] = 0.f; }
  float f0r[9], f1r[9];
#pragma unroll
  for (int k = 0; k < 9; k++) { f0r[k] = dw[c * 9 + k]; f1r[k] = dw[(c + 384) * 9 + k]; }
  __syncthreads();
  int cp = (t & 127) * 2;
  int rg = t >> 7;
#pragma unroll
  for (int r = 0; r < 8; r++) {
    int row = rg * 8 + r;
    float a0 = 0.f, b0 = 0.f, a1 = 0.f, b1 = 0.f;
#pragma unroll
    for (int dh = 0; dh < 3; dh++) {
#pragma unroll
      for (int dwi = 0; dwi < 3; dwi++) {
        float w = f0r[dh * 3 + dwi];
        float wv = f1r[dh * 3 + dwi];
        a0 += s0[row + dh][cp + dwi] * w;
        a1 += s0[row + dh][cp + 1 + dwi] * w;
        b0 += s1[row + dh][cp + dwi] * wv;
        b1 += s1[row + dh][cp + 1 + dwi] * wv;
      }
    }
    float o0 = gelu_exact(a0) * b0;
    float o1 = gelu_exact(a1) * b1;
    *(__half2*)&g_gbh[(long)c * 65536 + (h0 + row) * 256 + cp] = __floats2half2_rn(o0, o1);
  }
}

// ---------------- K7: ff_out (384->192) + residual, fp16 MMA -----------------------
__global__ void k7_ffout(float* __restrict__ out) {
  extern __shared__ unsigned sA[];
  __shared__ float sfl2[192 * 34];
  int blk = blockIdx.x;
  int h = blk >> 3;
  int w0 = (blk & 7) * 32;
  int pix0 = h * 256 + w0;
  int t = threadIdx.x;
  for (int idx = t; idx < 6144; idx += 256) {
    int p = idx & 31, kk = idx >> 5;
    int c = kk * 2;
    __half h0 = g_gbh[(long)c * 65536 + pix0 + p];
    __half h1 = g_gbh[(long)(c + 1) * 65536 + pix0 + p];
    __half2 hv = __halves2half2(h0, h1);
    sA[p * 196 + kk] = *(unsigned*)&hv;
  }
  __syncthreads();
  int wa = t >> 5, lane = t & 31;
  int rq = lane >> 2, acol = lane & 3, ccol0 = 2 * acol;
  float acc[3][2][4];
#pragma unroll
  for (int j = 0; j < 3; j++)
#pragma unroll
    for (int mt = 0; mt < 2; mt++)
#pragma unroll
      for (int r = 0; r < 4; r++) acc[j][mt][r] = 0.f;
  for (int kit = 0; kit < 24; kit++) {
    unsigned A[2][4];
#pragma unroll
    for (int mt = 0; mt < 2; mt++) {
      int r = mt * 16 + rq;
      A[mt][0] = sA[r * 196 + kit * 8 + acol];
      A[mt][1] = sA[(r + 8) * 196 + kit * 8 + acol];
      A[mt][2] = sA[r * 196 + kit * 8 + acol + 4];
      A[mt][3] = sA[(r + 8) * 196 + kit * 8 + acol + 4];
    }
#pragma unroll
    for (int j = 0; j < 3; j++) {
      ull wv = g_wp_out[((wa * 3 + j) * 24 + kit) * 32 + lane];
#pragma unroll
      for (int mt = 0; mt < 2; mt++)
        mma_f16(acc[j][mt], A[mt], (unsigned)wv, (unsigned)(wv >> 32));
    }
  }
#pragma unroll
  for (int j = 0; j < 3; j++) {
    int oc = (wa * 3 + j) * 8 + ccol0;
#pragma unroll
    for (int mt = 0; mt < 2; mt++) {
      int r0 = mt * 16 + rq;
      sfl2[oc * 34 + r0] = acc[j][mt][0];
      sfl2[(oc + 1) * 34 + r0] = acc[j][mt][1];
      sfl2[oc * 34 + r0 + 8] = acc[j][mt][2];
      sfl2[(oc + 1) * 34 + r0 + 8] = acc[j][mt][3];
    }
  }
  __syncthreads();
  for (int idx = t; idx < 6144; idx += 256) {
    int oc = idx >> 5, p = idx & 31;
    int gi = oc * 65536 + pix0 + p;
    out[gi] = g_xres[gi] + sfl2[oc * 34 + p];
  }
}

// ---------------- host launcher ----------------------------------------------------
extern "C" void kernel_launch(void* const* d_in, const int* in_sizes, int n_in,
                              void* d_out, int out_size) {
  const float* x    = (const float*)d_in[0];
  const float* ln1w = (const float*)d_in[1];
  const float* ln1b = (const float*)d_in[2];
  const float* ln2w = (const float*)d_in[3];
  const float* ln2b = (const float*)d_in[4];
  const float* wqkv = (const float*)d_in[5];
  const float* w11  = (const float*)d_in[6];
  const float* b11  = (const float*)d_in[7];
  const float* w12  = (const float*)d_in[8];
  const float* b12  = (const float*)d_in[9];
  const float* w2   = (const float*)d_in[10];
  const float* b2   = (const float*)d_in[11];
  const float* c11  = (const float*)d_in[12];
  const float* ffin = (const float*)d_in[13];
  const float* ffdw = (const float*)d_in[14];
  const float* ffou = (const float*)d_in[15];
  float* out = (float*)d_out;

  const int smem1 = 192 * 65 * 4;                 // 49920
  const int smem23 = 6400 * 4;                    // 25600
  const int smem4 = 192 * 65 * 4;                 // 49920
  const int smem5 = 12544 * 4 + 64 * 100 * 4;     // 75776
  const int smem7 = 32 * 196 * 4;                 // 25088
  cudaFuncSetAttribute(k1_qkv, cudaFuncAttributeMaxDynamicSharedMemorySize, smem1);
  cudaFuncSetAttribute(k23_attn_geglu, cudaFuncAttributeMaxDynamicSharedMemorySize, smem23);
  cudaFuncSetAttribute(k4_conv11, cudaFuncAttributeMaxDynamicSharedMemorySize, smem4);
  cudaFuncSetAttribute(k5_ln_ffin, cudaFuncAttributeMaxDynamicSharedMemorySize, smem5);
  cudaFuncSetAttribute(k7_ffout, cudaFuncAttributeMaxDynamicSharedMemorySize, smem7);

  kpos<<<1, 64>>>();
  kpack<<<144, 256>>>(c11, ffin, ffou, w11, w12, w2, wqkv);
  k1_qkv<<<3072, 256, smem1>>>(x, ln1w, ln1b);
  {
    dim3 g23(1024, 3);
    k23_attn_geglu<<<g23, 256, smem23>>>(b11, b12, b2);
  }
  k4_conv11<<<1024, 256, smem4>>>(x);
  k5_ln_ffin<<<1024, 256, smem5>>>(ln2w, ln2b);
  {
    dim3 g6(16, 384);
    k6_dw<<<g6, 256>>>(ffdw);
  }
  k7_ffout<<<2048, 256, smem7>>>(out);
}

// round 9
// speedup vs baseline: 7.2038x; 1.0982x over previous
#include <cuda_runtime.h>
#include <cuda_fp16.h>
#include <math.h>

typedef unsigned long long ull;

// ---------------- fp16 MMA helpers -------------------------------------------------
__device__ __forceinline__ unsigned h2pk(float a, float b) {
  __half2 h = __floats2half2_rn(a, b);
  return *(unsigned*)&h;
}
__device__ __forceinline__ void mma_f16(float* c, const unsigned* a, unsigned b0, unsigned b1) {
  asm volatile(
      "mma.sync.aligned.m16n8k16.row.col.f32.f16.f16.f32 "
      "{%0,%1,%2,%3},{%4,%5,%6,%7},{%8,%9},{%0,%1,%2,%3};"
      : "+f"(c[0]), "+f"(c[1]), "+f"(c[2]), "+f"(c[3])
      : "r"(a[0]), "r"(a[1]), "r"(a[2]), "r"(a[3]), "r"(b0), "r"(b1));
}
__device__ __forceinline__ float gelu_exact(float a) {
  return 0.5f * a * (1.f + erff(a * 0.70710678118654752f));
}

// ---------------- static device scratch --------------------------------------------
__device__ float g_pos[64 * 64];
// q/k stored as fp16 hi/lo split; v stored fp16 transposed [head][ch][key]
__device__ __half g_qh[3 * 1024 * 4096];
__device__ __half g_ql[3 * 1024 * 4096];
__device__ __half g_kh[3 * 1024 * 4096];
__device__ __half g_kl[3 * 1024 * 4096];
__device__ __half g_vt[3 * 1024 * 4096];
__device__ float g_xres[192 * 65536];
__device__ __half g_hbh[768 * 65536];
__device__ __half g_gbh[384 * 65536];
// packed fp16 weight fragments: [ntile][kit16][lane] -> (b0 | b1<<32)
__device__ ull g_wp_in[96 * 12 * 32];     // ff_in  (K=192, N=768)
__device__ ull g_wp_out[24 * 24 * 32];    // ff_out (K=384, N=192)
__device__ ull g_wp11[3 * 8 * 12 * 32];   // me_w11 (K=192, N=64)
__device__ ull g_wp12[3 * 8 * 12 * 32];   // me_w12
__device__ ull g_wp2[3 * 8 * 4 * 32];     // me_w2  (K=64,  N=64)
__device__ ull g_wpqkv[24 * 4 * 32];      // w_qkv  (K=64,  N=192)
__device__ ull g_wp192[24 * 12 * 32];     // conv11 (K=192, N=192)

// ---------------- K0a: sine positional encoding ------------------------------------
__global__ void kpos() {
  int n = threadIdx.x;
  int i = n >> 3, j = n & 7;
  double scale = 6.283185307179586476925286766559;
  double yv = (double)(i + 1) / (8.0 + 1e-6) * scale;
  double xv = (double)(j + 1) / (8.0 + 1e-6) * scale;
  for (int c = 0; c < 64; c++) {
    double base = (c < 32) ? yv : xv;
    int k = (c < 32) ? c : (c - 32);
    double dt = pow(10000.0, (double)(k >> 1) / 16.0);
    double v = base / dt;
    g_pos[n * 64 + c] = (float)(((k & 1) == 0) ? sin(v) : cos(v));
  }
}

// ---------------- K0b: fp16 fragment packing ---------------------------------------
__global__ void kpack(const float* __restrict__ c11, const float* __restrict__ ffin,
                      const float* __restrict__ ffout, const float* __restrict__ w11,
                      const float* __restrict__ w12, const float* __restrict__ w2,
                      const float* __restrict__ wqkv) {
  int idx = blockIdx.x * 256 + threadIdx.x;
  int lane = idx & 31;
  if (idx < 36864) {  // wp_in [96][12][32], src [o=768][k=192]
    int kit = (idx >> 5) % 12, nt = idx / 384;
    int o = nt * 8 + (lane >> 2), k0 = kit * 16 + (lane & 3) * 2;
    unsigned b0 = h2pk(ffin[o * 192 + k0], ffin[o * 192 + k0 + 1]);
    unsigned b1 = h2pk(ffin[o * 192 + k0 + 8], ffin[o * 192 + k0 + 9]);
    g_wp_in[idx] = (ull)b0 | ((ull)b1 << 32);
  }
  if (idx < 18432) {  // wp_out [24][24][32], src [o=192][k=384]
    int kit = (idx >> 5) % 24, nt = idx / 768;
    int o = nt * 8 + (lane >> 2), k0 = kit * 16 + (lane & 3) * 2;
    unsigned b0 = h2pk(ffout[o * 384 + k0], ffout[o * 384 + k0 + 1]);
    unsigned b1 = h2pk(ffout[o * 384 + k0 + 8], ffout[o * 384 + k0 + 9]);
    g_wp_out[idx] = (ull)b0 | ((ull)b1 << 32);
  }
  if (idx < 9216) {  // wp11/wp12 [3][8][12][32], src [e][k=192][f=64]
    int e = idx / 3072, r = idx % 3072;
    int kit = (r >> 5) % 12, nt = r / 384;
    int f = nt * 8 + (lane >> 2), k0 = kit * 16 + (lane & 3) * 2;
    const float* Wa = w11 + e * 12288;
    const float* Wb = w12 + e * 12288;
    unsigned a0 = h2pk(Wa[k0 * 64 + f], Wa[(k0 + 1) * 64 + f]);
    unsigned a1 = h2pk(Wa[(k0 + 8) * 64 + f], Wa[(k0 + 9) * 64 + f]);
    g_wp11[idx] = (ull)a0 | ((ull)a1 << 32);
    unsigned c0 = h2pk(Wb[k0 * 64 + f], Wb[(k0 + 1) * 64 + f]);
    unsigned c1 = h2pk(Wb[(k0 + 8) * 64 + f], Wb[(k0 + 9) * 64 + f]);
    g_wp12[idx] = (ull)c0 | ((ull)c1 << 32);
  }
  if (idx < 3072) {  // wp2 [3][8][4][32], src [e][k=64][f=64]
    int e = idx / 1024, r = idx % 1024;
    int kit = (r >> 5) % 4, nt = r / 128;
    int f = nt * 8 + (lane >> 2), k0 = kit * 16 + (lane & 3) * 2;
    const float* Wa = w2 + e * 4096;
    unsigned b0 = h2pk(Wa[k0 * 64 + f], Wa[(k0 + 1) * 64 + f]);
    unsigned b1 = h2pk(Wa[(k0 + 8) * 64 + f], Wa[(k0 + 9) * 64 + f]);
    g_wp2[idx] = (ull)b0 | ((ull)b1 << 32);
  }
  if (idx < 3072) {  // wpqkv [24][4][32], src [k=64][n=192]
    int kit = (idx >> 5) % 4, nt = idx / 128;
    int n = nt * 8 + (lane >> 2), k0 = kit * 16 + (lane & 3) * 2;
    unsigned b0 = h2pk(wqkv[k0 * 192 + n], wqkv[(k0 + 1) * 192 + n]);
    unsigned b1 = h2pk(wqkv[(k0 + 8) * 192 + n], wqkv[(k0 + 9) * 192 + n]);
    g_wpqkv[idx] = (ull)b0 | ((ull)b1 << 32);
  }
  if (idx < 9216) {  // wp192 [24][12][32], src [o=192][k=192]
    int kit = (idx >> 5) % 12, nt = idx / 384;
    int o = nt * 8 + (lane >> 2), k0 = kit * 16 + (lane & 3) * 2;
    unsigned b0 = h2pk(c11[o * 192 + k0], c11[o * 192 + k0 + 1]);
    unsigned b1 = h2pk(c11[o * 192 + k0 + 8], c11[o * 192 + k0 + 9]);
    g_wp192[idx] = (ull)b0 | ((ull)b1 << 32);
  }
}

// ---------------- K1: shift+window + LN1 + pos + QKV GEMM (fp16 MMA) ---------------
__global__ void k1_qkv(const float* __restrict__ x, const float* __restrict__ ln1w,
                       const float* __restrict__ ln1b) {
  extern __shared__ float sm1[];
  float* sx = sm1;
  unsigned* snT = (unsigned*)(sm1 + 4160);
  float* sout = sm1;
  __shared__ float smean[64], srstd[64];
  int blk = blockIdx.x;
  int e = blk >> 10, wwin = blk & 1023;
  int wh = wwin >> 5, ww = wwin & 31;
  int t = threadIdx.x;
  for (int idx = t; idx < 4096; idx += 256) {
    int c = idx >> 6, n = idx & 63;
    int i = n >> 3, j = n & 7;
    int h0 = (wh * 8 + i + 4) & 255;
    int w0 = (ww * 8 + j + 4) & 255;
    sx[n * 65 + c] = x[((e * 64 + c) * 256 + h0) * 256 + w0];
  }
  __syncthreads();
  if (t < 64) {
    int n = t;
    float m = 0.f;
#pragma unroll
    for (int c = 0; c < 64; c++) m += sx[n * 65 + c];
    m *= (1.f / 64.f);
    float v = 0.f;
#pragma unroll
    for (int c = 0; c < 64; c++) { float d = sx[n * 65 + c] - m; v += d * d; }
    v *= (1.f / 64.f);
    smean[n] = m;
    srstd[n] = rsqrtf(v + 1e-5f);
  }
  __syncthreads();
  for (int idx = t; idx < 2048; idx += 256) {
    int n = idx >> 5, kk = idx & 31;
    int c = kk * 2;
    float v0 = (sx[n * 65 + c] - smean[n]) * srstd[n] * ln1w[c] + ln1b[c] + g_pos[n * 64 + c];
    float v1 = (sx[n * 65 + c + 1] - smean[n]) * srstd[n] * ln1w[c + 1] + ln1b[c + 1] + g_pos[n * 64 + c + 1];
    snT[n * 36 + kk] = h2pk(v0, v1);
  }
  __syncthreads();
  int wa = t >> 5, lane = t & 31;
  int rq = lane >> 2, acol = lane & 3, ccol0 = 2 * acol;
  float acc[3][4][4];
#pragma unroll
  for (int j = 0; j < 3; j++)
#pragma unroll
    for (int mt = 0; mt < 4; mt++)
#pragma unroll
      for (int r = 0; r < 4; r++) acc[j][mt][r] = 0.f;
  for (int kit = 0; kit < 4; kit++) {
    unsigned A[4][4];
#pragma unroll
    for (int mt = 0; mt < 4; mt++) {
      int r = mt * 16 + rq;
      A[mt][0] = snT[r * 36 + kit * 8 + acol];
      A[mt][1] = snT[(r + 8) * 36 + kit * 8 + acol];
      A[mt][2] = snT[r * 36 + kit * 8 + acol + 4];
      A[mt][3] = snT[(r + 8) * 36 + kit * 8 + acol + 4];
    }
#pragma unroll
    for (int j = 0; j < 3; j++) {
      ull wv = g_wpqkv[((wa * 3 + j) * 4 + kit) * 32 + lane];
#pragma unroll
      for (int mt = 0; mt < 4; mt++)
        mma_f16(acc[j][mt], A[mt], (unsigned)wv, (unsigned)(wv >> 32));
    }
  }
  __syncthreads();
#pragma unroll
  for (int j = 0; j < 3; j++) {
    int jc = (wa * 3 + j) * 8 + ccol0;
#pragma unroll
    for (int mt = 0; mt < 4; mt++) {
      int r0 = mt * 16 + rq;
      sout[jc * 65 + r0] = acc[j][mt][0];
      sout[(jc + 1) * 65 + r0] = acc[j][mt][1];
      sout[jc * 65 + r0 + 8] = acc[j][mt][2];
      sout[(jc + 1) * 65 + r0 + 8] = acc[j][mt][3];
    }
  }
  __syncthreads();
  long wb = (long)(e * 1024 + wwin);
  // q/k: hi/lo fp16 split, half2-vectorized (channel pairs)
  for (int idx = t; idx < 4096; idx += 256) {
    int ch2 = idx & 7, n = (idx >> 3) & 63, hh = (idx >> 9) & 3, p = idx >> 11;
    int c0 = ch2 * 2;
    float vv0 = sout[(p * 64 + c0 * 4 + hh) * 65 + n];
    float vv1 = sout[(p * 64 + (c0 + 1) * 4 + hh) * 65 + n];
    __half h0 = __float2half_rn(vv0), h1 = __float2half_rn(vv1);
    __half2 hi = __halves2half2(h0, h1);
    __half2 lo = __floats2half2_rn(vv0 - __half2float(h0), vv1 - __half2float(h1));
    long qi = (wb * 4 + hh) * 1024 + n * 16 + c0;
    if (p == 0) {
      *(__half2*)&g_qh[qi] = hi;
      *(__half2*)&g_ql[qi] = lo;
    } else {
      *(__half2*)&g_kh[qi] = hi;
      *(__half2*)&g_kl[qi] = lo;
    }
  }
  // v: fp16 transposed [hh][ch][n], half2-vectorized (key pairs)
  for (int idx = t; idx < 2048; idx += 256) {
    int n2 = idx & 31, co = idx >> 5;
    int hh = co & 3, ch = co >> 2;
    float vv0 = sout[(128 + co) * 65 + 2 * n2];
    float vv1 = sout[(128 + co) * 65 + 2 * n2 + 1];
    *(__half2*)&g_vt[(wb * 4 + hh) * 1024 + ch * 64 + 2 * n2] = __floats2half2_rn(vv0, vv1);
  }
}

// ---------------- K234: fused 3-exposure attention + GEGLU + conv1x1 + residual ----
// one block per window. dyn smem u32[12800]: sgin[6400] | sya[6400]; sres aliases all.
__device__ __forceinline__ ull maskw(int row, int wh, int ww) {
  ull m = 0ULL;
  if (wh == 31) m |= ((row >> 3) < 4) ? 0xFFFFFFFF00000000ULL : 0x00000000FFFFFFFFULL;
  if (ww == 31) m |= ((row & 7) < 4) ? 0xF0F0F0F0F0F0F0F0ULL : 0x0F0F0F0F0F0F0F0FULL;
  return m;
}

__global__ void __launch_bounds__(256, 2)
k234_fused(const float* __restrict__ b11, const float* __restrict__ b12,
           const float* __restrict__ b2, const float* __restrict__ x) {
  extern __shared__ unsigned smu[];
  unsigned* sgin = smu;          // 6400 uints
  unsigned* sya = smu + 6400;    // 6400 uints ([n][96+pad] conv A-tile, stride 100)
  float* sres = (float*)smu;     // 12480 floats (alias; used after conv MMA)
  __shared__ unsigned stu[64 * 36];
  int w = blockIdx.x;
  int wh = w >> 5, ww = w & 31;
  const int ekvA_of[3] = {1, 0, 1};
  const int ekvB_of[3] = {2, 2, 0};
  int t = threadIdx.x;
  int wa = t >> 5, lane = t & 31;
  int rq = lane >> 2, acol = lane & 3;
  int slot = wa >> 2, hh = wa & 3;
  // masks depend only on (w, row) -> hoisted
  for (int e = 0; e < 3; e++) {
    long qb = (long)(e * 1024 + w) * 4096;
    // --- phase1: merged-q copy + attention (both write disjoint sgin regions) ---
    for (int idx = t; idx < 1024; idx += 256) {
      int n = idx >> 4, pr = idx & 15;
      int hh2 = pr >> 2, c2 = (pr & 3) * 4;
      uint2 qv = *(const uint2*)&g_qh[qb + hh2 * 1024 + n * 16 + c2];
      sgin[n * 100 + 64 + pr * 2] = qv.x;
      sgin[n * 100 + 64 + pr * 2 + 1] = qv.y;
    }
    {
      int ekv = slot ? ekvB_of[e] : ekvA_of[e];
      long kb = ((long)(ekv * 1024 + w) * 4 + hh) * 1024;
      long qhb = qb + hh * 1024;
      unsigned Kfh[8][2], Kfl[8][2];
#pragma unroll
      for (int nt = 0; nt < 8; nt++) {
        int row = nt * 8 + rq;
        Kfh[nt][0] = *(const unsigned*)&g_kh[kb + row * 16 + 2 * acol];
        Kfh[nt][1] = *(const unsigned*)&g_kh[kb + row * 16 + 8 + 2 * acol];
        Kfl[nt][0] = *(const unsigned*)&g_kl[kb + row * 16 + 2 * acol];
        Kfl[nt][1] = *(const unsigned*)&g_kl[kb + row * 16 + 8 + 2 * acol];
      }
      unsigned Vf[4][2][2];
#pragma unroll
      for (int kit = 0; kit < 4; kit++)
#pragma unroll
        for (int n2 = 0; n2 < 2; n2++) {
          Vf[kit][n2][0] = *(const unsigned*)&g_vt[kb + (n2 * 8 + rq) * 64 + (kit * 8 + acol) * 2];
          Vf[kit][n2][1] = *(const unsigned*)&g_vt[kb + (n2 * 8 + rq) * 64 + (kit * 8 + 4 + acol) * 2];
        }
#pragma unroll
      for (int mt = 0; mt < 4; mt++) {
        int r0 = mt * 16 + rq;
        unsigned Ah[4], Al[4];
        Ah[0] = *(const unsigned*)&g_qh[qhb + r0 * 16 + 2 * acol];
        Ah[1] = *(const unsigned*)&g_qh[qhb + (r0 + 8) * 16 + 2 * acol];
        Ah[2] = *(const unsigned*)&g_qh[qhb + r0 * 16 + 8 + 2 * acol];
        Ah[3] = *(const unsigned*)&g_qh[qhb + (r0 + 8) * 16 + 8 + 2 * acol];
        Al[0] = *(const unsigned*)&g_ql[qhb + r0 * 16 + 2 * acol];
        Al[1] = *(const unsigned*)&g_ql[qhb + (r0 + 8) * 16 + 2 * acol];
        Al[2] = *(const unsigned*)&g_ql[qhb + r0 * 16 + 8 + 2 * acol];
        Al[3] = *(const unsigned*)&g_ql[qhb + (r0 + 8) * 16 + 8 + 2 * acol];
        float sc[8][4];
#pragma unroll
        for (int nt = 0; nt < 8; nt++) {
#pragma unroll
          for (int r = 0; r < 4; r++) sc[nt][r] = 0.f;
          mma_f16(sc[nt], Ah, Kfh[nt][0], Kfh[nt][1]);
          mma_f16(sc[nt], Ah, Kfl[nt][0], Kfl[nt][1]);
          mma_f16(sc[nt], Al, Kfh[nt][0], Kfh[nt][1]);
        }
        ull m0 = maskw(r0, wh, ww);
        ull m1 = maskw(r0 + 8, wh, ww);
        float sum0 = 0.f, sum1 = 0.f;
        unsigned Pf[4][4];
#pragma unroll
        for (int nt = 0; nt < 8; nt++) {
          int c0 = nt * 8 + 2 * acol;
          float p0 = ((m0 >> c0) & 1) ? 0.f : __expf(sc[nt][0] * 0.125f);
          float p1 = ((m0 >> (c0 + 1)) & 1) ? 0.f : __expf(sc[nt][1] * 0.125f);
          float p2 = ((m1 >> c0) & 1) ? 0.f : __expf(sc[nt][2] * 0.125f);
          float p3 = ((m1 >> (c0 + 1)) & 1) ? 0.f : __expf(sc[nt][3] * 0.125f);
          sum0 += p0 + p1;
          sum1 += p2 + p3;
          Pf[nt >> 1][(nt & 1) ? 2 : 0] = h2pk(p0, p1);
          Pf[nt >> 1][(nt & 1) ? 3 : 1] = h2pk(p2, p3);
        }
        sum0 += __shfl_xor_sync(0xFFFFFFFFu, sum0, 1);
        sum0 += __shfl_xor_sync(0xFFFFFFFFu, sum0, 2);
        sum1 += __shfl_xor_sync(0xFFFFFFFFu, sum1, 1);
        sum1 += __shfl_xor_sync(0xFFFFFFFFu, sum1, 2);
        float inv0 = 1.f / sum0, inv1 = 1.f / sum1;
        float oc[2][4];
#pragma unroll
        for (int n2 = 0; n2 < 2; n2++)
#pragma unroll
          for (int r = 0; r < 4; r++) oc[n2][r] = 0.f;
#pragma unroll
        for (int kit = 0; kit < 4; kit++)
#pragma unroll
          for (int n2 = 0; n2 < 2; n2++)
            mma_f16(oc[n2], Pf[kit], Vf[kit][n2][0], Vf[kit][n2][1]);
#pragma unroll
        for (int n2 = 0; n2 < 2; n2++) {
          int fb = slot * 32 + hh * 8 + n2 * 4 + acol;
          sgin[r0 * 100 + fb] = h2pk(oc[n2][0] * inv0, oc[n2][1] * inv0);
          sgin[(r0 + 8) * 100 + fb] = h2pk(oc[n2][2] * inv1, oc[n2][3] * inv1);
        }
      }
    }
    __syncthreads();
    // ---- GEGLU GEMM1 ----
    float a1[4][4], g1[4][4];
    {
      int o = wa * 8 + 2 * acol;
      float ba0 = b11[e * 64 + o], ba1 = b11[e * 64 + o + 1];
      float bg0 = b12[e * 64 + o], bg1 = b12[e * 64 + o + 1];
#pragma unroll
      for (int mt = 0; mt < 4; mt++) {
        a1[mt][0] = ba0; a1[mt][1] = ba1; a1[mt][2] = ba0; a1[mt][3] = ba1;
        g1[mt][0] = bg0; g1[mt][1] = bg1; g1[mt][2] = bg0; g1[mt][3] = bg1;
      }
    }
    const ull* W11 = g_wp11 + e * 3072 + wa * 12 * 32;
    const ull* W12 = g_wp12 + e * 3072 + wa * 12 * 32;
    for (int kit = 0; kit < 12; kit++) {
      unsigned A[4][4];
#pragma unroll
      for (int mt = 0; mt < 4; mt++) {
        int r = mt * 16 + rq;
        A[mt][0] = sgin[r * 100 + kit * 8 + acol];
        A[mt][1] = sgin[(r + 8) * 100 + kit * 8 + acol];
        A[mt][2] = sgin[r * 100 + kit * 8 + acol + 4];
        A[mt][3] = sgin[(r + 8) * 100 + kit * 8 + acol + 4];
      }
      ull wv1 = W11[kit * 32 + lane];
      ull wv2 = W12[kit * 32 + lane];
#pragma unroll
      for (int mt = 0; mt < 4; mt++) {
        mma_f16(a1[mt], A[mt], (unsigned)wv1, (unsigned)(wv1 >> 32));
        mma_f16(g1[mt], A[mt], (unsigned)wv2, (unsigned)(wv2 >> 32));
      }
    }
#pragma unroll
    for (int mt = 0; mt < 4; mt++) {
      int r0 = mt * 16 + rq;
      stu[r0 * 36 + wa * 4 + acol] = h2pk(gelu_exact(a1[mt][0]) * g1[mt][0],
                                          gelu_exact(a1[mt][1]) * g1[mt][1]);
      stu[(r0 + 8) * 36 + wa * 4 + acol] = h2pk(gelu_exact(a1[mt][2]) * g1[mt][2],
                                                gelu_exact(a1[mt][3]) * g1[mt][3]);
    }
    __syncthreads();
    // ---- GEGLU GEMM2 -> write y directly into conv A-tile (sya) ----
    float y2[4][4];
    {
      int o = wa * 8 + 2 * acol;
      float b0 = b2[e * 64 + o], b1v = b2[e * 64 + o + 1];
#pragma unroll
      for (int mt = 0; mt < 4; mt++) {
        y2[mt][0] = b0; y2[mt][1] = b1v; y2[mt][2] = b0; y2[mt][3] = b1v;
      }
    }
    const ull* W2 = g_wp2 + e * 1024 + wa * 4 * 32;
    for (int kit = 0; kit < 4; kit++) {
      unsigned A[4][4];
#pragma unroll
      for (int mt = 0; mt < 4; mt++) {
        int r = mt * 16 + rq;
        A[mt][0] = stu[r * 36 + kit * 8 + acol];
        A[mt][1] = stu[(r + 8) * 36 + kit * 8 + acol];
        A[mt][2] = stu[r * 36 + kit * 8 + acol + 4];
        A[mt][3] = stu[(r + 8) * 36 + kit * 8 + acol + 4];
      }
      ull wv = W2[kit * 32 + lane];
#pragma unroll
      for (int mt = 0; mt < 4; mt++)
        mma_f16(y2[mt], A[mt], (unsigned)wv, (unsigned)(wv >> 32));
    }
    int kkb = e * 32 + wa * 4 + acol;
#pragma unroll
    for (int mt = 0; mt < 4; mt++) {
      int r0 = mt * 16 + rq;
      sya[r0 * 100 + kkb] = h2pk(y2[mt][0], y2[mt][1]);
      sya[(r0 + 8) * 100 + kkb] = h2pk(y2[mt][2], y2[mt][3]);
    }
    __syncthreads();
  }
  // ---- conv1x1 (192x192) over the assembled y tile ----
  float acc[3][4][4];
#pragma unroll
  for (int j = 0; j < 3; j++)
#pragma unroll
    for (int mt = 0; mt < 4; mt++)
#pragma unroll
      for (int r = 0; r < 4; r++) acc[j][mt][r] = 0.f;
  for (int kit = 0; kit < 12; kit++) {
    unsigned A[4][4];
#pragma unroll
    for (int mt = 0; mt < 4; mt++) {
      int r = mt * 16 + rq;
      A[mt][0] = sya[r * 100 + kit * 8 + acol];
      A[mt][1] = sya[(r + 8) * 100 + kit * 8 + acol];
      A[mt][2] = sya[r * 100 + kit * 8 + acol + 4];
      A[mt][3] = sya[(r + 8) * 100 + kit * 8 + acol + 4];
    }
#pragma unroll
    for (int j = 0; j < 3; j++) {
      ull wv = g_wp192[((wa * 3 + j) * 12 + kit) * 32 + lane];
#pragma unroll
      for (int mt = 0; mt < 4; mt++)
        mma_f16(acc[j][mt], A[mt], (unsigned)wv, (unsigned)(wv >> 32));
    }
  }
  __syncthreads();   // sya fully consumed; sres may alias it now
  int ccol0 = 2 * acol;
#pragma unroll
  for (int j = 0; j < 3; j++) {
    int oc = (wa * 3 + j) * 8 + ccol0;
#pragma unroll
    for (int mt = 0; mt < 4; mt++) {
      int r0 = mt * 16 + rq;
      sres[oc * 65 + r0] = acc[j][mt][0];
      sres[(oc + 1) * 65 + r0] = acc[j][mt][1];
      sres[oc * 65 + r0 + 8] = acc[j][mt][2];
      sres[(oc + 1) * 65 + r0 + 8] = acc[j][mt][3];
    }
  }
  __syncthreads();
  for (int idx = t; idx < 12288; idx += 256) {
    int n = idx & 63, oc = idx >> 6;
    int i = n >> 3, j = n & 7;
    int hp = (wh * 8 + i + 4) & 255;
    int wp = (ww * 8 + j + 4) & 255;
    int gi = oc * 65536 + hp * 256 + wp;
    g_xres[gi] = sres[oc * 65 + n] + x[gi];
  }
}

// ---------------- K5: LN2 + ff_in (192->768) fp16 MMA, reduced smem ----------------
// dyn f32[14848]: sxn [64][196] @0 (dies) | sxh u32 [64][100] @0 (in-place) | sfl @6400
__global__ void k5_ln_ffin(const float* __restrict__ ln2w, const float* __restrict__ ln2b) {
  extern __shared__ float sm5[];
  float* sxn = sm5;
  unsigned* sxh = (unsigned*)sm5;
  float* sfl = sm5 + 6400;
  __shared__ float red[256], red2[256], smean[64], srstd[64];
  int blk = blockIdx.x;
  int h = blk >> 2;
  int w0 = (blk & 3) * 64;
  int pix0 = h * 256 + w0;
  int t = threadIdx.x;
  for (int idx = t; idx < 12288; idx += 256) {
    int c = idx >> 6, p = idx & 63;
    sxn[p * 196 + c] = g_xres[c * 65536 + pix0 + p];
  }
  __syncthreads();
  {
    int p = t & 63, g = t >> 6;
    float s = 0.f, s2v = 0.f;
    for (int c = g; c < 192; c += 4) { float v = sxn[p * 196 + c]; s += v; s2v += v * v; }
    red[t] = s;
    red2[t] = s2v;
  }
  __syncthreads();
  if (t < 64) {
    float s = red[t] + red[64 + t] + red[128 + t] + red[192 + t];
    float s2v = red2[t] + red2[64 + t] + red2[128 + t] + red2[192 + t];
    float m = s * (1.f / 192.f);
    float var = s2v * (1.f / 192.f) - m * m;
    smean[t] = m;
    srstd[t] = rsqrtf(var + 1e-5f);
  }
  __syncthreads();
  // in-place f32 -> fp16 conversion via register staging (sxh aliases sxn)
  unsigned tmp[24];
#pragma unroll
  for (int k = 0; k < 24; k++) {
    int idx = t + k * 256;
    int p = idx / 96, kk = idx - p * 96;
    int c = kk * 2;
    float v0 = (sxn[p * 196 + c] - smean[p]) * srstd[p] * ln2w[c] + ln2b[c];
    float v1 = (sxn[p * 196 + c + 1] - smean[p]) * srstd[p] * ln2w[c + 1] + ln2b[c + 1];
    tmp[k] = h2pk(v0, v1);
  }
  __syncthreads();
#pragma unroll
  for (int k = 0; k < 24; k++) {
    int idx = t + k * 256;
    int p = idx / 96, kk = idx - p * 96;
    sxh[p * 100 + kk] = tmp[k];
  }
  __syncthreads();
  int wa = t >> 5, lane = t & 31;
  int rq = lane >> 2, acol = lane & 3, ccol0 = 2 * acol;
  for (int ch = 0; ch < 6; ch++) {
    float acc[2][4][4];
#pragma unroll
    for (int j = 0; j < 2; j++)
#pragma unroll
      for (int mt = 0; mt < 4; mt++)
#pragma unroll
        for (int r = 0; r < 4; r++) acc[j][mt][r] = 0.f;
    for (int kit = 0; kit < 12; kit++) {
      unsigned A[4][4];
#pragma unroll
      for (int mt = 0; mt < 4; mt++) {
        int r = mt * 16 + rq;
        A[mt][0] = sxh[r * 100 + kit * 8 + acol];
        A[mt][1] = sxh[(r + 8) * 100 + kit * 8 + acol];
        A[mt][2] = sxh[r * 100 + kit * 8 + acol + 4];
        A[mt][3] = sxh[(r + 8) * 100 + kit * 8 + acol + 4];
      }
#pragma unroll
      for (int j = 0; j < 2; j++) {
        int nt = wa * 12 + ch * 2 + j;
        ull wv = g_wp_in[(nt * 12 + kit) * 32 + lane];
#pragma unroll
        for (int mt = 0; mt < 4; mt++)
          mma_f16(acc[j][mt], A[mt], (unsigned)wv, (unsigned)(wv >> 32));
      }
    }
#pragma unroll
    for (int j = 0; j < 2; j++) {
      int lc = (wa * 2 + j) * 8 + ccol0;
#pragma unroll
      for (int mt = 0; mt < 4; mt++) {
        int r0 = mt * 16 + rq;
        sfl[lc * 66 + r0] = acc[j][mt][0];
        sfl[(lc + 1) * 66 + r0] = acc[j][mt][1];
        sfl[lc * 66 + r0 + 8] = acc[j][mt][2];
        sfl[(lc + 1) * 66 + r0 + 8] = acc[j][mt][3];
      }
    }
    __syncthreads();
    for (int idx = t; idx < 4096; idx += 256) {
      int lc = idx >> 5, p2 = (idx & 31) * 2;
      int o = ((lc >> 4) * 12 + ch * 2 + ((lc >> 3) & 1)) * 8 + (lc & 7);
      *(__half2*)&g_hbh[(long)o * 65536 + pix0 + p2] =
          __floats2half2_rn(sfl[lc * 66 + p2], sfl[lc * 66 + p2 + 1]);
    }
    __syncthreads();
  }
}

// ---------------- K6: depthwise 3x3 + gelu(g1)*g2, 16 rows/block, half2 ------------
__global__ void k6_dw(const float* __restrict__ dw) {
  __shared__ float s0[18][264];
  __shared__ float s1[18][264];
  int h0 = blockIdx.x * 16;
  int c = blockIdx.y;
  int t = threadIdx.x;
  const __half* p0 = g_hbh + (long)c * 65536;
  const __half* p1 = g_hbh + (long)(c + 384) * 65536;
  for (int idx = t; idx < 18 * 128; idx += 256) {
    int r = idx >> 7, cc = idx & 127;
    int hh = h0 - 1 + r;
    float2 v0 = make_float2(0.f, 0.f), v1 = make_float2(0.f, 0.f);
    if (hh >= 0 && hh < 256) {
      v0 = __half22float2(*(const __half2*)&p0[hh * 256 + cc * 2]);
      v1 = __half22float2(*(const __half2*)&p1[hh * 256 + cc * 2]);
    }
    s0[r][1 + 2 * cc] = v0.x;
    s0[r][2 + 2 * cc] = v0.y;
    s1[r][1 + 2 * cc] = v1.x;
    s1[r][2 + 2 * cc] = v1.y;
  }
  if (t < 18) { s0[t][0] = 0.f; s0[t][257] = 0.f; s1[t][0] = 0.f; s1[t][257] = 0.f; }
  float f0r[9], f1r[9];
#pragma unroll
  for (int k = 0; k < 9; k++) { f0r[k] = dw[c * 9 + k]; f1r[k] = dw[(c + 384) * 9 + k]; }
  __syncthreads();
  int cp = (t & 127) * 2;
  int rg = t >> 7;
#pragma unroll
  for (int r = 0; r < 8; r++) {
    int row = rg * 8 + r;
    float a0 = 0.f, b0 = 0.f, a1 = 0.f, b1 = 0.f;
#pragma unroll
    for (int dh = 0; dh < 3; dh++) {
#pragma unroll
      for (int dwi = 0; dwi < 3; dwi++) {
        float w = f0r[dh * 3 + dwi];
        float wv = f1r[dh * 3 + dwi];
        a0 += s0[row + dh][cp + dwi] * w;
        a1 += s0[row + dh][cp + 1 + dwi] * w;
        b0 += s1[row + dh][cp + dwi] * wv;
        b1 += s1[row + dh][cp + 1 + dwi] * wv;
      }
    }
    float o0 = gelu_exact(a0) * b0;
    float o1 = gelu_exact(a1) * b1;
    *(__half2*)&g_gbh[(long)c * 65536 + (h0 + row) * 256 + cp] = __floats2half2_rn(o0, o1);
  }
}

// ---------------- K7: ff_out (384->192) + residual, fp16 MMA -----------------------
__global__ void k7_ffout(float* __restrict__ out) {
  extern __shared__ unsigned sA[];
  __shared__ float sfl2[192 * 34];
  int blk = blockIdx.x;
  int h = blk >> 3;
  int w0 = (blk & 7) * 32;
  int pix0 = h * 256 + w0;
  int t = threadIdx.x;
  for (int idx = t; idx < 6144; idx += 256) {
    int p = idx & 31, kk = idx >> 5;
    int c = kk * 2;
    __half h0 = g_gbh[(long)c * 65536 + pix0 + p];
    __half h1 = g_gbh[(long)(c + 1) * 65536 + pix0 + p];
    __half2 hv = __halves2half2(h0, h1);
    sA[p * 196 + kk] = *(unsigned*)&hv;
  }
  __syncthreads();
  int wa = t >> 5, lane = t & 31;
  int rq = lane >> 2, acol = lane & 3, ccol0 = 2 * acol;
  float acc[3][2][4];
#pragma unroll
  for (int j = 0; j < 3; j++)
#pragma unroll
    for (int mt = 0; mt < 2; mt++)
#pragma unroll
      for (int r = 0; r < 4; r++) acc[j][mt][r] = 0.f;
  for (int kit = 0; kit < 24; kit++) {
    unsigned A[2][4];
#pragma unroll
    for (int mt = 0; mt < 2; mt++) {
      int r = mt * 16 + rq;
      A[mt][0] = sA[r * 196 + kit * 8 + acol];
      A[mt][1] = sA[(r + 8) * 196 + kit * 8 + acol];
      A[mt][2] = sA[r * 196 + kit * 8 + acol + 4];
      A[mt][3] = sA[(r + 8) * 196 + kit * 8 + acol + 4];
    }
#pragma unroll
    for (int j = 0; j < 3; j++) {
      ull wv = g_wp_out[((wa * 3 + j) * 24 + kit) * 32 + lane];
#pragma unroll
      for (int mt = 0; mt < 2; mt++)
        mma_f16(acc[j][mt], A[mt], (unsigned)wv, (unsigned)(wv >> 32));
    }
  }
#pragma unroll
  for (int j = 0; j < 3; j++) {
    int oc = (wa * 3 + j) * 8 + ccol0;
#pragma unroll
    for (int mt = 0; mt < 2; mt++) {
      int r0 = mt * 16 + rq;
      sfl2[oc * 34 + r0] = acc[j][mt][0];
      sfl2[(oc + 1) * 34 + r0] = acc[j][mt][1];
      sfl2[oc * 34 + r0 + 8] = acc[j][mt][2];
      sfl2[(oc + 1) * 34 + r0 + 8] = acc[j][mt][3];
    }
  }
  __syncthreads();
  for (int idx = t; idx < 6144; idx += 256) {
    int oc = idx >> 5, p = idx & 31;
    int gi = oc * 65536 + pix0 + p;
    out[gi] = g_xres[gi] + sfl2[oc * 34 + p];
  }
}

// ---------------- host launcher ----------------------------------------------------
extern "C" void kernel_launch(void* const* d_in, const int* in_sizes, int n_in,
                              void* d_out, int out_size) {
  const float* x    = (const float*)d_in[0];
  const float* ln1w = (const float*)d_in[1];
  const float* ln1b = (const float*)d_in[2];
  const float* ln2w = (const float*)d_in[3];
  const float* ln2b = (const float*)d_in[4];
  const float* wqkv = (const float*)d_in[5];
  const float* w11  = (const float*)d_in[6];
  const float* b11  = (const float*)d_in[7];
  const float* w12  = (const float*)d_in[8];
  const float* b12  = (const float*)d_in[9];
  const float* w2   = (const float*)d_in[10];
  const float* b2   = (const float*)d_in[11];
  const float* c11  = (const float*)d_in[12];
  const float* ffin = (const float*)d_in[13];
  const float* ffdw = (const float*)d_in[14];
  const float* ffou = (const float*)d_in[15];
  float* out = (float*)d_out;

  const int smem1 = 192 * 65 * 4;                 // 49920
  const int smem234 = 12800 * 4;                  // 51200
  const int smem5 = 14848 * 4;                    // 59392
  const int smem7 = 32 * 196 * 4;                 // 25088
  cudaFuncSetAttribute(k1_qkv, cudaFuncAttributeMaxDynamicSharedMemorySize, smem1);
  cudaFuncSetAttribute(k234_fused, cudaFuncAttributeMaxDynamicSharedMemorySize, smem234);
  cudaFuncSetAttribute(k5_ln_ffin, cudaFuncAttributeMaxDynamicSharedMemorySize, smem5);
  cudaFuncSetAttribute(k7_ffout, cudaFuncAttributeMaxDynamicSharedMemorySize, smem7);

  kpos<<<1, 64>>>();
  kpack<<<144, 256>>>(c11, ffin, ffou, w11, w12, w2, wqkv);
  k1_qkv<<<3072, 256, smem1>>>(x, ln1w, ln1b);
  k234_fused<<<1024, 256, smem234>>>(b11, b12, b2, x);
  k5_ln_ffin<<<1024, 256, smem5>>>(ln2w, ln2b);
  {
    dim3 g6(16, 384);
    k6_dw<<<g6, 256>>>(ffdw);
  }
  k7_ffout<<<2048, 256, smem7>>>(out);
}